// round 7
// baseline (speedup 1.0000x reference)
#include <cuda_runtime.h>
#include <cuda_bf16.h>
#include <cstdint>

#define NB 8
#define SS 2048
#define DD 1024
#define AA 512
#define DVV 512

// GEMM tiling: 128x256 CTA tile, 64x64 warp tile, BK=32, 3-stage cp.async
#define BM 128
#define BN 256
#define BKC 32
#define ROW64 64                      // bytes per smem row (32 bf16; XOR swizzle)
#define APLANE (128 * ROW64)          // 8192 B
#define BPLANE (256 * ROW64)          // 16384 B
#define STAGE (2 * APLANE + 2 * BPLANE)   // 49152 B  [Ahi|Alo|Bhi|Blo]
#define AHI_OFF 0
#define ALO_OFF APLANE
#define BHI_OFF (2 * APLANE)
#define BLO_OFF (2 * APLANE + BPLANE)
#define NSTAGE 3
#define SMEM_PIPE (NSTAGE * STAGE)    // 147456 B

// ---------------------------------------------------------------------------
// Scratch (__device__ globals; allocation-free rule)
// ---------------------------------------------------------------------------
__device__ __nv_bfloat16 g_QbHi[(size_t)NB * SS * DD];
__device__ __nv_bfloat16 g_QbLo[(size_t)NB * SS * DD];
__device__ __nv_bfloat16 g_KbHi[(size_t)NB * SS * DD];
__device__ __nv_bfloat16 g_KbLo[(size_t)NB * SS * DD];
__device__ __nv_bfloat16 g_VbHi[(size_t)NB * SS * DD];
__device__ __nv_bfloat16 g_VbLo[(size_t)NB * SS * DD];
__device__ __nv_bfloat16 g_WqHi[(size_t)AA * DD];
__device__ __nv_bfloat16 g_WqLo[(size_t)AA * DD];
__device__ __nv_bfloat16 g_WkHi[(size_t)AA * DD];
__device__ __nv_bfloat16 g_WkLo[(size_t)AA * DD];
__device__ __nv_bfloat16 g_WvHi[(size_t)DVV * DD];
__device__ __nv_bfloat16 g_WvLo[(size_t)DVV * DD];
__device__ __nv_bfloat16 g_QpHi[(size_t)NB * SS * AA];
__device__ __nv_bfloat16 g_QpLo[(size_t)NB * SS * AA];
__device__ __nv_bfloat16 g_KpHi[(size_t)NB * SS * AA];
__device__ __nv_bfloat16 g_KpLo[(size_t)NB * SS * AA];
__device__ __nv_bfloat16 g_WVTHi[(size_t)NB * DVV * SS];   // [b][v][s]
__device__ __nv_bfloat16 g_WVTLo[(size_t)NB * DVV * SS];
__device__ __nv_bfloat16 g_AtHi[(size_t)NB * SS * SS];
__device__ __nv_bfloat16 g_AtLo[(size_t)NB * SS * SS];
__device__ __nv_bfloat16 g_MkT[(size_t)NB * SS * SS];      // -1e9*mask, [b][k][q]

// ---------------------------------------------------------------------------
// Helpers
// ---------------------------------------------------------------------------
__device__ __forceinline__ uint32_t smem_u32(const void* p) {
    uint32_t a;
    asm("{ .reg .u64 t; cvta.to.shared.u64 t, %1; cvt.u32.u64 %0, t; }" : "=r"(a) : "l"(p));
    return a;
}
__device__ __forceinline__ void cp16(uint32_t dst, const void* src) {
    asm volatile("cp.async.cg.shared.global [%0], [%1], 16;" :: "r"(dst), "l"(src));
}
#define CP_COMMIT() asm volatile("cp.async.commit_group;" ::: "memory")
#define CP_WAIT1()  asm volatile("cp.async.wait_group 1;" ::: "memory")
#define CP_WAIT0()  asm volatile("cp.async.wait_group 0;" ::: "memory")

__device__ __forceinline__ void ldsm4(uint32_t (&r)[4], uint32_t addr) {
    asm volatile("ldmatrix.sync.aligned.m8n8.x4.shared.b16 {%0,%1,%2,%3}, [%4];"
        : "=r"(r[0]), "=r"(r[1]), "=r"(r[2]), "=r"(r[3]) : "r"(addr));
}
__device__ __forceinline__ void mma_bf16(float* d, const uint32_t* a, uint32_t b0, uint32_t b1) {
    asm volatile("mma.sync.aligned.m16n8k16.row.col.f32.bf16.bf16.f32 "
        "{%0,%1,%2,%3}, {%4,%5,%6,%7}, {%8,%9}, {%0,%1,%2,%3};"
        : "+f"(d[0]), "+f"(d[1]), "+f"(d[2]), "+f"(d[3])
        : "r"(a[0]), "r"(a[1]), "r"(a[2]), "r"(a[3]), "r"(b0), "r"(b1));
}
__device__ __forceinline__ void split2(float a, float b, uint32_t& hi, uint32_t& lo) {
    __nv_bfloat16 ah = __float2bfloat16_rn(a);
    __nv_bfloat16 bh = __float2bfloat16_rn(b);
    __nv_bfloat16 al = __float2bfloat16_rn(a - __bfloat162float(ah));
    __nv_bfloat16 bl = __float2bfloat16_rn(b - __bfloat162float(bh));
    hi = (uint32_t)__bfloat16_as_ushort(ah) | ((uint32_t)__bfloat16_as_ushort(bh) << 16);
    lo = (uint32_t)__bfloat16_as_ushort(al) | ((uint32_t)__bfloat16_as_ushort(bl) << 16);
}

// Per-lane ldmatrix offsets (plane-relative, swizzled). [subtile][ks]
struct FragOff { uint32_t a[4][2]; uint32_t b[4][2]; };
__device__ __forceinline__ void frag_offsets(int lane, int warp_m, int warp_n, FragOff& F) {
    int ha = lane >> 4;                      // A k-half (0/1)
#pragma unroll
    for (int wm = 0; wm < 4; wm++) {
        int row = warp_m * 64 + wm * 16 + (lane & 15);
        int x = (row >> 1) & 3;
#pragma unroll
        for (int ks = 0; ks < 2; ks++)
            F.a[wm][ks] = (uint32_t)(row * ROW64 + (((ks * 2 + ha) ^ x) << 4));
    }
    int rb = (lane & 7) + ((lane >> 4) << 3);
    int hb = (lane & 8) ? 1 : 0;             // B k-half
#pragma unroll
    for (int p = 0; p < 4; p++) {
        int row = warp_n * 64 + p * 16 + rb;
        int x = (row >> 1) & 3;
#pragma unroll
        for (int ks = 0; ks < 2; ks++)
            F.b[p][ks] = (uint32_t)(row * ROW64 + (((ks * 2 + hb) ^ x) << 4));
    }
}

// Issue cp.async for one BK=32 chunk into the given stage base (swizzled dst)
// A: 128 rows (tid>>1, k-half tid&1), 2x16B per plane.
// B: 256 rows (tid), full 64B row per plane.
__device__ __forceinline__ void issue_cp(uint32_t sbase,
    const __nv_bfloat16* __restrict__ Ahi, const __nv_bfloat16* __restrict__ Alo, int lda,
    const __nv_bfloat16* __restrict__ Bhi, const __nv_bfloat16* __restrict__ Blo, int ldb,
    int k0, int tid)
{
    {
        const int lrow = tid >> 1;
        const int c0 = (tid & 1) * 2;
        const int x = (lrow >> 1) & 3;
        const int koff = k0 + (tid & 1) * 16;
        uint32_t d0 = sbase + (uint32_t)(lrow * ROW64 + ((c0 ^ x) << 4));
        uint32_t d1 = sbase + (uint32_t)(lrow * ROW64 + (((c0 + 1) ^ x) << 4));
        const __nv_bfloat16* a0 = Ahi + (size_t)lrow * lda + koff;
        const __nv_bfloat16* a1 = Alo + (size_t)lrow * lda + koff;
        cp16(d0 + AHI_OFF, a0);  cp16(d1 + AHI_OFF, a0 + 8);
        cp16(d0 + ALO_OFF, a1);  cp16(d1 + ALO_OFF, a1 + 8);
    }
    {
        const int row = tid;
        const int x = (row >> 1) & 3;
        const __nv_bfloat16* b0 = Bhi + (size_t)row * ldb + k0;
        const __nv_bfloat16* b1 = Blo + (size_t)row * ldb + k0;
        uint32_t base = sbase + (uint32_t)(row * ROW64);
#pragma unroll
        for (int c = 0; c < 4; c++) {
            uint32_t off = (uint32_t)(((c ^ x) << 4));
            cp16(base + BHI_OFF + off, b0 + c * 8);
            cp16(base + BLO_OFF + off, b1 + c * 8);
        }
    }
}

// One BK=32 chunk of bf16x3 MMA (warp tile 64x64)
__device__ __forceinline__ void mma_chunk32(uint32_t sb, const FragOff& F, float (*acc)[8][4]) {
#pragma unroll
    for (int ks = 0; ks < 2; ks++) {
        uint32_t af[4][4], bh[4][4], bl[4][4];
#pragma unroll
        for (int wm = 0; wm < 4; wm++) ldsm4(af[wm], sb + AHI_OFF + F.a[wm][ks]);
#pragma unroll
        for (int p = 0; p < 4; p++) ldsm4(bh[p], sb + BHI_OFF + F.b[p][ks]);
#pragma unroll
        for (int p = 0; p < 4; p++) ldsm4(bl[p], sb + BLO_OFF + F.b[p][ks]);
#pragma unroll
        for (int wm = 0; wm < 4; wm++)
#pragma unroll
            for (int wn = 0; wn < 8; wn++) {
                mma_bf16(acc[wm][wn], af[wm], bh[wn >> 1][(wn & 1) * 2], bh[wn >> 1][(wn & 1) * 2 + 1]);
                mma_bf16(acc[wm][wn], af[wm], bl[wn >> 1][(wn & 1) * 2], bl[wn >> 1][(wn & 1) * 2 + 1]);
            }
#pragma unroll
        for (int wm = 0; wm < 4; wm++) ldsm4(af[wm], sb + ALO_OFF + F.a[wm][ks]);
#pragma unroll
        for (int wm = 0; wm < 4; wm++)
#pragma unroll
            for (int wn = 0; wn < 8; wn++)
                mma_bf16(acc[wm][wn], af[wm], bh[wn >> 1][(wn & 1) * 2], bh[wn >> 1][(wn & 1) * 2 + 1]);
    }
}

// 3-stage pipelined bf16 GEMM core (acc += A * B^T over K)
__device__ __forceinline__ void gemm_core(uint32_t sb,
    const __nv_bfloat16* Ahi, const __nv_bfloat16* Alo, int lda,
    const __nv_bfloat16* Bhi, const __nv_bfloat16* Blo, int ldb,
    int K, int tid, const FragOff& F, float (*acc)[8][4])
{
    const int nch = K / BKC;
    issue_cp(sb, Ahi, Alo, lda, Bhi, Blo, ldb, 0, tid);
    CP_COMMIT();
    issue_cp(sb + STAGE, Ahi, Alo, lda, Bhi, Blo, ldb, BKC, tid);
    CP_COMMIT();
    uint32_t cur = 0, nxt2 = 2 * STAGE;
    for (int ch = 0; ch < nch; ch++) {
        if (ch < nch - 1) { CP_WAIT1(); } else { CP_WAIT0(); }
        __syncthreads();
        if (ch + 2 < nch) {
            issue_cp(sb + nxt2, Ahi, Alo, lda, Bhi, Blo, ldb, (ch + 2) * BKC, tid);
            CP_COMMIT();
        }
        mma_chunk32(sb + cur, F, acc);
        cur = (cur == (NSTAGE - 1) * STAGE) ? 0 : cur + STAGE;
        nxt2 = (nxt2 == (NSTAGE - 1) * STAGE) ? 0 : nxt2 + STAGE;
    }
    __syncthreads();
}

// ---------------------------------------------------------------------------
// Fused elementwise fp32 -> bf16 hi/lo split (3 tensors via blockIdx.z)
// ---------------------------------------------------------------------------
struct SplitArgs {
    const float* in[3];
    __nv_bfloat16* hi[3];
    __nv_bfloat16* lo[3];
};
__global__ void split3_kernel(SplitArgs a, int n4)
{
    int z = blockIdx.z;
    int i = blockIdx.x * blockDim.x + threadIdx.x;
    if (i < n4) {
        float4 v = reinterpret_cast<const float4*>(a.in[z])[i];
        uint32_t h0, l0, h1, l1;
        split2(v.x, v.y, h0, l0);
        split2(v.z, v.w, h1, l1);
        reinterpret_cast<uint2*>(a.hi[z])[i] = make_uint2(h0, h1);
        reinterpret_cast<uint2*>(a.lo[z])[i] = make_uint2(l0, l1);
    }
}

// ---------------------------------------------------------------------------
// Mask transpose + prescale: mT[b][k][q] = bf16(-1e9 * mask[b][q][k])
// ---------------------------------------------------------------------------
__global__ __launch_bounds__(256)
void maskT_kernel(const int* __restrict__ mask, __nv_bfloat16* __restrict__ mT)
{
    __shared__ float t[32][33];
    const int b = blockIdx.z;
    const int q0 = blockIdx.y * 32, k0 = blockIdx.x * 32;
    const int* mb = mask + (size_t)b * SS * SS;
    __nv_bfloat16* ob = mT + (size_t)b * SS * SS;
#pragma unroll
    for (int i = 0; i < 4; i++) {
        int q = q0 + threadIdx.y + i * 8;
        t[threadIdx.y + i * 8][threadIdx.x] =
            -1e9f * (float)mb[(size_t)q * SS + k0 + threadIdx.x];
    }
    __syncthreads();
#pragma unroll
    for (int i = 0; i < 4; i++) {
        int k = k0 + threadIdx.y + i * 8;
        ob[(size_t)k * SS + q0 + threadIdx.x] =
            __float2bfloat16_rn(t[threadIdx.x][threadIdx.y + i * 8]);
    }
}

// ---------------------------------------------------------------------------
// Fused projection (Q/K/V via blockIdx.z): C = A*W^T + bias -> bf16 hi/lo.
// z==2 (V): writes WVT[b][n][s] via two-pass smem transpose.
// ---------------------------------------------------------------------------
struct ProjArgs {
    const __nv_bfloat16 *Ahi[3], *Alo[3], *Whi[3], *Wlo[3];
    const float* bias[3];
    __nv_bfloat16 *Chi[3], *Clo[3];
};
__global__ __launch_bounds__(256, 1)
void proj_kernel(ProjArgs P)
{
    extern __shared__ char smem[];
    uint32_t sb = smem_u32(smem);
    const int tid = threadIdx.x, lane = tid & 31, wid = tid >> 5;
    const int warp_m = wid & 1, warp_n = wid >> 1;
    const int m0 = blockIdx.y * BM, n0 = blockIdx.x * BN;
    const int z = blockIdx.z;
    const __nv_bfloat16* Ahi = P.Ahi[z];
    const __nv_bfloat16* Alo = P.Alo[z];
    const __nv_bfloat16* Whi = P.Whi[z];
    const __nv_bfloat16* Wlo = P.Wlo[z];
    const float* bias = P.bias[z];
    __nv_bfloat16* Chi = P.Chi[z];
    __nv_bfloat16* Clo = P.Clo[z];

    float acc[4][8][4];
#pragma unroll
    for (int i = 0; i < 4; i++)
#pragma unroll
        for (int j = 0; j < 8; j++)
#pragma unroll
            for (int r = 0; r < 4; r++) acc[i][j][r] = 0.f;

    FragOff F;
    frag_offsets(lane, warp_m, warp_n, F);

    gemm_core(sb, Ahi + (size_t)m0 * DD, Alo + (size_t)m0 * DD, DD,
              Whi + (size_t)n0 * DD, Wlo + (size_t)n0 * DD, DD,
              DD, tid, F, acc);

    if (z != 2) {
#pragma unroll
        for (int wn = 0; wn < 8; wn++) {
            int n = n0 + warp_n * 64 + wn * 8 + (lane & 3) * 2;
            float b0 = bias[n], b1 = bias[n + 1];
#pragma unroll
            for (int wm = 0; wm < 4; wm++)
#pragma unroll
                for (int h = 0; h < 2; h++) {
                    int m = m0 + warp_m * 64 + wm * 16 + (lane >> 2) + h * 8;
                    uint32_t hv, lv;
                    split2(acc[wm][wn][h * 2] + b0, acc[wm][wn][h * 2 + 1] + b1, hv, lv);
                    *reinterpret_cast<uint32_t*>(Chi + (size_t)m * AA + n) = hv;
                    *reinterpret_cast<uint32_t*>(Clo + (size_t)m * AA + n) = lv;
                }
        }
    } else {
        // Two-pass transpose: pass 0 = hi plane, pass 1 = lo plane.
        // T: 256 rows (local n) x 272 bytes (128 bf16 + pad, 16B-aligned rows)
        char* T = smem;
        const size_t b = (size_t)(m0 >> 11);
        const int s0 = m0 & (SS - 1);
#pragma unroll
        for (int pass = 0; pass < 2; pass++) {
#pragma unroll
            for (int wn = 0; wn < 8; wn++) {
                int ln = warp_n * 64 + wn * 8 + (lane & 3) * 2;
                float b0 = bias[n0 + ln], b1 = bias[n0 + ln + 1];
#pragma unroll
                for (int wm = 0; wm < 4; wm++)
#pragma unroll
                    for (int h = 0; h < 2; h++) {
                        int lm = warp_m * 64 + wm * 16 + (lane >> 2) + h * 8;
                        float v0 = acc[wm][wn][h * 2] + b0;
                        float v1 = acc[wm][wn][h * 2 + 1] + b1;
                        __nv_bfloat16 h0 = __float2bfloat16_rn(v0);
                        __nv_bfloat16 h1 = __float2bfloat16_rn(v1);
                        __nv_bfloat16 w0 = pass ? __float2bfloat16_rn(v0 - __bfloat162float(h0)) : h0;
                        __nv_bfloat16 w1 = pass ? __float2bfloat16_rn(v1 - __bfloat162float(h1)) : h1;
                        *reinterpret_cast<__nv_bfloat16*>(T + ln * 272 + lm * 2) = w0;
                        *reinterpret_cast<__nv_bfloat16*>(T + (ln + 1) * 272 + lm * 2) = w1;
                    }
            }
            __syncthreads();
            __nv_bfloat16* dst = (pass ? Clo : Chi) + (b * DVV + n0 + tid) * SS + s0;
#pragma unroll
            for (int g = 0; g < 16; g++)
                *reinterpret_cast<uint4*>(dst + g * 8) =
                    *reinterpret_cast<uint4*>(T + tid * 272 + g * 16);
            __syncthreads();
        }
    }
}

// ---------------------------------------------------------------------------
// Scores (pre-transposed): attn[b][k][q] = scale*Kp[k]·Qp[q] + mT[b][k][q]
// ---------------------------------------------------------------------------
__global__ __launch_bounds__(256, 1)
void scores_kernel(const __nv_bfloat16* __restrict__ KpHi, const __nv_bfloat16* __restrict__ KpLo,
                   const __nv_bfloat16* __restrict__ QpHi, const __nv_bfloat16* __restrict__ QpLo,
                   const __nv_bfloat16* __restrict__ mT, float* __restrict__ attn)
{
    extern __shared__ char smem[];
    uint32_t sb = smem_u32(smem);
    const int tid = threadIdx.x, lane = tid & 31, wid = tid >> 5;
    const int warp_m = wid & 1, warp_n = wid >> 1;
    const int m0 = blockIdx.y * BM, n0 = blockIdx.x * BN, b = blockIdx.z;

    float acc[4][8][4];
#pragma unroll
    for (int i = 0; i < 4; i++)
#pragma unroll
        for (int j = 0; j < 8; j++)
#pragma unroll
            for (int r = 0; r < 4; r++) acc[i][j][r] = 0.f;

    FragOff F;
    frag_offsets(lane, warp_m, warp_n, F);

    const size_t base = (size_t)b * SS * AA;
    gemm_core(sb, KpHi + base + (size_t)m0 * AA, KpLo + base + (size_t)m0 * AA, AA,
              QpHi + base + (size_t)n0 * AA, QpLo + base + (size_t)n0 * AA, AA,
              AA, tid, F, acc);

    const float scale = 0.04419417382415922f;   // 1/sqrt(512)
    const __nv_bfloat16* mb = mT + (size_t)b * SS * SS;
    float* ab = attn + (size_t)b * SS * SS;
#pragma unroll
    for (int wm = 0; wm < 4; wm++)
#pragma unroll
        for (int h = 0; h < 2; h++) {
            int k = m0 + warp_m * 64 + wm * 16 + (lane >> 2) + h * 8;
#pragma unroll
            for (int wn = 0; wn < 8; wn++) {
                int q = n0 + warp_n * 64 + wn * 8 + (lane & 3) * 2;
                uint32_t mu = *reinterpret_cast<const uint32_t*>(mb + (size_t)k * SS + q);
                float mv0 = __bfloat162float(__ushort_as_bfloat16((unsigned short)(mu & 0xFFFF)));
                float mv1 = __bfloat162float(__ushort_as_bfloat16((unsigned short)(mu >> 16)));
                *reinterpret_cast<float2*>(ab + (size_t)k * SS + q) =
                    make_float2(fmaf(acc[wm][wn][h * 2], scale, mv0),
                                fmaf(acc[wm][wn][h * 2 + 1], scale, mv1));
            }
        }
}

// ---------------------------------------------------------------------------
// Output: out[b][k][v] = sum_q attn[b][k][q] * WVT[b][v][q]
// ---------------------------------------------------------------------------
__global__ __launch_bounds__(256, 1)
void out_kernel(const __nv_bfloat16* __restrict__ AtHi, const __nv_bfloat16* __restrict__ AtLo,
                const __nv_bfloat16* __restrict__ WVTHi, const __nv_bfloat16* __restrict__ WVTLo,
                float* __restrict__ out)
{
    extern __shared__ char smem[];
    uint32_t sb = smem_u32(smem);
    const int tid = threadIdx.x, lane = tid & 31, wid = tid >> 5;
    const int warp_m = wid & 1, warp_n = wid >> 1;
    const int m0 = blockIdx.y * BM, n0 = blockIdx.x * BN, b = blockIdx.z;

    float acc[4][8][4];
#pragma unroll
    for (int i = 0; i < 4; i++)
#pragma unroll
        for (int j = 0; j < 8; j++)
#pragma unroll
            for (int r = 0; r < 4; r++) acc[i][j][r] = 0.f;

    FragOff F;
    frag_offsets(lane, warp_m, warp_n, F);

    const size_t abase = (size_t)b * SS * SS;
    const size_t bbase = (size_t)b * DVV * SS;
    gemm_core(sb, AtHi + abase + (size_t)m0 * SS, AtLo + abase + (size_t)m0 * SS, SS,
              WVTHi + bbase + (size_t)n0 * SS, WVTLo + bbase + (size_t)n0 * SS, SS,
              SS, tid, F, acc);

    float* ob = out + (size_t)b * SS * DVV;
#pragma unroll
    for (int wm = 0; wm < 4; wm++)
#pragma unroll
        for (int h = 0; h < 2; h++) {
            int m = m0 + warp_m * 64 + wm * 16 + (lane >> 2) + h * 8;
#pragma unroll
            for (int wn = 0; wn < 8; wn++) {
                int n = n0 + warp_n * 64 + wn * 8 + (lane & 3) * 2;
                *reinterpret_cast<float2*>(ob + (size_t)m * DVV + n) =
                    make_float2(acc[wm][wn][h * 2], acc[wm][wn][h * 2 + 1]);
            }
        }
}

// ---------------------------------------------------------------------------
// In-place row softmax (fp32) + bf16 hi/lo split write for the out GEMM.
// ---------------------------------------------------------------------------
__global__ void softmax_rows(float* __restrict__ p,
                             __nv_bfloat16* __restrict__ hi,
                             __nv_bfloat16* __restrict__ lo)
{
    __shared__ float red[33];
    size_t rb = (size_t)blockIdx.x * SS;
    float* x = p + rb;
    int tid = threadIdx.x;
    float v[8];
    float mx = -1e30f;
#pragma unroll
    for (int i = 0; i < 8; i++) { v[i] = x[tid + i * 256]; mx = fmaxf(mx, v[i]); }
#pragma unroll
    for (int o = 16; o > 0; o >>= 1) mx = fmaxf(mx, __shfl_xor_sync(0xffffffffu, mx, o));
    if ((tid & 31) == 0) red[tid >> 5] = mx;
    __syncthreads();
    if (tid < 32) {
        float m = (tid < 8) ? red[tid] : -1e30f;
#pragma unroll
        for (int o = 4; o > 0; o >>= 1) m = fmaxf(m, __shfl_xor_sync(0xffffffffu, m, o));
        if (tid == 0) red[32] = m;
    }
    __syncthreads();
    mx = red[32];
    float s = 0.f;
#pragma unroll
    for (int i = 0; i < 8; i++) { v[i] = __expf(v[i] - mx); s += v[i]; }
#pragma unroll
    for (int o = 16; o > 0; o >>= 1) s += __shfl_xor_sync(0xffffffffu, s, o);
    if ((tid & 31) == 0) red[tid >> 5] = s;
    __syncthreads();
    if (tid < 32) {
        float m = (tid < 8) ? red[tid] : 0.f;
#pragma unroll
        for (int o = 4; o > 0; o >>= 1) m += __shfl_xor_sync(0xffffffffu, m, o);
        if (tid == 0) red[32] = m;
    }
    __syncthreads();
    float inv = 1.0f / red[32];
#pragma unroll
    for (int i = 0; i < 8; i++) {
        int idx = tid + i * 256;
        float val = v[i] * inv;
        x[idx] = val;
        __nv_bfloat16 h = __float2bfloat16_rn(val);
        hi[rb + idx] = h;
        lo[rb + idx] = __float2bfloat16_rn(val - __bfloat162float(h));
    }
}

// ---------------------------------------------------------------------------
extern "C" void kernel_launch(void* const* d_in, const int* in_sizes, int n_in,
                              void* d_out, int out_size)
{
    const float* Q    = (const float*)d_in[0];
    const float* K    = (const float*)d_in[1];
    const float* V    = (const float*)d_in[2];
    const int*   mask = (const int*)  d_in[3];
    const float* Wq   = (const float*)d_in[4];
    const float* bq   = (const float*)d_in[5];
    const float* Wk   = (const float*)d_in[6];
    const float* bk   = (const float*)d_in[7];
    const float* Wv   = (const float*)d_in[8];
    const float* bv   = (const float*)d_in[9];

    float* out  = (float*)d_out;                   // selfOutput [B,S,Dv]
    float* attn = out + (size_t)NB * SS * DVV;     // attn       [B,S,S]

    static __nv_bfloat16 *pQbHi, *pQbLo, *pKbHi, *pKbLo, *pVbHi, *pVbLo;
    static __nv_bfloat16 *pWqHi, *pWqLo, *pWkHi, *pWkLo, *pWvHi, *pWvLo;
    static __nv_bfloat16 *pQpHi, *pQpLo, *pKpHi, *pKpLo, *pWVTHi, *pWVTLo;
    static __nv_bfloat16 *pAtHi, *pAtLo, *pMkT;
    static cudaStream_t s2;
    static cudaEvent_t evFork, evJoin;
    static bool inited = false;
    if (!inited) {
        cudaGetSymbolAddress((void**)&pQbHi, g_QbHi);   cudaGetSymbolAddress((void**)&pQbLo, g_QbLo);
        cudaGetSymbolAddress((void**)&pKbHi, g_KbHi);   cudaGetSymbolAddress((void**)&pKbLo, g_KbLo);
        cudaGetSymbolAddress((void**)&pVbHi, g_VbHi);   cudaGetSymbolAddress((void**)&pVbLo, g_VbLo);
        cudaGetSymbolAddress((void**)&pWqHi, g_WqHi);   cudaGetSymbolAddress((void**)&pWqLo, g_WqLo);
        cudaGetSymbolAddress((void**)&pWkHi, g_WkHi);   cudaGetSymbolAddress((void**)&pWkLo, g_WkLo);
        cudaGetSymbolAddress((void**)&pWvHi, g_WvHi);   cudaGetSymbolAddress((void**)&pWvLo, g_WvLo);
        cudaGetSymbolAddress((void**)&pQpHi, g_QpHi);   cudaGetSymbolAddress((void**)&pQpLo, g_QpLo);
        cudaGetSymbolAddress((void**)&pKpHi, g_KpHi);   cudaGetSymbolAddress((void**)&pKpLo, g_KpLo);
        cudaGetSymbolAddress((void**)&pWVTHi, g_WVTHi); cudaGetSymbolAddress((void**)&pWVTLo, g_WVTLo);
        cudaGetSymbolAddress((void**)&pAtHi, g_AtHi);   cudaGetSymbolAddress((void**)&pAtLo, g_AtLo);
        cudaGetSymbolAddress((void**)&pMkT, g_MkT);
        cudaFuncSetAttribute(proj_kernel,   cudaFuncAttributeMaxDynamicSharedMemorySize, SMEM_PIPE);
        cudaFuncSetAttribute(scores_kernel, cudaFuncAttributeMaxDynamicSharedMemorySize, SMEM_PIPE);
        cudaFuncSetAttribute(out_kernel,    cudaFuncAttributeMaxDynamicSharedMemorySize, SMEM_PIPE);
        cudaStreamCreateWithFlags(&s2, cudaStreamNonBlocking);
        cudaEventCreateWithFlags(&evFork, cudaEventDisableTiming);
        cudaEventCreateWithFlags(&evJoin, cudaEventDisableTiming);
        inited = true;
    }

    // Fork: maskT depends only on the mask input; overlap with splits + proj.
    cudaEventRecord(evFork, 0);
    cudaStreamWaitEvent(s2, evFork, 0);
    maskT_kernel<<<dim3(SS / 32, SS / 32, NB), dim3(32, 8), 0, s2>>>(mask, pMkT);
    cudaEventRecord(evJoin, s2);

    // 1) Pre-split fp32 inputs to bf16 hi/lo
    {
        SplitArgs sa;
        sa.in[0] = Q; sa.in[1] = K; sa.in[2] = V;
        sa.hi[0] = pQbHi; sa.hi[1] = pKbHi; sa.hi[2] = pVbHi;
        sa.lo[0] = pQbLo; sa.lo[1] = pKbLo; sa.lo[2] = pVbLo;
        int n4 = (NB * SS * DD) / 4;
        split3_kernel<<<dim3((n4 + 255) / 256, 1, 3), 256>>>(sa, n4);

        SplitArgs sw;
        sw.in[0] = Wq; sw.in[1] = Wk; sw.in[2] = Wv;
        sw.hi[0] = pWqHi; sw.hi[1] = pWkHi; sw.hi[2] = pWvHi;
        sw.lo[0] = pWqLo; sw.lo[1] = pWkLo; sw.lo[2] = pWvLo;
        int w4 = (AA * DD) / 4;
        split3_kernel<<<dim3((w4 + 255) / 256, 1, 3), 256>>>(sw, w4);
    }

    // 2) Fused projections (Q, K, V in one launch; z selects)
    {
        ProjArgs P;
        P.Ahi[0] = pQbHi; P.Alo[0] = pQbLo; P.Whi[0] = pWqHi; P.Wlo[0] = pWqLo;
        P.bias[0] = bq;   P.Chi[0] = pQpHi; P.Clo[0] = pQpLo;
        P.Ahi[1] = pKbHi; P.Alo[1] = pKbLo; P.Whi[1] = pWkHi; P.Wlo[1] = pWkLo;
        P.bias[1] = bk;   P.Chi[1] = pKpHi; P.Clo[1] = pKpLo;
        P.Ahi[2] = pVbHi; P.Alo[2] = pVbLo; P.Whi[2] = pWvHi; P.Wlo[2] = pWvLo;
        P.bias[2] = bv;   P.Chi[2] = pWVTHi; P.Clo[2] = pWVTLo;
        proj_kernel<<<dim3(AA / BN, (NB * SS) / BM, 3), 256, SMEM_PIPE>>>(P);
    }

    // Join: scores needs maskT output
    cudaStreamWaitEvent(0, evJoin, 0);

    // 3) Masked, pre-transposed scores -> attn (fp32, in d_out)
    scores_kernel<<<dim3(SS / BN, SS / BM, NB), 256, SMEM_PIPE>>>(pKpHi, pKpLo, pQpHi, pQpLo, pMkT, attn);
    // 4) Row softmax in place + bf16 hi/lo side-write
    softmax_rows<<<NB * SS, 256>>>(attn, pAtHi, pAtLo);
    // 5) selfOutput = attn @ WV  (K = 2048)
    out_kernel<<<dim3(DVV / BN, SS / BM, NB), 256, SMEM_PIPE>>>(pAtHi, pAtLo, pWVTHi, pWVTLo, out);
}

// round 8
// speedup vs baseline: 1.2155x; 1.2155x over previous
#include <cuda_runtime.h>
#include <cuda_bf16.h>
#include <cstdint>

#define NB 8
#define SS 2048
#define DD 1024
#define AA 512
#define DVV 512

// GEMM tiling: 128x128 CTA tile, BK=32, 3-stage cp.async pipeline, swizzled smem
#define BM 128
#define BN 128
#define BKC 32
#define ROW64 64                      // bytes per smem row (32 bf16; XOR swizzle)
#define PLANE (128 * ROW64)           // 8192 B per operand plane
#define STAGE (4 * PLANE)             // 32768 B per stage
#define NSTAGE 3
#define SMEM_PIPE (NSTAGE * STAGE)    // 98304 B

// ---------------------------------------------------------------------------
// Scratch (__device__ globals; allocation-free rule)
// ---------------------------------------------------------------------------
__device__ __nv_bfloat16 g_QbHi[(size_t)NB * SS * DD];
__device__ __nv_bfloat16 g_QbLo[(size_t)NB * SS * DD];
__device__ __nv_bfloat16 g_KbHi[(size_t)NB * SS * DD];
__device__ __nv_bfloat16 g_KbLo[(size_t)NB * SS * DD];
__device__ __nv_bfloat16 g_VbHi[(size_t)NB * SS * DD];
__device__ __nv_bfloat16 g_VbLo[(size_t)NB * SS * DD];
__device__ __nv_bfloat16 g_WqHi[(size_t)AA * DD];
__device__ __nv_bfloat16 g_WqLo[(size_t)AA * DD];
__device__ __nv_bfloat16 g_WkHi[(size_t)AA * DD];
__device__ __nv_bfloat16 g_WkLo[(size_t)AA * DD];
__device__ __nv_bfloat16 g_WvHi[(size_t)DVV * DD];
__device__ __nv_bfloat16 g_WvLo[(size_t)DVV * DD];
__device__ __nv_bfloat16 g_QpHi[(size_t)NB * SS * AA];
__device__ __nv_bfloat16 g_QpLo[(size_t)NB * SS * AA];
__device__ __nv_bfloat16 g_KpHi[(size_t)NB * SS * AA];
__device__ __nv_bfloat16 g_KpLo[(size_t)NB * SS * AA];
__device__ __nv_bfloat16 g_WVTHi[(size_t)NB * DVV * SS];   // [b][v][s]
__device__ __nv_bfloat16 g_WVTLo[(size_t)NB * DVV * SS];
__device__ __nv_bfloat16 g_AtHi[(size_t)NB * SS * SS];
__device__ __nv_bfloat16 g_AtLo[(size_t)NB * SS * SS];
__device__ __nv_bfloat16 g_MkT[(size_t)NB * SS * SS];      // -1e9*mask, [b][k][q]

// ---------------------------------------------------------------------------
// Helpers
// ---------------------------------------------------------------------------
__device__ __forceinline__ uint32_t smem_u32(const void* p) {
    uint32_t a;
    asm("{ .reg .u64 t; cvta.to.shared.u64 t, %1; cvt.u32.u64 %0, t; }" : "=r"(a) : "l"(p));
    return a;
}
__device__ __forceinline__ void cp16(uint32_t dst, const void* src) {
    asm volatile("cp.async.cg.shared.global [%0], [%1], 16;" :: "r"(dst), "l"(src));
}
#define CP_COMMIT() asm volatile("cp.async.commit_group;" ::: "memory")
#define CP_WAIT1()  asm volatile("cp.async.wait_group 1;" ::: "memory")
#define CP_WAIT0()  asm volatile("cp.async.wait_group 0;" ::: "memory")

__device__ __forceinline__ void ldsm4(uint32_t (&r)[4], uint32_t addr) {
    asm volatile("ldmatrix.sync.aligned.m8n8.x4.shared.b16 {%0,%1,%2,%3}, [%4];"
        : "=r"(r[0]), "=r"(r[1]), "=r"(r[2]), "=r"(r[3]) : "r"(addr));
}
__device__ __forceinline__ void mma_bf16(float* d, const uint32_t* a, uint32_t b0, uint32_t b1) {
    asm volatile("mma.sync.aligned.m16n8k16.row.col.f32.bf16.bf16.f32 "
        "{%0,%1,%2,%3}, {%4,%5,%6,%7}, {%8,%9}, {%0,%1,%2,%3};"
        : "+f"(d[0]), "+f"(d[1]), "+f"(d[2]), "+f"(d[3])
        : "r"(a[0]), "r"(a[1]), "r"(a[2]), "r"(a[3]), "r"(b0), "r"(b1));
}
__device__ __forceinline__ void split2(float a, float b, uint32_t& hi, uint32_t& lo) {
    __nv_bfloat16 ah = __float2bfloat16_rn(a);
    __nv_bfloat16 bh = __float2bfloat16_rn(b);
    __nv_bfloat16 al = __float2bfloat16_rn(a - __bfloat162float(ah));
    __nv_bfloat16 bl = __float2bfloat16_rn(b - __bfloat162float(bh));
    hi = (uint32_t)__bfloat16_as_ushort(ah) | ((uint32_t)__bfloat16_as_ushort(bh) << 16);
    lo = (uint32_t)__bfloat16_as_ushort(al) | ((uint32_t)__bfloat16_as_ushort(bl) << 16);
}

// Per-lane ldmatrix offsets (plane-relative, swizzled). [operand][ks]
struct FragOff { uint32_t a[4][2]; uint32_t b[2][2]; };
__device__ __forceinline__ void frag_offsets(int lane, int warp_m, int warp_n, FragOff& F) {
    int ha = lane >> 4;                      // A k-half (0/1)
#pragma unroll
    for (int wm = 0; wm < 4; wm++) {
        int row = warp_m * 64 + wm * 16 + (lane & 15);
        int x = (row >> 1) & 3;
#pragma unroll
        for (int ks = 0; ks < 2; ks++)
            F.a[wm][ks] = (uint32_t)(row * ROW64 + (((ks * 2 + ha) ^ x) << 4));
    }
    int rb = (lane & 7) + ((lane >> 4) << 3);
    int hb = (lane & 8) ? 1 : 0;             // B k-half
#pragma unroll
    for (int p = 0; p < 2; p++) {
        int row = warp_n * 32 + p * 16 + rb;
        int x = (row >> 1) & 3;
#pragma unroll
        for (int ks = 0; ks < 2; ks++)
            F.b[p][ks] = (uint32_t)(row * ROW64 + (((ks * 2 + hb) ^ x) << 4));
    }
}

// Issue cp.async for one BK=32 chunk into the given stage base (swizzled dst)
__device__ __forceinline__ void issue_cp(uint32_t sbase,
    const __nv_bfloat16* __restrict__ Ahi, const __nv_bfloat16* __restrict__ Alo, int lda,
    const __nv_bfloat16* __restrict__ Bhi, const __nv_bfloat16* __restrict__ Blo, int ldb,
    int k0, int tid)
{
    const int lrow = tid >> 1;
    const int c0 = (tid & 1) * 2;
    const int x = (lrow >> 1) & 3;
    const int koff = k0 + (tid & 1) * 16;
    uint32_t d0 = sbase + (uint32_t)(lrow * ROW64 + ((c0 ^ x) << 4));
    uint32_t d1 = sbase + (uint32_t)(lrow * ROW64 + (((c0 + 1) ^ x) << 4));
    const __nv_bfloat16* a0 = Ahi + (size_t)lrow * lda + koff;
    const __nv_bfloat16* a1 = Alo + (size_t)lrow * lda + koff;
    const __nv_bfloat16* b0 = Bhi + (size_t)lrow * ldb + koff;
    const __nv_bfloat16* b1 = Blo + (size_t)lrow * ldb + koff;
    cp16(d0, a0);               cp16(d1, a0 + 8);
    cp16(d0 + PLANE, a1);       cp16(d1 + PLANE, a1 + 8);
    cp16(d0 + 2 * PLANE, b0);   cp16(d1 + 2 * PLANE, b0 + 8);
    cp16(d0 + 3 * PLANE, b1);   cp16(d1 + 3 * PLANE, b1 + 8);
}

// One BK=32 chunk of bf16x3 MMA. All 12 LDSM per k-step batched up-front,
// then 48 HMMA issued as one dense burst (acc targets rotate; no RAW chains).
__device__ __forceinline__ void mma_chunk32(uint32_t sb, const FragOff& F, float (*acc)[4][4]) {
#pragma unroll
    for (int ks = 0; ks < 2; ks++) {
        uint32_t ah[4][4], al[4][4], bh[2][4], bl[2][4];
#pragma unroll
        for (int wm = 0; wm < 4; wm++) ldsm4(ah[wm], sb + F.a[wm][ks]);
#pragma unroll
        for (int wm = 0; wm < 4; wm++) ldsm4(al[wm], sb + PLANE + F.a[wm][ks]);
#pragma unroll
        for (int p = 0; p < 2; p++) ldsm4(bh[p], sb + 2 * PLANE + F.b[p][ks]);
#pragma unroll
        for (int p = 0; p < 2; p++) ldsm4(bl[p], sb + 3 * PLANE + F.b[p][ks]);
#pragma unroll
        for (int wm = 0; wm < 4; wm++)
#pragma unroll
            for (int wn = 0; wn < 4; wn++) {
                uint32_t h0 = bh[wn >> 1][(wn & 1) * 2], h1 = bh[wn >> 1][(wn & 1) * 2 + 1];
                mma_bf16(acc[wm][wn], ah[wm], h0, h1);
                mma_bf16(acc[wm][wn], ah[wm], bl[wn >> 1][(wn & 1) * 2], bl[wn >> 1][(wn & 1) * 2 + 1]);
                mma_bf16(acc[wm][wn], al[wm], h0, h1);
            }
    }
}

// 3-stage pipelined bf16 GEMM core (acc += A * B^T over K)
__device__ __forceinline__ void gemm_core(uint32_t sb,
    const __nv_bfloat16* Ahi, const __nv_bfloat16* Alo, int lda,
    const __nv_bfloat16* Bhi, const __nv_bfloat16* Blo, int ldb,
    int K, int tid, const FragOff& F, float (*acc)[4][4])
{
    const int nch = K / BKC;
    issue_cp(sb, Ahi, Alo, lda, Bhi, Blo, ldb, 0, tid);
    CP_COMMIT();
    issue_cp(sb + STAGE, Ahi, Alo, lda, Bhi, Blo, ldb, BKC, tid);
    CP_COMMIT();
    uint32_t cur = 0, nxt2 = 2 * STAGE;
    for (int ch = 0; ch < nch; ch++) {
        if (ch < nch - 1) { CP_WAIT1(); } else { CP_WAIT0(); }
        __syncthreads();
        if (ch + 2 < nch) {
            issue_cp(sb + nxt2, Ahi, Alo, lda, Bhi, Blo, ldb, (ch + 2) * BKC, tid);
            CP_COMMIT();
        }
        mma_chunk32(sb + cur, F, acc);
        cur = (cur == (NSTAGE - 1) * STAGE) ? 0 : cur + STAGE;
        nxt2 = (nxt2 == (NSTAGE - 1) * STAGE) ? 0 : nxt2 + STAGE;
    }
    __syncthreads();
}

// ---------------------------------------------------------------------------
// Fused elementwise fp32 -> bf16 hi/lo split (3 tensors via blockIdx.z)
// ---------------------------------------------------------------------------
struct SplitArgs {
    const float* in[3];
    __nv_bfloat16* hi[3];
    __nv_bfloat16* lo[3];
};
__global__ void split3_kernel(SplitArgs a, int n4)
{
    int z = blockIdx.z;
    int i = blockIdx.x * blockDim.x + threadIdx.x;
    if (i < n4) {
        float4 v = reinterpret_cast<const float4*>(a.in[z])[i];
        uint32_t h0, l0, h1, l1;
        split2(v.x, v.y, h0, l0);
        split2(v.z, v.w, h1, l1);
        reinterpret_cast<uint2*>(a.hi[z])[i] = make_uint2(h0, h1);
        reinterpret_cast<uint2*>(a.lo[z])[i] = make_uint2(l0, l1);
    }
}

// ---------------------------------------------------------------------------
// Mask transpose + prescale: mT[b][k][q] = bf16(-1e9 * mask[b][q][k])
// ---------------------------------------------------------------------------
__global__ __launch_bounds__(256)
void maskT_kernel(const int* __restrict__ mask, __nv_bfloat16* __restrict__ mT)
{
    __shared__ float t[32][33];
    const int b = blockIdx.z;
    const int q0 = blockIdx.y * 32, k0 = blockIdx.x * 32;
    const int* mb = mask + (size_t)b * SS * SS;
    __nv_bfloat16* ob = mT + (size_t)b * SS * SS;
#pragma unroll
    for (int i = 0; i < 4; i++) {
        int q = q0 + threadIdx.y + i * 8;
        t[threadIdx.y + i * 8][threadIdx.x] =
            -1e9f * (float)mb[(size_t)q * SS + k0 + threadIdx.x];
    }
    __syncthreads();
#pragma unroll
    for (int i = 0; i < 4; i++) {
        int k = k0 + threadIdx.y + i * 8;
        ob[(size_t)k * SS + q0 + threadIdx.x] =
            __float2bfloat16_rn(t[threadIdx.x][threadIdx.y + i * 8]);
    }
}

// ---------------------------------------------------------------------------
// Projection: C[M,512] = A[M,1024]*W[512,1024]^T + bias -> bf16 hi/lo
// transpose=1 (V): writes WVT[b][n][s] via smem transpose.
// ---------------------------------------------------------------------------
__global__ __launch_bounds__(256, 2)
void proj_kernel(const __nv_bfloat16* __restrict__ Ahi, const __nv_bfloat16* __restrict__ Alo,
                 const __nv_bfloat16* __restrict__ Whi, const __nv_bfloat16* __restrict__ Wlo,
                 const float* __restrict__ bias,
                 __nv_bfloat16* __restrict__ Chi, __nv_bfloat16* __restrict__ Clo,
                 int transpose)
{
    extern __shared__ char smem[];
    uint32_t sb = smem_u32(smem);
    const int tid = threadIdx.x, lane = tid & 31, wid = tid >> 5;
    const int warp_m = wid & 1, warp_n = wid >> 1;
    const int m0 = blockIdx.y * BM, n0 = blockIdx.x * BN;

    float acc[4][4][4];
#pragma unroll
    for (int i = 0; i < 4; i++)
#pragma unroll
        for (int j = 0; j < 4; j++)
#pragma unroll
            for (int r = 0; r < 4; r++) acc[i][j][r] = 0.f;

    FragOff F;
    frag_offsets(lane, warp_m, warp_n, F);

    gemm_core(sb, Ahi + (size_t)m0 * DD, Alo + (size_t)m0 * DD, DD,
              Whi + (size_t)n0 * DD, Wlo + (size_t)n0 * DD, DD,
              DD, tid, F, acc);

    if (!transpose) {
#pragma unroll
        for (int wn = 0; wn < 4; wn++) {
            int n = n0 + warp_n * 32 + wn * 8 + (lane & 3) * 2;
            float b0 = bias[n], b1 = bias[n + 1];
#pragma unroll
            for (int wm = 0; wm < 4; wm++)
#pragma unroll
                for (int h = 0; h < 2; h++) {
                    int m = m0 + warp_m * 64 + wm * 16 + (lane >> 2) + h * 8;
                    uint32_t hv, lv;
                    split2(acc[wm][wn][h * 2] + b0, acc[wm][wn][h * 2 + 1] + b1, hv, lv);
                    *reinterpret_cast<uint32_t*>(Chi + (size_t)m * AA + n) = hv;
                    *reinterpret_cast<uint32_t*>(Clo + (size_t)m * AA + n) = lv;
                }
        }
    } else {
        char* T = smem;   // stride 272B rows; hi plane at 0, lo plane at 34816
#pragma unroll
        for (int wn = 0; wn < 4; wn++) {
            int ln = warp_n * 32 + wn * 8 + (lane & 3) * 2;
            float b0 = bias[n0 + ln], b1 = bias[n0 + ln + 1];
#pragma unroll
            for (int wm = 0; wm < 4; wm++)
#pragma unroll
                for (int h = 0; h < 2; h++) {
                    int lm = warp_m * 64 + wm * 16 + (lane >> 2) + h * 8;
                    float v0 = acc[wm][wn][h * 2] + b0;
                    float v1 = acc[wm][wn][h * 2 + 1] + b1;
                    __nv_bfloat16 h0 = __float2bfloat16_rn(v0);
                    __nv_bfloat16 l0 = __float2bfloat16_rn(v0 - __bfloat162float(h0));
                    __nv_bfloat16 h1 = __float2bfloat16_rn(v1);
                    __nv_bfloat16 l1 = __float2bfloat16_rn(v1 - __bfloat162float(h1));
                    *reinterpret_cast<__nv_bfloat16*>(T + ln * 272 + lm * 2) = h0;
                    *reinterpret_cast<__nv_bfloat16*>(T + (ln + 1) * 272 + lm * 2) = h1;
                    *reinterpret_cast<__nv_bfloat16*>(T + 34816 + ln * 272 + lm * 2) = l0;
                    *reinterpret_cast<__nv_bfloat16*>(T + 34816 + (ln + 1) * 272 + lm * 2) = l1;
                }
        }
        __syncthreads();
        int v = tid >> 1, hs = (tid & 1) * 64;
        size_t b = (size_t)(m0 >> 11);
        int s0 = m0 & (SS - 1);
        __nv_bfloat16* dh = Chi + (b * DVV + n0 + v) * SS + s0 + hs;
        __nv_bfloat16* dl = Clo + (b * DVV + n0 + v) * SS + s0 + hs;
#pragma unroll
        for (int g = 0; g < 8; g++) {
            *reinterpret_cast<uint4*>(dh + g * 8) =
                *reinterpret_cast<uint4*>(T + v * 272 + (hs + g * 8) * 2);
            *reinterpret_cast<uint4*>(dl + g * 8) =
                *reinterpret_cast<uint4*>(T + 34816 + v * 272 + (hs + g * 8) * 2);
        }
    }
}

// ---------------------------------------------------------------------------
// Scores (pre-transposed): attn[b][k][q] = scale*Kp[k]·Qp[q] + mT[b][k][q]
// ---------------------------------------------------------------------------
__global__ __launch_bounds__(256, 2)
void scores_kernel(const __nv_bfloat16* __restrict__ KpHi, const __nv_bfloat16* __restrict__ KpLo,
                   const __nv_bfloat16* __restrict__ QpHi, const __nv_bfloat16* __restrict__ QpLo,
                   const __nv_bfloat16* __restrict__ mT, float* __restrict__ attn)
{
    extern __shared__ char smem[];
    uint32_t sb = smem_u32(smem);
    const int tid = threadIdx.x, lane = tid & 31, wid = tid >> 5;
    const int warp_m = wid & 1, warp_n = wid >> 1;
    const int m0 = blockIdx.y * BM, n0 = blockIdx.x * BN, b = blockIdx.z;

    float acc[4][4][4];
#pragma unroll
    for (int i = 0; i < 4; i++)
#pragma unroll
        for (int j = 0; j < 4; j++)
#pragma unroll
            for (int r = 0; r < 4; r++) acc[i][j][r] = 0.f;

    FragOff F;
    frag_offsets(lane, warp_m, warp_n, F);

    const size_t base = (size_t)b * SS * AA;
    gemm_core(sb, KpHi + base + (size_t)m0 * AA, KpLo + base + (size_t)m0 * AA, AA,
              QpHi + base + (size_t)n0 * AA, QpLo + base + (size_t)n0 * AA, AA,
              AA, tid, F, acc);

    const float scale = 0.04419417382415922f;   // 1/sqrt(512)
    const __nv_bfloat16* mb = mT + (size_t)b * SS * SS;
    float* ab = attn + (size_t)b * SS * SS;
#pragma unroll
    for (int wm = 0; wm < 4; wm++)
#pragma unroll
        for (int h = 0; h < 2; h++) {
            int k = m0 + warp_m * 64 + wm * 16 + (lane >> 2) + h * 8;
#pragma unroll
            for (int wn = 0; wn < 4; wn++) {
                int q = n0 + warp_n * 32 + wn * 8 + (lane & 3) * 2;
                uint32_t mu = *reinterpret_cast<const uint32_t*>(mb + (size_t)k * SS + q);
                float mv0 = __bfloat162float(__ushort_as_bfloat16((unsigned short)(mu & 0xFFFF)));
                float mv1 = __bfloat162float(__ushort_as_bfloat16((unsigned short)(mu >> 16)));
                *reinterpret_cast<float2*>(ab + (size_t)k * SS + q) =
                    make_float2(fmaf(acc[wm][wn][h * 2], scale, mv0),
                                fmaf(acc[wm][wn][h * 2 + 1], scale, mv1));
            }
        }
}

// ---------------------------------------------------------------------------
// Output: out[b][k][v] = sum_q attn[b][k][q] * WVT[b][v][q]
// ---------------------------------------------------------------------------
__global__ __launch_bounds__(256, 2)
void out_kernel(const __nv_bfloat16* __restrict__ AtHi, const __nv_bfloat16* __restrict__ AtLo,
                const __nv_bfloat16* __restrict__ WVTHi, const __nv_bfloat16* __restrict__ WVTLo,
                float* __restrict__ out)
{
    extern __shared__ char smem[];
    uint32_t sb = smem_u32(smem);
    const int tid = threadIdx.x, lane = tid & 31, wid = tid >> 5;
    const int warp_m = wid & 1, warp_n = wid >> 1;
    const int m0 = blockIdx.y * BM, n0 = blockIdx.x * BN, b = blockIdx.z;

    float acc[4][4][4];
#pragma unroll
    for (int i = 0; i < 4; i++)
#pragma unroll
        for (int j = 0; j < 4; j++)
#pragma unroll
            for (int r = 0; r < 4; r++) acc[i][j][r] = 0.f;

    FragOff F;
    frag_offsets(lane, warp_m, warp_n, F);

    const size_t abase = (size_t)b * SS * SS;
    const size_t bbase = (size_t)b * DVV * SS;
    gemm_core(sb, AtHi + abase + (size_t)m0 * SS, AtLo + abase + (size_t)m0 * SS, SS,
              WVTHi + bbase + (size_t)n0 * SS, WVTLo + bbase + (size_t)n0 * SS, SS,
              SS, tid, F, acc);

    float* ob = out + (size_t)b * SS * DVV;
#pragma unroll
    for (int wm = 0; wm < 4; wm++)
#pragma unroll
        for (int h = 0; h < 2; h++) {
            int m = m0 + warp_m * 64 + wm * 16 + (lane >> 2) + h * 8;
#pragma unroll
            for (int wn = 0; wn < 4; wn++) {
                int n = n0 + warp_n * 32 + wn * 8 + (lane & 3) * 2;
                *reinterpret_cast<float2*>(ob + (size_t)m * DVV + n) =
                    make_float2(acc[wm][wn][h * 2], acc[wm][wn][h * 2 + 1]);
            }
        }
}

// ---------------------------------------------------------------------------
// In-place row softmax (fp32) + bf16 hi/lo split write for the out GEMM.
// ---------------------------------------------------------------------------
__global__ void softmax_rows(float* __restrict__ p,
                             __nv_bfloat16* __restrict__ hi,
                             __nv_bfloat16* __restrict__ lo)
{
    __shared__ float red[33];
    size_t rb = (size_t)blockIdx.x * SS;
    float* x = p + rb;
    int tid = threadIdx.x;
    float v[8];
    float mx = -1e30f;
#pragma unroll
    for (int i = 0; i < 8; i++) { v[i] = x[tid + i * 256]; mx = fmaxf(mx, v[i]); }
#pragma unroll
    for (int o = 16; o > 0; o >>= 1) mx = fmaxf(mx, __shfl_xor_sync(0xffffffffu, mx, o));
    if ((tid & 31) == 0) red[tid >> 5] = mx;
    __syncthreads();
    if (tid < 32) {
        float m = (tid < 8) ? red[tid] : -1e30f;
#pragma unroll
        for (int o = 4; o > 0; o >>= 1) m = fmaxf(m, __shfl_xor_sync(0xffffffffu, m, o));
        if (tid == 0) red[32] = m;
    }
    __syncthreads();
    mx = red[32];
    float s = 0.f;
#pragma unroll
    for (int i = 0; i < 8; i++) { v[i] = __expf(v[i] - mx); s += v[i]; }
#pragma unroll
    for (int o = 16; o > 0; o >>= 1) s += __shfl_xor_sync(0xffffffffu, s, o);
    if ((tid & 31) == 0) red[tid >> 5] = s;
    __syncthreads();
    if (tid < 32) {
        float m = (tid < 8) ? red[tid] : 0.f;
#pragma unroll
        for (int o = 4; o > 0; o >>= 1) m += __shfl_xor_sync(0xffffffffu, m, o);
        if (tid == 0) red[32] = m;
    }
    __syncthreads();
    float inv = 1.0f / red[32];
#pragma unroll
    for (int i = 0; i < 8; i++) {
        int idx = tid + i * 256;
        float val = v[i] * inv;
        x[idx] = val;
        __nv_bfloat16 h = __float2bfloat16_rn(val);
        hi[rb + idx] = h;
        lo[rb + idx] = __float2bfloat16_rn(val - __bfloat162float(h));
    }
}

// ---------------------------------------------------------------------------
extern "C" void kernel_launch(void* const* d_in, const int* in_sizes, int n_in,
                              void* d_out, int out_size)
{
    const float* Q    = (const float*)d_in[0];
    const float* K    = (const float*)d_in[1];
    const float* V    = (const float*)d_in[2];
    const int*   mask = (const int*)  d_in[3];
    const float* Wq   = (const float*)d_in[4];
    const float* bq   = (const float*)d_in[5];
    const float* Wk   = (const float*)d_in[6];
    const float* bk   = (const float*)d_in[7];
    const float* Wv   = (const float*)d_in[8];
    const float* bv   = (const float*)d_in[9];

    float* out  = (float*)d_out;                   // selfOutput [B,S,Dv]
    float* attn = out + (size_t)NB * SS * DVV;     // attn       [B,S,S]

    static __nv_bfloat16 *pQbHi, *pQbLo, *pKbHi, *pKbLo, *pVbHi, *pVbLo;
    static __nv_bfloat16 *pWqHi, *pWqLo, *pWkHi, *pWkLo, *pWvHi, *pWvLo;
    static __nv_bfloat16 *pQpHi, *pQpLo, *pKpHi, *pKpLo, *pWVTHi, *pWVTLo;
    static __nv_bfloat16 *pAtHi, *pAtLo, *pMkT;
    static bool inited = false;
    if (!inited) {
        cudaGetSymbolAddress((void**)&pQbHi, g_QbHi);   cudaGetSymbolAddress((void**)&pQbLo, g_QbLo);
        cudaGetSymbolAddress((void**)&pKbHi, g_KbHi);   cudaGetSymbolAddress((void**)&pKbLo, g_KbLo);
        cudaGetSymbolAddress((void**)&pVbHi, g_VbHi);   cudaGetSymbolAddress((void**)&pVbLo, g_VbLo);
        cudaGetSymbolAddress((void**)&pWqHi, g_WqHi);   cudaGetSymbolAddress((void**)&pWqLo, g_WqLo);
        cudaGetSymbolAddress((void**)&pWkHi, g_WkHi);   cudaGetSymbolAddress((void**)&pWkLo, g_WkLo);
        cudaGetSymbolAddress((void**)&pWvHi, g_WvHi);   cudaGetSymbolAddress((void**)&pWvLo, g_WvLo);
        cudaGetSymbolAddress((void**)&pQpHi, g_QpHi);   cudaGetSymbolAddress((void**)&pQpLo, g_QpLo);
        cudaGetSymbolAddress((void**)&pKpHi, g_KpHi);   cudaGetSymbolAddress((void**)&pKpLo, g_KpLo);
        cudaGetSymbolAddress((void**)&pWVTHi, g_WVTHi); cudaGetSymbolAddress((void**)&pWVTLo, g_WVTLo);
        cudaGetSymbolAddress((void**)&pAtHi, g_AtHi);   cudaGetSymbolAddress((void**)&pAtLo, g_AtLo);
        cudaGetSymbolAddress((void**)&pMkT, g_MkT);
        cudaFuncSetAttribute(proj_kernel,   cudaFuncAttributeMaxDynamicSharedMemorySize, SMEM_PIPE);
        cudaFuncSetAttribute(scores_kernel, cudaFuncAttributeMaxDynamicSharedMemorySize, SMEM_PIPE);
        cudaFuncSetAttribute(out_kernel,    cudaFuncAttributeMaxDynamicSharedMemorySize, SMEM_PIPE);
        inited = true;
    }

    // 1) Pre-split fp32 inputs to bf16 hi/lo (fused: QKV in one launch, weights in one)
    {
        SplitArgs sa;
        sa.in[0] = Q; sa.in[1] = K; sa.in[2] = V;
        sa.hi[0] = pQbHi; sa.hi[1] = pKbHi; sa.hi[2] = pVbHi;
        sa.lo[0] = pQbLo; sa.lo[1] = pKbLo; sa.lo[2] = pVbLo;
        int n4 = (NB * SS * DD) / 4;
        split3_kernel<<<dim3((n4 + 255) / 256, 1, 3), 256>>>(sa, n4);

        SplitArgs sw;
        sw.in[0] = Wq; sw.in[1] = Wk; sw.in[2] = Wv;
        sw.hi[0] = pWqHi; sw.hi[1] = pWkHi; sw.hi[2] = pWvHi;
        sw.lo[0] = pWqLo; sw.lo[1] = pWkLo; sw.lo[2] = pWvLo;
        int w4 = (AA * DD) / 4;
        split3_kernel<<<dim3((w4 + 255) / 256, 1, 3), 256>>>(sw, w4);
    }
    // 2) Mask transpose + prescale
    maskT_kernel<<<dim3(SS / 32, SS / 32, NB), dim3(32, 8)>>>(mask, pMkT);

    dim3 blk(256);
    // 3) Projections: M = 16384, N = 512, K = 1024
    proj_kernel<<<dim3(4, 128), blk, SMEM_PIPE>>>(pQbHi, pQbLo, pWqHi, pWqLo, bq, pQpHi, pQpLo, 0);
    proj_kernel<<<dim3(4, 128), blk, SMEM_PIPE>>>(pKbHi, pKbLo, pWkHi, pWkLo, bk, pKpHi, pKpLo, 0);
    proj_kernel<<<dim3(4, 128), blk, SMEM_PIPE>>>(pVbHi, pVbLo, pWvHi, pWvLo, bv, pWVTHi, pWVTLo, 1);
    // 4) Masked, pre-transposed scores -> attn (fp32, in d_out)
    scores_kernel<<<dim3(16, 16, NB), blk, SMEM_PIPE>>>(pKpHi, pKpLo, pQpHi, pQpLo, pMkT, attn);
    // 5) Row softmax in place + bf16 hi/lo side-write
    softmax_rows<<<NB * SS, 256>>>(attn, pAtHi, pAtLo);
    // 6) selfOutput = attn @ WV  (K = 2048)
    out_kernel<<<dim3(4, 16, NB), blk, SMEM_PIPE>>>(pAtHi, pAtLo, pWVTHi, pWVTLo, out);
}

// round 9
// speedup vs baseline: 1.2759x; 1.0497x over previous
#include <cuda_runtime.h>
#include <cuda_bf16.h>
#include <cstdint>

#define NB 8
#define SS 2048
#define DD 1024
#define AA 512
#define DVV 512

// GEMM tiling: 128x128 CTA tile, BK=32, 3-stage cp.async pipeline, swizzled smem
#define BM 128
#define BN 128
#define BKC 32
#define ROW64 64                      // bytes per smem row (32 bf16; XOR swizzle)
#define PLANE (128 * ROW64)           // 8192 B per operand plane
#define STAGE (4 * PLANE)             // 32768 B per stage
#define NSTAGE 3
#define SMEM_PIPE (NSTAGE * STAGE)    // 98304 B

// ---------------------------------------------------------------------------
// Scratch (__device__ globals; allocation-free rule)
// ---------------------------------------------------------------------------
__device__ __nv_bfloat16 g_QbHi[(size_t)NB * SS * DD];
__device__ __nv_bfloat16 g_QbLo[(size_t)NB * SS * DD];
__device__ __nv_bfloat16 g_KbHi[(size_t)NB * SS * DD];
__device__ __nv_bfloat16 g_KbLo[(size_t)NB * SS * DD];
__device__ __nv_bfloat16 g_VbHi[(size_t)NB * SS * DD];
__device__ __nv_bfloat16 g_VbLo[(size_t)NB * SS * DD];
__device__ __nv_bfloat16 g_WqHi[(size_t)AA * DD];
__device__ __nv_bfloat16 g_WqLo[(size_t)AA * DD];
__device__ __nv_bfloat16 g_WkHi[(size_t)AA * DD];
__device__ __nv_bfloat16 g_WkLo[(size_t)AA * DD];
__device__ __nv_bfloat16 g_WvHi[(size_t)DVV * DD];
__device__ __nv_bfloat16 g_WvLo[(size_t)DVV * DD];
__device__ __nv_bfloat16 g_QpHi[(size_t)NB * SS * AA];
__device__ __nv_bfloat16 g_QpLo[(size_t)NB * SS * AA];
__device__ __nv_bfloat16 g_KpHi[(size_t)NB * SS * AA];
__device__ __nv_bfloat16 g_KpLo[(size_t)NB * SS * AA];
__device__ __nv_bfloat16 g_WVTHi[(size_t)NB * DVV * SS];   // [b][v][s]
__device__ __nv_bfloat16 g_WVTLo[(size_t)NB * DVV * SS];
__device__ __nv_bfloat16 g_AtHi[(size_t)NB * SS * SS];
__device__ __nv_bfloat16 g_AtLo[(size_t)NB * SS * SS];
__device__ __nv_bfloat16 g_MkT[(size_t)NB * SS * SS];      // -1e9*mask, [b][k][q]

// ---------------------------------------------------------------------------
// Helpers
// ---------------------------------------------------------------------------
__device__ __forceinline__ uint32_t smem_u32(const void* p) {
    uint32_t a;
    asm("{ .reg .u64 t; cvta.to.shared.u64 t, %1; cvt.u32.u64 %0, t; }" : "=r"(a) : "l"(p));
    return a;
}
__device__ __forceinline__ void cp16(uint32_t dst, const void* src) {
    asm volatile("cp.async.cg.shared.global [%0], [%1], 16;" :: "r"(dst), "l"(src));
}
#define CP_COMMIT() asm volatile("cp.async.commit_group;" ::: "memory")
#define CP_WAIT1()  asm volatile("cp.async.wait_group 1;" ::: "memory")
#define CP_WAIT0()  asm volatile("cp.async.wait_group 0;" ::: "memory")

__device__ __forceinline__ void ldsm4(uint32_t (&r)[4], uint32_t addr) {
    asm volatile("ldmatrix.sync.aligned.m8n8.x4.shared.b16 {%0,%1,%2,%3}, [%4];"
        : "=r"(r[0]), "=r"(r[1]), "=r"(r[2]), "=r"(r[3]) : "r"(addr));
}
__device__ __forceinline__ void mma_bf16(float* d, const uint32_t* a, uint32_t b0, uint32_t b1) {
    asm volatile("mma.sync.aligned.m16n8k16.row.col.f32.bf16.bf16.f32 "
        "{%0,%1,%2,%3}, {%4,%5,%6,%7}, {%8,%9}, {%0,%1,%2,%3};"
        : "+f"(d[0]), "+f"(d[1]), "+f"(d[2]), "+f"(d[3])
        : "r"(a[0]), "r"(a[1]), "r"(a[2]), "r"(a[3]), "r"(b0), "r"(b1));
}
__device__ __forceinline__ void split2(float a, float b, uint32_t& hi, uint32_t& lo) {
    __nv_bfloat16 ah = __float2bfloat16_rn(a);
    __nv_bfloat16 bh = __float2bfloat16_rn(b);
    __nv_bfloat16 al = __float2bfloat16_rn(a - __bfloat162float(ah));
    __nv_bfloat16 bl = __float2bfloat16_rn(b - __bfloat162float(bh));
    hi = (uint32_t)__bfloat16_as_ushort(ah) | ((uint32_t)__bfloat16_as_ushort(bh) << 16);
    lo = (uint32_t)__bfloat16_as_ushort(al) | ((uint32_t)__bfloat16_as_ushort(bl) << 16);
}

// Per-lane ldmatrix offsets (plane-relative, swizzled). [operand][ks]
struct FragOff { uint32_t a[4][2]; uint32_t b[2][2]; };
__device__ __forceinline__ void frag_offsets(int lane, int warp_m, int warp_n, FragOff& F) {
    int ha = lane >> 4;                      // A k-half (0/1)
#pragma unroll
    for (int wm = 0; wm < 4; wm++) {
        int row = warp_m * 64 + wm * 16 + (lane & 15);
        int x = (row >> 1) & 3;
#pragma unroll
        for (int ks = 0; ks < 2; ks++)
            F.a[wm][ks] = (uint32_t)(row * ROW64 + (((ks * 2 + ha) ^ x) << 4));
    }
    int rb = (lane & 7) + ((lane >> 4) << 3);
    int hb = (lane & 8) ? 1 : 0;             // B k-half
#pragma unroll
    for (int p = 0; p < 2; p++) {
        int row = warp_n * 32 + p * 16 + rb;
        int x = (row >> 1) & 3;
#pragma unroll
        for (int ks = 0; ks < 2; ks++)
            F.b[p][ks] = (uint32_t)(row * ROW64 + (((ks * 2 + hb) ^ x) << 4));
    }
}

// Issue cp.async for one BK=32 chunk into the given stage base (swizzled dst)
__device__ __forceinline__ void issue_cp(uint32_t sbase,
    const __nv_bfloat16* __restrict__ Ahi, const __nv_bfloat16* __restrict__ Alo, int lda,
    const __nv_bfloat16* __restrict__ Bhi, const __nv_bfloat16* __restrict__ Blo, int ldb,
    int k0, int tid)
{
    const int lrow = tid >> 1;
    const int c0 = (tid & 1) * 2;
    const int x = (lrow >> 1) & 3;
    const int koff = k0 + (tid & 1) * 16;
    uint32_t d0 = sbase + (uint32_t)(lrow * ROW64 + ((c0 ^ x) << 4));
    uint32_t d1 = sbase + (uint32_t)(lrow * ROW64 + (((c0 + 1) ^ x) << 4));
    const __nv_bfloat16* a0 = Ahi + (size_t)lrow * lda + koff;
    const __nv_bfloat16* a1 = Alo + (size_t)lrow * lda + koff;
    const __nv_bfloat16* b0 = Bhi + (size_t)lrow * ldb + koff;
    const __nv_bfloat16* b1 = Blo + (size_t)lrow * ldb + koff;
    cp16(d0, a0);               cp16(d1, a0 + 8);
    cp16(d0 + PLANE, a1);       cp16(d1 + PLANE, a1 + 8);
    cp16(d0 + 2 * PLANE, b0);   cp16(d1 + 2 * PLANE, b0 + 8);
    cp16(d0 + 3 * PLANE, b1);   cp16(d1 + 3 * PLANE, b1 + 8);
}

// One BK=32 chunk of bf16x3 MMA (R5 ordering — measured best)
__device__ __forceinline__ void mma_chunk32(uint32_t sb, const FragOff& F, float (*acc)[4][4]) {
#pragma unroll
    for (int ks = 0; ks < 2; ks++) {
        uint32_t af[4][4], bh[2][4], bl[2][4];
#pragma unroll
        for (int wm = 0; wm < 4; wm++) ldsm4(af[wm], sb + F.a[wm][ks]);
#pragma unroll
        for (int p = 0; p < 2; p++) ldsm4(bh[p], sb + 2 * PLANE + F.b[p][ks]);
#pragma unroll
        for (int p = 0; p < 2; p++) ldsm4(bl[p], sb + 3 * PLANE + F.b[p][ks]);
#pragma unroll
        for (int wm = 0; wm < 4; wm++)
#pragma unroll
            for (int wn = 0; wn < 4; wn++) {
                mma_bf16(acc[wm][wn], af[wm], bh[wn >> 1][(wn & 1) * 2], bh[wn >> 1][(wn & 1) * 2 + 1]);
                mma_bf16(acc[wm][wn], af[wm], bl[wn >> 1][(wn & 1) * 2], bl[wn >> 1][(wn & 1) * 2 + 1]);
            }
#pragma unroll
        for (int wm = 0; wm < 4; wm++) ldsm4(af[wm], sb + PLANE + F.a[wm][ks]);
#pragma unroll
        for (int wm = 0; wm < 4; wm++)
#pragma unroll
            for (int wn = 0; wn < 4; wn++)
                mma_bf16(acc[wm][wn], af[wm], bh[wn >> 1][(wn & 1) * 2], bh[wn >> 1][(wn & 1) * 2 + 1]);
    }
}

// 3-stage pipelined bf16 GEMM core (acc += A * B^T over K)
__device__ __forceinline__ void gemm_core(uint32_t sb,
    const __nv_bfloat16* Ahi, const __nv_bfloat16* Alo, int lda,
    const __nv_bfloat16* Bhi, const __nv_bfloat16* Blo, int ldb,
    int K, int tid, const FragOff& F, float (*acc)[4][4])
{
    const int nch = K / BKC;
    issue_cp(sb, Ahi, Alo, lda, Bhi, Blo, ldb, 0, tid);
    CP_COMMIT();
    issue_cp(sb + STAGE, Ahi, Alo, lda, Bhi, Blo, ldb, BKC, tid);
    CP_COMMIT();
    uint32_t cur = 0, nxt2 = 2 * STAGE;
    for (int ch = 0; ch < nch; ch++) {
        if (ch < nch - 1) { CP_WAIT1(); } else { CP_WAIT0(); }
        __syncthreads();
        if (ch + 2 < nch) {
            issue_cp(sb + nxt2, Ahi, Alo, lda, Bhi, Blo, ldb, (ch + 2) * BKC, tid);
            CP_COMMIT();
        }
        mma_chunk32(sb + cur, F, acc);
        cur = (cur == (NSTAGE - 1) * STAGE) ? 0 : cur + STAGE;
        nxt2 = (nxt2 == (NSTAGE - 1) * STAGE) ? 0 : nxt2 + STAGE;
    }
    __syncthreads();
}

// ---------------------------------------------------------------------------
// Fused elementwise fp32 -> bf16 hi/lo split (3 tensors via blockIdx.z)
// ---------------------------------------------------------------------------
struct SplitArgs {
    const float* in[3];
    __nv_bfloat16* hi[3];
    __nv_bfloat16* lo[3];
};
__global__ void split3_kernel(SplitArgs a, int n4)
{
    int z = blockIdx.z;
    int i = blockIdx.x * blockDim.x + threadIdx.x;
    if (i < n4) {
        float4 v = reinterpret_cast<const float4*>(a.in[z])[i];
        uint32_t h0, l0, h1, l1;
        split2(v.x, v.y, h0, l0);
        split2(v.z, v.w, h1, l1);
        reinterpret_cast<uint2*>(a.hi[z])[i] = make_uint2(h0, h1);
        reinterpret_cast<uint2*>(a.lo[z])[i] = make_uint2(l0, l1);
    }
}

// ---------------------------------------------------------------------------
// Mask transpose + prescale: mT[b][k][q] = bf16(-1e9 * mask[b][q][k])
// ---------------------------------------------------------------------------
__global__ __launch_bounds__(256)
void maskT_kernel(const int* __restrict__ mask, __nv_bfloat16* __restrict__ mT)
{
    __shared__ float t[32][33];
    const int b = blockIdx.z;
    const int q0 = blockIdx.y * 32, k0 = blockIdx.x * 32;
    const int* mb = mask + (size_t)b * SS * SS;
    __nv_bfloat16* ob = mT + (size_t)b * SS * SS;
#pragma unroll
    for (int i = 0; i < 4; i++) {
        int q = q0 + threadIdx.y + i * 8;
        t[threadIdx.y + i * 8][threadIdx.x] =
            -1e9f * (float)mb[(size_t)q * SS + k0 + threadIdx.x];
    }
    __syncthreads();
#pragma unroll
    for (int i = 0; i < 4; i++) {
        int k = k0 + threadIdx.y + i * 8;
        ob[(size_t)k * SS + q0 + threadIdx.x] =
            __float2bfloat16_rn(t[threadIdx.x][threadIdx.y + i * 8]);
    }
}

// ---------------------------------------------------------------------------
// Fused projection (Q/K/V via blockIdx.z): C = A*W^T + bias -> bf16 hi/lo.
// z==2 (V): writes WVT[b][n][s] via smem transpose.
// ---------------------------------------------------------------------------
struct ProjArgs {
    const __nv_bfloat16 *Ahi[3], *Alo[3], *Whi[3], *Wlo[3];
    const float* bias[3];
    __nv_bfloat16 *Chi[3], *Clo[3];
};
__global__ __launch_bounds__(256, 2)
void proj_kernel(ProjArgs P)
{
    extern __shared__ char smem[];
    uint32_t sb = smem_u32(smem);
    const int tid = threadIdx.x, lane = tid & 31, wid = tid >> 5;
    const int warp_m = wid & 1, warp_n = wid >> 1;
    const int m0 = blockIdx.y * BM, n0 = blockIdx.x * BN;
    const int z = blockIdx.z;
    const __nv_bfloat16* Ahi = P.Ahi[z];
    const __nv_bfloat16* Alo = P.Alo[z];
    const __nv_bfloat16* Whi = P.Whi[z];
    const __nv_bfloat16* Wlo = P.Wlo[z];
    const float* bias = P.bias[z];
    __nv_bfloat16* Chi = P.Chi[z];
    __nv_bfloat16* Clo = P.Clo[z];

    float acc[4][4][4];
#pragma unroll
    for (int i = 0; i < 4; i++)
#pragma unroll
        for (int j = 0; j < 4; j++)
#pragma unroll
            for (int r = 0; r < 4; r++) acc[i][j][r] = 0.f;

    FragOff F;
    frag_offsets(lane, warp_m, warp_n, F);

    gemm_core(sb, Ahi + (size_t)m0 * DD, Alo + (size_t)m0 * DD, DD,
              Whi + (size_t)n0 * DD, Wlo + (size_t)n0 * DD, DD,
              DD, tid, F, acc);

    if (z != 2) {
#pragma unroll
        for (int wn = 0; wn < 4; wn++) {
            int n = n0 + warp_n * 32 + wn * 8 + (lane & 3) * 2;
            float b0 = bias[n], b1 = bias[n + 1];
#pragma unroll
            for (int wm = 0; wm < 4; wm++)
#pragma unroll
                for (int h = 0; h < 2; h++) {
                    int m = m0 + warp_m * 64 + wm * 16 + (lane >> 2) + h * 8;
                    uint32_t hv, lv;
                    split2(acc[wm][wn][h * 2] + b0, acc[wm][wn][h * 2 + 1] + b1, hv, lv);
                    *reinterpret_cast<uint32_t*>(Chi + (size_t)m * AA + n) = hv;
                    *reinterpret_cast<uint32_t*>(Clo + (size_t)m * AA + n) = lv;
                }
        }
    } else {
        char* T = smem;   // stride 272B rows; hi plane at 0, lo plane at 34816
#pragma unroll
        for (int wn = 0; wn < 4; wn++) {
            int ln = warp_n * 32 + wn * 8 + (lane & 3) * 2;
            float b0 = bias[n0 + ln], b1 = bias[n0 + ln + 1];
#pragma unroll
            for (int wm = 0; wm < 4; wm++)
#pragma unroll
                for (int h = 0; h < 2; h++) {
                    int lm = warp_m * 64 + wm * 16 + (lane >> 2) + h * 8;
                    float v0 = acc[wm][wn][h * 2] + b0;
                    float v1 = acc[wm][wn][h * 2 + 1] + b1;
                    __nv_bfloat16 h0 = __float2bfloat16_rn(v0);
                    __nv_bfloat16 l0 = __float2bfloat16_rn(v0 - __bfloat162float(h0));
                    __nv_bfloat16 h1 = __float2bfloat16_rn(v1);
                    __nv_bfloat16 l1 = __float2bfloat16_rn(v1 - __bfloat162float(h1));
                    *reinterpret_cast<__nv_bfloat16*>(T + ln * 272 + lm * 2) = h0;
                    *reinterpret_cast<__nv_bfloat16*>(T + (ln + 1) * 272 + lm * 2) = h1;
                    *reinterpret_cast<__nv_bfloat16*>(T + 34816 + ln * 272 + lm * 2) = l0;
                    *reinterpret_cast<__nv_bfloat16*>(T + 34816 + (ln + 1) * 272 + lm * 2) = l1;
                }
        }
        __syncthreads();
        int v = tid >> 1, hs = (tid & 1) * 64;
        size_t b = (size_t)(m0 >> 11);
        int s0 = m0 & (SS - 1);
        __nv_bfloat16* dh = Chi + (b * DVV + n0 + v) * SS + s0 + hs;
        __nv_bfloat16* dl = Clo + (b * DVV + n0 + v) * SS + s0 + hs;
#pragma unroll
        for (int g = 0; g < 8; g++) {
            *reinterpret_cast<uint4*>(dh + g * 8) =
                *reinterpret_cast<uint4*>(T + v * 272 + (hs + g * 8) * 2);
            *reinterpret_cast<uint4*>(dl + g * 8) =
                *reinterpret_cast<uint4*>(T + 34816 + v * 272 + (hs + g * 8) * 2);
        }
    }
}

// ---------------------------------------------------------------------------
// Scores (pre-transposed): attn[b][k][q] = scale*Kp[k]·Qp[q] + mT[b][k][q]
// ---------------------------------------------------------------------------
__global__ __launch_bounds__(256, 2)
void scores_kernel(const __nv_bfloat16* __restrict__ KpHi, const __nv_bfloat16* __restrict__ KpLo,
                   const __nv_bfloat16* __restrict__ QpHi, const __nv_bfloat16* __restrict__ QpLo,
                   const __nv_bfloat16* __restrict__ mT, float* __restrict__ attn)
{
    extern __shared__ char smem[];
    uint32_t sb = smem_u32(smem);
    const int tid = threadIdx.x, lane = tid & 31, wid = tid >> 5;
    const int warp_m = wid & 1, warp_n = wid >> 1;
    const int m0 = blockIdx.y * BM, n0 = blockIdx.x * BN, b = blockIdx.z;

    float acc[4][4][4];
#pragma unroll
    for (int i = 0; i < 4; i++)
#pragma unroll
        for (int j = 0; j < 4; j++)
#pragma unroll
            for (int r = 0; r < 4; r++) acc[i][j][r] = 0.f;

    FragOff F;
    frag_offsets(lane, warp_m, warp_n, F);

    const size_t base = (size_t)b * SS * AA;
    gemm_core(sb, KpHi + base + (size_t)m0 * AA, KpLo + base + (size_t)m0 * AA, AA,
              QpHi + base + (size_t)n0 * AA, QpLo + base + (size_t)n0 * AA, AA,
              AA, tid, F, acc);

    const float scale = 0.04419417382415922f;   // 1/sqrt(512)
    const __nv_bfloat16* mb = mT + (size_t)b * SS * SS;
    float* ab = attn + (size_t)b * SS * SS;
#pragma unroll
    for (int wm = 0; wm < 4; wm++)
#pragma unroll
        for (int h = 0; h < 2; h++) {
            int k = m0 + warp_m * 64 + wm * 16 + (lane >> 2) + h * 8;
#pragma unroll
            for (int wn = 0; wn < 4; wn++) {
                int q = n0 + warp_n * 32 + wn * 8 + (lane & 3) * 2;
                uint32_t mu = *reinterpret_cast<const uint32_t*>(mb + (size_t)k * SS + q);
                float mv0 = __bfloat162float(__ushort_as_bfloat16((unsigned short)(mu & 0xFFFF)));
                float mv1 = __bfloat162float(__ushort_as_bfloat16((unsigned short)(mu >> 16)));
                *reinterpret_cast<float2*>(ab + (size_t)k * SS + q) =
                    make_float2(fmaf(acc[wm][wn][h * 2], scale, mv0),
                                fmaf(acc[wm][wn][h * 2 + 1], scale, mv1));
            }
        }
}

// ---------------------------------------------------------------------------
// Output: out[b][k][v] = sum_q attn[b][k][q] * WVT[b][v][q]
// ---------------------------------------------------------------------------
__global__ __launch_bounds__(256, 2)
void out_kernel(const __nv_bfloat16* __restrict__ AtHi, const __nv_bfloat16* __restrict__ AtLo,
                const __nv_bfloat16* __restrict__ WVTHi, const __nv_bfloat16* __restrict__ WVTLo,
                float* __restrict__ out)
{
    extern __shared__ char smem[];
    uint32_t sb = smem_u32(smem);
    const int tid = threadIdx.x, lane = tid & 31, wid = tid >> 5;
    const int warp_m = wid & 1, warp_n = wid >> 1;
    const int m0 = blockIdx.y * BM, n0 = blockIdx.x * BN, b = blockIdx.z;

    float acc[4][4][4];
#pragma unroll
    for (int i = 0; i < 4; i++)
#pragma unroll
        for (int j = 0; j < 4; j++)
#pragma unroll
            for (int r = 0; r < 4; r++) acc[i][j][r] = 0.f;

    FragOff F;
    frag_offsets(lane, warp_m, warp_n, F);

    const size_t abase = (size_t)b * SS * SS;
    const size_t bbase = (size_t)b * DVV * SS;
    gemm_core(sb, AtHi + abase + (size_t)m0 * SS, AtLo + abase + (size_t)m0 * SS, SS,
              WVTHi + bbase + (size_t)n0 * SS, WVTLo + bbase + (size_t)n0 * SS, SS,
              SS, tid, F, acc);

    float* ob = out + (size_t)b * SS * DVV;
#pragma unroll
    for (int wm = 0; wm < 4; wm++)
#pragma unroll
        for (int h = 0; h < 2; h++) {
            int m = m0 + warp_m * 64 + wm * 16 + (lane >> 2) + h * 8;
#pragma unroll
            for (int wn = 0; wn < 4; wn++) {
                int n = n0 + warp_n * 32 + wn * 8 + (lane & 3) * 2;
                *reinterpret_cast<float2*>(ob + (size_t)m * DVV + n) =
                    make_float2(acc[wm][wn][h * 2], acc[wm][wn][h * 2 + 1]);
            }
        }
}

// ---------------------------------------------------------------------------
// In-place row softmax (fp32) + bf16 hi/lo split write for the out GEMM.
// ---------------------------------------------------------------------------
__global__ void softmax_rows(float* __restrict__ p,
                             __nv_bfloat16* __restrict__ hi,
                             __nv_bfloat16* __restrict__ lo)
{
    __shared__ float red[33];
    size_t rb = (size_t)blockIdx.x * SS;
    float* x = p + rb;
    int tid = threadIdx.x;
    float v[8];
    float mx = -1e30f;
#pragma unroll
    for (int i = 0; i < 8; i++) { v[i] = x[tid + i * 256]; mx = fmaxf(mx, v[i]); }
#pragma unroll
    for (int o = 16; o > 0; o >>= 1) mx = fmaxf(mx, __shfl_xor_sync(0xffffffffu, mx, o));
    if ((tid & 31) == 0) red[tid >> 5] = mx;
    __syncthreads();
    if (tid < 32) {
        float m = (tid < 8) ? red[tid] : -1e30f;
#pragma unroll
        for (int o = 4; o > 0; o >>= 1) m = fmaxf(m, __shfl_xor_sync(0xffffffffu, m, o));
        if (tid == 0) red[32] = m;
    }
    __syncthreads();
    mx = red[32];
    float s = 0.f;
#pragma unroll
    for (int i = 0; i < 8; i++) { v[i] = __expf(v[i] - mx); s += v[i]; }
#pragma unroll
    for (int o = 16; o > 0; o >>= 1) s += __shfl_xor_sync(0xffffffffu, s, o);
    if ((tid & 31) == 0) red[tid >> 5] = s;
    __syncthreads();
    if (tid < 32) {
        float m = (tid < 8) ? red[tid] : 0.f;
#pragma unroll
        for (int o = 4; o > 0; o >>= 1) m += __shfl_xor_sync(0xffffffffu, m, o);
        if (tid == 0) red[32] = m;
    }
    __syncthreads();
    float inv = 1.0f / red[32];
#pragma unroll
    for (int i = 0; i < 8; i++) {
        int idx = tid + i * 256;
        float val = v[i] * inv;
        x[idx] = val;
        __nv_bfloat16 h = __float2bfloat16_rn(val);
        hi[rb + idx] = h;
        lo[rb + idx] = __float2bfloat16_rn(val - __bfloat162float(h));
    }
}

// ---------------------------------------------------------------------------
extern "C" void kernel_launch(void* const* d_in, const int* in_sizes, int n_in,
                              void* d_out, int out_size)
{
    const float* Q    = (const float*)d_in[0];
    const float* K    = (const float*)d_in[1];
    const float* V    = (const float*)d_in[2];
    const int*   mask = (const int*)  d_in[3];
    const float* Wq   = (const float*)d_in[4];
    const float* bq   = (const float*)d_in[5];
    const float* Wk   = (const float*)d_in[6];
    const float* bk   = (const float*)d_in[7];
    const float* Wv   = (const float*)d_in[8];
    const float* bv   = (const float*)d_in[9];

    float* out  = (float*)d_out;                   // selfOutput [B,S,Dv]
    float* attn = out + (size_t)NB * SS * DVV;     // attn       [B,S,S]

    static __nv_bfloat16 *pQbHi, *pQbLo, *pKbHi, *pKbLo, *pVbHi, *pVbLo;
    static __nv_bfloat16 *pWqHi, *pWqLo, *pWkHi, *pWkLo, *pWvHi, *pWvLo;
    static __nv_bfloat16 *pQpHi, *pQpLo, *pKpHi, *pKpLo, *pWVTHi, *pWVTLo;
    static __nv_bfloat16 *pAtHi, *pAtLo, *pMkT;
    static bool inited = false;
    if (!inited) {
        cudaGetSymbolAddress((void**)&pQbHi, g_QbHi);   cudaGetSymbolAddress((void**)&pQbLo, g_QbLo);
        cudaGetSymbolAddress((void**)&pKbHi, g_KbHi);   cudaGetSymbolAddress((void**)&pKbLo, g_KbLo);
        cudaGetSymbolAddress((void**)&pVbHi, g_VbHi);   cudaGetSymbolAddress((void**)&pVbLo, g_VbLo);
        cudaGetSymbolAddress((void**)&pWqHi, g_WqHi);   cudaGetSymbolAddress((void**)&pWqLo, g_WqLo);
        cudaGetSymbolAddress((void**)&pWkHi, g_WkHi);   cudaGetSymbolAddress((void**)&pWkLo, g_WkLo);
        cudaGetSymbolAddress((void**)&pWvHi, g_WvHi);   cudaGetSymbolAddress((void**)&pWvLo, g_WvLo);
        cudaGetSymbolAddress((void**)&pQpHi, g_QpHi);   cudaGetSymbolAddress((void**)&pQpLo, g_QpLo);
        cudaGetSymbolAddress((void**)&pKpHi, g_KpHi);   cudaGetSymbolAddress((void**)&pKpLo, g_KpLo);
        cudaGetSymbolAddress((void**)&pWVTHi, g_WVTHi); cudaGetSymbolAddress((void**)&pWVTLo, g_WVTLo);
        cudaGetSymbolAddress((void**)&pAtHi, g_AtHi);   cudaGetSymbolAddress((void**)&pAtLo, g_AtLo);
        cudaGetSymbolAddress((void**)&pMkT, g_MkT);
        cudaFuncSetAttribute(proj_kernel,   cudaFuncAttributeMaxDynamicSharedMemorySize, SMEM_PIPE);
        cudaFuncSetAttribute(scores_kernel, cudaFuncAttributeMaxDynamicSharedMemorySize, SMEM_PIPE);
        cudaFuncSetAttribute(out_kernel,    cudaFuncAttributeMaxDynamicSharedMemorySize, SMEM_PIPE);
        inited = true;
    }

    // 1) Pre-split fp32 inputs to bf16 hi/lo (fused: QKV in one launch, weights in one)
    {
        SplitArgs sa;
        sa.in[0] = Q; sa.in[1] = K; sa.in[2] = V;
        sa.hi[0] = pQbHi; sa.hi[1] = pKbHi; sa.hi[2] = pVbHi;
        sa.lo[0] = pQbLo; sa.lo[1] = pKbLo; sa.lo[2] = pVbLo;
        int n4 = (NB * SS * DD) / 4;
        split3_kernel<<<dim3((n4 + 255) / 256, 1, 3), 256>>>(sa, n4);

        SplitArgs sw;
        sw.in[0] = Wq; sw.in[1] = Wk; sw.in[2] = Wv;
        sw.hi[0] = pWqHi; sw.hi[1] = pWkHi; sw.hi[2] = pWvHi;
        sw.lo[0] = pWqLo; sw.lo[1] = pWkLo; sw.lo[2] = pWvLo;
        int w4 = (AA * DD) / 4;
        split3_kernel<<<dim3((w4 + 255) / 256, 1, 3), 256>>>(sw, w4);
    }
    // 2) Mask transpose + prescale (main stream; fork measured neutral-negative)
    maskT_kernel<<<dim3(SS / 32, SS / 32, NB), dim3(32, 8)>>>(mask, pMkT);

    // 3) Fused projections (Q, K, V in one launch; z selects)
    {
        ProjArgs P;
        P.Ahi[0] = pQbHi; P.Alo[0] = pQbLo; P.Whi[0] = pWqHi; P.Wlo[0] = pWqLo;
        P.bias[0] = bq;   P.Chi[0] = pQpHi; P.Clo[0] = pQpLo;
        P.Ahi[1] = pKbHi; P.Alo[1] = pKbLo; P.Whi[1] = pWkHi; P.Wlo[1] = pWkLo;
        P.bias[1] = bk;   P.Chi[1] = pKpHi; P.Clo[1] = pKpLo;
        P.Ahi[2] = pVbHi; P.Alo[2] = pVbLo; P.Whi[2] = pWvHi; P.Wlo[2] = pWvLo;
        P.bias[2] = bv;   P.Chi[2] = pWVTHi; P.Clo[2] = pWVTLo;
        proj_kernel<<<dim3(4, 128, 3), 256, SMEM_PIPE>>>(P);
    }

    // 4) Masked, pre-transposed scores -> attn (fp32, in d_out)
    scores_kernel<<<dim3(16, 16, NB), 256, SMEM_PIPE>>>(pKpHi, pKpLo, pQpHi, pQpLo, pMkT, attn);
    // 5) Row softmax in place + bf16 hi/lo side-write
    softmax_rows<<<NB * SS, 256>>>(attn, pAtHi, pAtLo);
    // 6) selfOutput = attn @ WV  (K = 2048)
    out_kernel<<<dim3(4, 16, NB), 256, SMEM_PIPE>>>(pAtHi, pAtLo, pWVTHi, pWVTLo, out);
}

// round 10
// speedup vs baseline: 1.7001x; 1.3324x over previous
#include <cuda_runtime.h>
#include <cuda_bf16.h>
#include <cuda_fp16.h>
#include <cstdint>

#define NB 8
#define SS 2048
#define DD 1024
#define AA 512
#define DVV 512

// GEMM tiling: 128x128 CTA tile, BK=32, 3-stage cp.async pipeline, swizzled smem
// fp16 2-pass: planes per stage = A-hi, A-lo, B-hi
#define BM 128
#define BN 128
#define BKC 32
#define ROW64 64                      // bytes per smem row (32 fp16; XOR swizzle)
#define PLANE (128 * ROW64)           // 8192 B per operand plane
#define STAGE (3 * PLANE)             // 24576 B per stage
#define NSTAGE 3
#define SMEM_PIPE (NSTAGE * STAGE)    // 73728 B

// ---------------------------------------------------------------------------
// Scratch (__device__ globals; allocation-free rule)
// ---------------------------------------------------------------------------
__device__ __half g_QbHi[(size_t)NB * SS * DD];
__device__ __half g_QbLo[(size_t)NB * SS * DD];
__device__ __half g_KbHi[(size_t)NB * SS * DD];
__device__ __half g_KbLo[(size_t)NB * SS * DD];
__device__ __half g_VbHi[(size_t)NB * SS * DD];
__device__ __half g_VbLo[(size_t)NB * SS * DD];
__device__ __half g_WqHi[(size_t)AA * DD];     // weights truncated to fp16 (B operand)
__device__ __half g_WkHi[(size_t)AA * DD];
__device__ __half g_WvHi[(size_t)DVV * DD];
__device__ __half g_QpHi[(size_t)NB * SS * AA];    // Qp truncated (B of scores)
__device__ __half g_KpHi[(size_t)NB * SS * AA];    // Kp hi+lo (A of scores)
__device__ __half g_KpLo[(size_t)NB * SS * AA];
__device__ __half g_WVTHi[(size_t)NB * DVV * SS];  // [b][v][s], truncated (B of out)
__device__ __half g_AtHi[(size_t)NB * SS * SS];    // attn hi+lo (A of out)
__device__ __half g_AtLo[(size_t)NB * SS * SS];
__device__ __nv_bfloat16 g_MkT[(size_t)NB * SS * SS];  // -1e9*mask, [b][k][q] (bf16: fp16 overflows)

// ---------------------------------------------------------------------------
// Helpers
// ---------------------------------------------------------------------------
__device__ __forceinline__ uint32_t smem_u32(const void* p) {
    uint32_t a;
    asm("{ .reg .u64 t; cvta.to.shared.u64 t, %1; cvt.u32.u64 %0, t; }" : "=r"(a) : "l"(p));
    return a;
}
__device__ __forceinline__ void cp16(uint32_t dst, const void* src) {
    asm volatile("cp.async.cg.shared.global [%0], [%1], 16;" :: "r"(dst), "l"(src));
}
#define CP_COMMIT() asm volatile("cp.async.commit_group;" ::: "memory")
#define CP_WAIT1()  asm volatile("cp.async.wait_group 1;" ::: "memory")
#define CP_WAIT0()  asm volatile("cp.async.wait_group 0;" ::: "memory")

__device__ __forceinline__ void ldsm4(uint32_t (&r)[4], uint32_t addr) {
    asm volatile("ldmatrix.sync.aligned.m8n8.x4.shared.b16 {%0,%1,%2,%3}, [%4];"
        : "=r"(r[0]), "=r"(r[1]), "=r"(r[2]), "=r"(r[3]) : "r"(addr));
}
__device__ __forceinline__ void mma_f16(float* d, const uint32_t* a, uint32_t b0, uint32_t b1) {
    asm volatile("mma.sync.aligned.m16n8k16.row.col.f32.f16.f16.f32 "
        "{%0,%1,%2,%3}, {%4,%5,%6,%7}, {%8,%9}, {%0,%1,%2,%3};"
        : "+f"(d[0]), "+f"(d[1]), "+f"(d[2]), "+f"(d[3])
        : "r"(a[0]), "r"(a[1]), "r"(a[2]), "r"(a[3]), "r"(b0), "r"(b1));
}
// fp32 -> fp16 hi/lo split (two values packed per u32)
__device__ __forceinline__ void split2h(float a, float b, uint32_t& hi, uint32_t& lo) {
    __half ah = __float2half_rn(a);
    __half bh = __float2half_rn(b);
    __half al = __float2half_rn(a - __half2float(ah));
    __half bl = __float2half_rn(b - __half2float(bh));
    hi = (uint32_t)__half_as_ushort(ah) | ((uint32_t)__half_as_ushort(bh) << 16);
    lo = (uint32_t)__half_as_ushort(al) | ((uint32_t)__half_as_ushort(bl) << 16);
}

// Per-lane ldmatrix offsets (plane-relative, swizzled). [operand][ks]
struct FragOff { uint32_t a[4][2]; uint32_t b[2][2]; };
__device__ __forceinline__ void frag_offsets(int lane, int warp_m, int warp_n, FragOff& F) {
    int ha = lane >> 4;                      // A k-half (0/1)
#pragma unroll
    for (int wm = 0; wm < 4; wm++) {
        int row = warp_m * 64 + wm * 16 + (lane & 15);
        int x = (row >> 1) & 3;
#pragma unroll
        for (int ks = 0; ks < 2; ks++)
            F.a[wm][ks] = (uint32_t)(row * ROW64 + (((ks * 2 + ha) ^ x) << 4));
    }
    int rb = (lane & 7) + ((lane >> 4) << 3);
    int hb = (lane & 8) ? 1 : 0;             // B k-half
#pragma unroll
    for (int p = 0; p < 2; p++) {
        int row = warp_n * 32 + p * 16 + rb;
        int x = (row >> 1) & 3;
#pragma unroll
        for (int ks = 0; ks < 2; ks++)
            F.b[p][ks] = (uint32_t)(row * ROW64 + (((ks * 2 + hb) ^ x) << 4));
    }
}

// Issue cp.async for one BK=32 chunk (3 planes: Ahi, Alo, Bhi)
__device__ __forceinline__ void issue_cp(uint32_t sbase,
    const __half* __restrict__ Ahi, const __half* __restrict__ Alo, int lda,
    const __half* __restrict__ Bhi, int ldb,
    int k0, int tid)
{
    const int lrow = tid >> 1;
    const int c0 = (tid & 1) * 2;
    const int x = (lrow >> 1) & 3;
    const int koff = k0 + (tid & 1) * 16;
    uint32_t d0 = sbase + (uint32_t)(lrow * ROW64 + ((c0 ^ x) << 4));
    uint32_t d1 = sbase + (uint32_t)(lrow * ROW64 + (((c0 + 1) ^ x) << 4));
    const __half* a0 = Ahi + (size_t)lrow * lda + koff;
    const __half* a1 = Alo + (size_t)lrow * lda + koff;
    const __half* b0 = Bhi + (size_t)lrow * ldb + koff;
    cp16(d0, a0);               cp16(d1, a0 + 8);
    cp16(d0 + PLANE, a1);       cp16(d1 + PLANE, a1 + 8);
    cp16(d0 + 2 * PLANE, b0);   cp16(d1 + 2 * PLANE, b0 + 8);
}

// One BK=32 chunk of fp16 2-pass MMA (R5 interleave pattern)
__device__ __forceinline__ void mma_chunk32(uint32_t sb, const FragOff& F, float (*acc)[4][4]) {
#pragma unroll
    for (int ks = 0; ks < 2; ks++) {
        uint32_t af[4][4], bh[2][4];
#pragma unroll
        for (int wm = 0; wm < 4; wm++) ldsm4(af[wm], sb + F.a[wm][ks]);
#pragma unroll
        for (int p = 0; p < 2; p++) ldsm4(bh[p], sb + 2 * PLANE + F.b[p][ks]);
#pragma unroll
        for (int wm = 0; wm < 4; wm++)
#pragma unroll
            for (int wn = 0; wn < 4; wn++)
                mma_f16(acc[wm][wn], af[wm], bh[wn >> 1][(wn & 1) * 2], bh[wn >> 1][(wn & 1) * 2 + 1]);
#pragma unroll
        for (int wm = 0; wm < 4; wm++) ldsm4(af[wm], sb + PLANE + F.a[wm][ks]);
#pragma unroll
        for (int wm = 0; wm < 4; wm++)
#pragma unroll
            for (int wn = 0; wn < 4; wn++)
                mma_f16(acc[wm][wn], af[wm], bh[wn >> 1][(wn & 1) * 2], bh[wn >> 1][(wn & 1) * 2 + 1]);
    }
}

// 3-stage pipelined fp16 GEMM core (acc += A * B^T over K)
__device__ __forceinline__ void gemm_core(uint32_t sb,
    const __half* Ahi, const __half* Alo, int lda,
    const __half* Bhi, int ldb,
    int K, int tid, const FragOff& F, float (*acc)[4][4])
{
    const int nch = K / BKC;
    issue_cp(sb, Ahi, Alo, lda, Bhi, ldb, 0, tid);
    CP_COMMIT();
    issue_cp(sb + STAGE, Ahi, Alo, lda, Bhi, ldb, BKC, tid);
    CP_COMMIT();
    uint32_t cur = 0, nxt2 = 2 * STAGE;
    for (int ch = 0; ch < nch; ch++) {
        if (ch < nch - 1) { CP_WAIT1(); } else { CP_WAIT0(); }
        __syncthreads();
        if (ch + 2 < nch) {
            issue_cp(sb + nxt2, Ahi, Alo, lda, Bhi, ldb, (ch + 2) * BKC, tid);
            CP_COMMIT();
        }
        mma_chunk32(sb + cur, F, acc);
        cur = (cur == (NSTAGE - 1) * STAGE) ? 0 : cur + STAGE;
        nxt2 = (nxt2 == (NSTAGE - 1) * STAGE) ? 0 : nxt2 + STAGE;
    }
    __syncthreads();
}

// ---------------------------------------------------------------------------
// Fused elementwise fp32 -> fp16 hi/lo split (3 tensors via blockIdx.z)
// ---------------------------------------------------------------------------
struct SplitArgs {
    const float* in[3];
    __half* hi[3];
    __half* lo[3];
};
__global__ void split3_kernel(SplitArgs a, int n4)
{
    int z = blockIdx.z;
    int i = blockIdx.x * blockDim.x + threadIdx.x;
    if (i < n4) {
        float4 v = reinterpret_cast<const float4*>(a.in[z])[i];
        uint32_t h0, l0, h1, l1;
        split2h(v.x, v.y, h0, l0);
        split2h(v.z, v.w, h1, l1);
        reinterpret_cast<uint2*>(a.hi[z])[i] = make_uint2(h0, h1);
        reinterpret_cast<uint2*>(a.lo[z])[i] = make_uint2(l0, l1);
    }
}

// Fused fp32 -> fp16 convert (hi only; weights)
struct ConvArgs {
    const float* in[3];
    __half* hi[3];
};
__global__ void conv3_kernel(ConvArgs a, int n4)
{
    int z = blockIdx.z;
    int i = blockIdx.x * blockDim.x + threadIdx.x;
    if (i < n4) {
        float4 v = reinterpret_cast<const float4*>(a.in[z])[i];
        __half2 h01 = __floats2half2_rn(v.x, v.y);
        __half2 h23 = __floats2half2_rn(v.z, v.w);
        reinterpret_cast<uint2*>(a.hi[z])[i] =
            make_uint2(*reinterpret_cast<uint32_t*>(&h01), *reinterpret_cast<uint32_t*>(&h23));
    }
}

// ---------------------------------------------------------------------------
// Mask transpose + prescale: mT[b][k][q] = bf16(-1e9 * mask[b][q][k])
// ---------------------------------------------------------------------------
__global__ __launch_bounds__(256)
void maskT_kernel(const int* __restrict__ mask, __nv_bfloat16* __restrict__ mT)
{
    __shared__ float t[32][33];
    const int b = blockIdx.z;
    const int q0 = blockIdx.y * 32, k0 = blockIdx.x * 32;
    const int* mb = mask + (size_t)b * SS * SS;
    __nv_bfloat16* ob = mT + (size_t)b * SS * SS;
#pragma unroll
    for (int i = 0; i < 4; i++) {
        int q = q0 + threadIdx.y + i * 8;
        t[threadIdx.y + i * 8][threadIdx.x] =
            -1e9f * (float)mb[(size_t)q * SS + k0 + threadIdx.x];
    }
    __syncthreads();
#pragma unroll
    for (int i = 0; i < 4; i++) {
        int k = k0 + threadIdx.y + i * 8;
        ob[(size_t)k * SS + q0 + threadIdx.x] =
            __float2bfloat16_rn(t[threadIdx.x][threadIdx.y + i * 8]);
    }
}

// ---------------------------------------------------------------------------
// Fused projection (Q/K/V via blockIdx.z): C = A*W^T + bias.
// z==0 (Q): write hi only (Qp is B of scores — truncated).
// z==1 (K): write hi+lo (Kp is A of scores).
// z==2 (V): write WVT[b][n][s] hi only via smem transpose (B of out).
// ---------------------------------------------------------------------------
struct ProjArgs {
    const __half *Ahi[3], *Alo[3], *Whi[3];
    const float* bias[3];
    __half *Chi[3], *Clo[3];   // Clo used only for z==1
};
__global__ __launch_bounds__(256, 2)
void proj_kernel(ProjArgs P)
{
    extern __shared__ char smem[];
    uint32_t sb = smem_u32(smem);
    const int tid = threadIdx.x, lane = tid & 31, wid = tid >> 5;
    const int warp_m = wid & 1, warp_n = wid >> 1;
    const int m0 = blockIdx.y * BM, n0 = blockIdx.x * BN;
    const int z = blockIdx.z;
    const __half* Ahi = P.Ahi[z];
    const __half* Alo = P.Alo[z];
    const __half* Whi = P.Whi[z];
    const float* bias = P.bias[z];
    __half* Chi = P.Chi[z];
    __half* Clo = P.Clo[z];

    float acc[4][4][4];
#pragma unroll
    for (int i = 0; i < 4; i++)
#pragma unroll
        for (int j = 0; j < 4; j++)
#pragma unroll
            for (int r = 0; r < 4; r++) acc[i][j][r] = 0.f;

    FragOff F;
    frag_offsets(lane, warp_m, warp_n, F);

    gemm_core(sb, Ahi + (size_t)m0 * DD, Alo + (size_t)m0 * DD, DD,
              Whi + (size_t)n0 * DD, DD, DD, tid, F, acc);

    if (z != 2) {
#pragma unroll
        for (int wn = 0; wn < 4; wn++) {
            int n = n0 + warp_n * 32 + wn * 8 + (lane & 3) * 2;
            float b0 = bias[n], b1 = bias[n + 1];
#pragma unroll
            for (int wm = 0; wm < 4; wm++)
#pragma unroll
                for (int h = 0; h < 2; h++) {
                    int m = m0 + warp_m * 64 + wm * 16 + (lane >> 2) + h * 8;
                    uint32_t hv, lv;
                    split2h(acc[wm][wn][h * 2] + b0, acc[wm][wn][h * 2 + 1] + b1, hv, lv);
                    *reinterpret_cast<uint32_t*>(Chi + (size_t)m * AA + n) = hv;
                    if (z == 1)
                        *reinterpret_cast<uint32_t*>(Clo + (size_t)m * AA + n) = lv;
                }
        }
    } else {
        // Transpose hi plane only through smem: rows = local n (128), 272B stride
        char* T = smem;
#pragma unroll
        for (int wn = 0; wn < 4; wn++) {
            int ln = warp_n * 32 + wn * 8 + (lane & 3) * 2;
            float b0 = bias[n0 + ln], b1 = bias[n0 + ln + 1];
#pragma unroll
            for (int wm = 0; wm < 4; wm++)
#pragma unroll
                for (int h = 0; h < 2; h++) {
                    int lm = warp_m * 64 + wm * 16 + (lane >> 2) + h * 8;
                    *reinterpret_cast<__half*>(T + ln * 272 + lm * 2) =
                        __float2half_rn(acc[wm][wn][h * 2] + b0);
                    *reinterpret_cast<__half*>(T + (ln + 1) * 272 + lm * 2) =
                        __float2half_rn(acc[wm][wn][h * 2 + 1] + b1);
                }
        }
        __syncthreads();
        int v = tid >> 1, hs = (tid & 1) * 64;
        size_t b = (size_t)(m0 >> 11);
        int s0 = m0 & (SS - 1);
        __half* dh = Chi + (b * DVV + n0 + v) * SS + s0 + hs;
#pragma unroll
        for (int g = 0; g < 8; g++)
            *reinterpret_cast<uint4*>(dh + g * 8) =
                *reinterpret_cast<uint4*>(T + v * 272 + (hs + g * 8) * 2);
    }
}

// ---------------------------------------------------------------------------
// Scores (pre-transposed): attn[b][k][q] = scale*Kp[k]·Qp[q] + mT[b][k][q]
// A = Kp (hi+lo), B = Qp (hi)
// ---------------------------------------------------------------------------
__global__ __launch_bounds__(256, 2)
void scores_kernel(const __half* __restrict__ KpHi, const __half* __restrict__ KpLo,
                   const __half* __restrict__ QpHi,
                   const __nv_bfloat16* __restrict__ mT, float* __restrict__ attn)
{
    extern __shared__ char smem[];
    uint32_t sb = smem_u32(smem);
    const int tid = threadIdx.x, lane = tid & 31, wid = tid >> 5;
    const int warp_m = wid & 1, warp_n = wid >> 1;
    const int m0 = blockIdx.y * BM, n0 = blockIdx.x * BN, b = blockIdx.z;

    float acc[4][4][4];
#pragma unroll
    for (int i = 0; i < 4; i++)
#pragma unroll
        for (int j = 0; j < 4; j++)
#pragma unroll
            for (int r = 0; r < 4; r++) acc[i][j][r] = 0.f;

    FragOff F;
    frag_offsets(lane, warp_m, warp_n, F);

    const size_t base = (size_t)b * SS * AA;
    gemm_core(sb, KpHi + base + (size_t)m0 * AA, KpLo + base + (size_t)m0 * AA, AA,
              QpHi + base + (size_t)n0 * AA, AA, AA, tid, F, acc);

    const float scale = 0.04419417382415922f;   // 1/sqrt(512)
    const __nv_bfloat16* mb = mT + (size_t)b * SS * SS;
    float* ab = attn + (size_t)b * SS * SS;
#pragma unroll
    for (int wm = 0; wm < 4; wm++)
#pragma unroll
        for (int h = 0; h < 2; h++) {
            int k = m0 + warp_m * 64 + wm * 16 + (lane >> 2) + h * 8;
#pragma unroll
            for (int wn = 0; wn < 4; wn++) {
                int q = n0 + warp_n * 32 + wn * 8 + (lane & 3) * 2;
                uint32_t mu = *reinterpret_cast<const uint32_t*>(mb + (size_t)k * SS + q);
                float mv0 = __bfloat162float(__ushort_as_bfloat16((unsigned short)(mu & 0xFFFF)));
                float mv1 = __bfloat162float(__ushort_as_bfloat16((unsigned short)(mu >> 16)));
                *reinterpret_cast<float2*>(ab + (size_t)k * SS + q) =
                    make_float2(fmaf(acc[wm][wn][h * 2], scale, mv0),
                                fmaf(acc[wm][wn][h * 2 + 1], scale, mv1));
            }
        }
}

// ---------------------------------------------------------------------------
// Output: out[b][k][v] = sum_q attn[b][k][q] * WVT[b][v][q]
// A = attn (hi+lo), B = WVT (hi)
// ---------------------------------------------------------------------------
__global__ __launch_bounds__(256, 2)
void out_kernel(const __half* __restrict__ AtHi, const __half* __restrict__ AtLo,
                const __half* __restrict__ WVTHi, float* __restrict__ out)
{
    extern __shared__ char smem[];
    uint32_t sb = smem_u32(smem);
    const int tid = threadIdx.x, lane = tid & 31, wid = tid >> 5;
    const int warp_m = wid & 1, warp_n = wid >> 1;
    const int m0 = blockIdx.y * BM, n0 = blockIdx.x * BN, b = blockIdx.z;

    float acc[4][4][4];
#pragma unroll
    for (int i = 0; i < 4; i++)
#pragma unroll
        for (int j = 0; j < 4; j++)
#pragma unroll
            for (int r = 0; r < 4; r++) acc[i][j][r] = 0.f;

    FragOff F;
    frag_offsets(lane, warp_m, warp_n, F);

    const size_t abase = (size_t)b * SS * SS;
    const size_t bbase = (size_t)b * DVV * SS;
    gemm_core(sb, AtHi + abase + (size_t)m0 * SS, AtLo + abase + (size_t)m0 * SS, SS,
              WVTHi + bbase + (size_t)n0 * SS, SS, SS, tid, F, acc);

    float* ob = out + (size_t)b * SS * DVV;
#pragma unroll
    for (int wm = 0; wm < 4; wm++)
#pragma unroll
        for (int h = 0; h < 2; h++) {
            int m = m0 + warp_m * 64 + wm * 16 + (lane >> 2) + h * 8;
#pragma unroll
            for (int wn = 0; wn < 4; wn++) {
                int n = n0 + warp_n * 32 + wn * 8 + (lane & 3) * 2;
                *reinterpret_cast<float2*>(ob + (size_t)m * DVV + n) =
                    make_float2(acc[wm][wn][h * 2], acc[wm][wn][h * 2 + 1]);
            }
        }
}

// ---------------------------------------------------------------------------
// In-place row softmax (fp32) + fp16 hi/lo split write for the out GEMM.
// ---------------------------------------------------------------------------
__global__ void softmax_rows(float* __restrict__ p,
                             __half* __restrict__ hi,
                             __half* __restrict__ lo)
{
    __shared__ float red[33];
    size_t rb = (size_t)blockIdx.x * SS;
    float* x = p + rb;
    int tid = threadIdx.x;
    float v[8];
    float mx = -1e30f;
#pragma unroll
    for (int i = 0; i < 8; i++) { v[i] = x[tid + i * 256]; mx = fmaxf(mx, v[i]); }
#pragma unroll
    for (int o = 16; o > 0; o >>= 1) mx = fmaxf(mx, __shfl_xor_sync(0xffffffffu, mx, o));
    if ((tid & 31) == 0) red[tid >> 5] = mx;
    __syncthreads();
    if (tid < 32) {
        float m = (tid < 8) ? red[tid] : -1e30f;
#pragma unroll
        for (int o = 4; o > 0; o >>= 1) m = fmaxf(m, __shfl_xor_sync(0xffffffffu, m, o));
        if (tid == 0) red[32] = m;
    }
    __syncthreads();
    mx = red[32];
    float s = 0.f;
#pragma unroll
    for (int i = 0; i < 8; i++) { v[i] = __expf(v[i] - mx); s += v[i]; }
#pragma unroll
    for (int o = 16; o > 0; o >>= 1) s += __shfl_xor_sync(0xffffffffu, s, o);
    if ((tid & 31) == 0) red[tid >> 5] = s;
    __syncthreads();
    if (tid < 32) {
        float m = (tid < 8) ? red[tid] : 0.f;
#pragma unroll
        for (int o = 4; o > 0; o >>= 1) m += __shfl_xor_sync(0xffffffffu, m, o);
        if (tid == 0) red[32] = m;
    }
    __syncthreads();
    float inv = 1.0f / red[32];
#pragma unroll
    for (int i = 0; i < 8; i++) {
        int idx = tid + i * 256;
        float val = v[i] * inv;
        x[idx] = val;
        __half h = __float2half_rn(val);
        hi[rb + idx] = h;
        lo[rb + idx] = __float2half_rn(val - __half2float(h));
    }
}

// ---------------------------------------------------------------------------
extern "C" void kernel_launch(void* const* d_in, const int* in_sizes, int n_in,
                              void* d_out, int out_size)
{
    const float* Q    = (const float*)d_in[0];
    const float* K    = (const float*)d_in[1];
    const float* V    = (const float*)d_in[2];
    const int*   mask = (const int*)  d_in[3];
    const float* Wq   = (const float*)d_in[4];
    const float* bq   = (const float*)d_in[5];
    const float* Wk   = (const float*)d_in[6];
    const float* bk   = (const float*)d_in[7];
    const float* Wv   = (const float*)d_in[8];
    const float* bv   = (const float*)d_in[9];

    float* out  = (float*)d_out;                   // selfOutput [B,S,Dv]
    float* attn = out + (size_t)NB * SS * DVV;     // attn       [B,S,S]

    static __half *pQbHi, *pQbLo, *pKbHi, *pKbLo, *pVbHi, *pVbLo;
    static __half *pWqHi, *pWkHi, *pWvHi;
    static __half *pQpHi, *pKpHi, *pKpLo, *pWVTHi, *pAtHi, *pAtLo;
    static __nv_bfloat16 *pMkT;
    static bool inited = false;
    if (!inited) {
        cudaGetSymbolAddress((void**)&pQbHi, g_QbHi);   cudaGetSymbolAddress((void**)&pQbLo, g_QbLo);
        cudaGetSymbolAddress((void**)&pKbHi, g_KbHi);   cudaGetSymbolAddress((void**)&pKbLo, g_KbLo);
        cudaGetSymbolAddress((void**)&pVbHi, g_VbHi);   cudaGetSymbolAddress((void**)&pVbLo, g_VbLo);
        cudaGetSymbolAddress((void**)&pWqHi, g_WqHi);
        cudaGetSymbolAddress((void**)&pWkHi, g_WkHi);
        cudaGetSymbolAddress((void**)&pWvHi, g_WvHi);
        cudaGetSymbolAddress((void**)&pQpHi, g_QpHi);
        cudaGetSymbolAddress((void**)&pKpHi, g_KpHi);   cudaGetSymbolAddress((void**)&pKpLo, g_KpLo);
        cudaGetSymbolAddress((void**)&pWVTHi, g_WVTHi);
        cudaGetSymbolAddress((void**)&pAtHi, g_AtHi);   cudaGetSymbolAddress((void**)&pAtLo, g_AtLo);
        cudaGetSymbolAddress((void**)&pMkT, g_MkT);
        cudaFuncSetAttribute(proj_kernel,   cudaFuncAttributeMaxDynamicSharedMemorySize, SMEM_PIPE);
        cudaFuncSetAttribute(scores_kernel, cudaFuncAttributeMaxDynamicSharedMemorySize, SMEM_PIPE);
        cudaFuncSetAttribute(out_kernel,    cudaFuncAttributeMaxDynamicSharedMemorySize, SMEM_PIPE);
        inited = true;
    }

    // 1) Pre-split fp32 inputs to fp16 hi/lo; weights to fp16 (hi only)
    {
        SplitArgs sa;
        sa.in[0] = Q; sa.in[1] = K; sa.in[2] = V;
        sa.hi[0] = pQbHi; sa.hi[1] = pKbHi; sa.hi[2] = pVbHi;
        sa.lo[0] = pQbLo; sa.lo[1] = pKbLo; sa.lo[2] = pVbLo;
        int n4 = (NB * SS * DD) / 4;
        split3_kernel<<<dim3((n4 + 255) / 256, 1, 3), 256>>>(sa, n4);

        ConvArgs cw;
        cw.in[0] = Wq; cw.in[1] = Wk; cw.in[2] = Wv;
        cw.hi[0] = pWqHi; cw.hi[1] = pWkHi; cw.hi[2] = pWvHi;
        int w4 = (AA * DD) / 4;
        conv3_kernel<<<dim3((w4 + 255) / 256, 1, 3), 256>>>(cw, w4);
    }
    // 2) Mask transpose + prescale
    maskT_kernel<<<dim3(SS / 32, SS / 32, NB), dim3(32, 8)>>>(mask, pMkT);

    // 3) Fused projections (Q, K, V in one launch; z selects)
    {
        ProjArgs P;
        P.Ahi[0] = pQbHi; P.Alo[0] = pQbLo; P.Whi[0] = pWqHi;
        P.bias[0] = bq;   P.Chi[0] = pQpHi; P.Clo[0] = nullptr;
        P.Ahi[1] = pKbHi; P.Alo[1] = pKbLo; P.Whi[1] = pWkHi;
        P.bias[1] = bk;   P.Chi[1] = pKpHi; P.Clo[1] = pKpLo;
        P.Ahi[2] = pVbHi; P.Alo[2] = pVbLo; P.Whi[2] = pWvHi;
        P.bias[2] = bv;   P.Chi[2] = pWVTHi; P.Clo[2] = nullptr;
        proj_kernel<<<dim3(4, 128, 3), 256, SMEM_PIPE>>>(P);
    }

    // 4) Masked, pre-transposed scores -> attn (fp32, in d_out)
    scores_kernel<<<dim3(16, 16, NB), 256, SMEM_PIPE>>>(pKpHi, pKpLo, pQpHi, pMkT, attn);
    // 5) Row softmax in place + fp16 hi/lo side-write
    softmax_rows<<<NB * SS, 256>>>(attn, pAtHi, pAtLo);
    // 6) selfOutput = attn @ WV  (K = 2048)
    out_kernel<<<dim3(4, 16, NB), 256, SMEM_PIPE>>>(pAtHi, pAtLo, pWVTHi, out);
}

// round 11
// speedup vs baseline: 1.7265x; 1.0156x over previous
#include <cuda_runtime.h>
#include <cuda_bf16.h>
#include <cuda_fp16.h>
#include <cstdint>

#define NB 8
#define SS 2048
#define DD 1024
#define AA 512
#define DVV 512

// GEMM tiling: 128x128 CTA tile, BK=32, 4-stage cp.async pipeline, swizzled smem
// fp16 2-pass: planes per stage = A-hi, A-lo, B-hi
#define BM 128
#define BN 128
#define BKC 32
#define ROW64 64                      // bytes per smem row (32 fp16; XOR swizzle)
#define PLANE (128 * ROW64)           // 8192 B per operand plane
#define STAGE (3 * PLANE)             // 24576 B per stage
#define NSTAGE 4
#define SMEM_PIPE (NSTAGE * STAGE)    // 98304 B

// ---------------------------------------------------------------------------
// Scratch (__device__ globals; allocation-free rule)
// ---------------------------------------------------------------------------
__device__ __half g_QbHi[(size_t)NB * SS * DD];
__device__ __half g_QbLo[(size_t)NB * SS * DD];   // unused by Q-proj (1-pass) but kept for layout symmetry
__device__ __half g_KbHi[(size_t)NB * SS * DD];
__device__ __half g_KbLo[(size_t)NB * SS * DD];
__device__ __half g_VbHi[(size_t)NB * SS * DD];
__device__ __half g_VbLo[(size_t)NB * SS * DD];
__device__ __half g_WqHi[(size_t)AA * DD];
__device__ __half g_WkHi[(size_t)AA * DD];
__device__ __half g_WvHi[(size_t)DVV * DD];
__device__ __half g_QpHi[(size_t)NB * SS * AA];    // Qp truncated (B of scores)
__device__ __half g_KpHi[(size_t)NB * SS * AA];    // Kp hi+lo (A of scores)
__device__ __half g_KpLo[(size_t)NB * SS * AA];
__device__ __half g_WVTHi[(size_t)NB * DVV * SS];  // [b][v][s], truncated (B of out)
__device__ __half g_AtHi[(size_t)NB * SS * SS];    // attn hi+lo (A of out)
__device__ __half g_AtLo[(size_t)NB * SS * SS];
__device__ __nv_bfloat16 g_MkT[(size_t)NB * SS * SS];  // -1e9*mask, [b][k][q]

// ---------------------------------------------------------------------------
// Helpers
// ---------------------------------------------------------------------------
__device__ __forceinline__ uint32_t smem_u32(const void* p) {
    uint32_t a;
    asm("{ .reg .u64 t; cvta.to.shared.u64 t, %1; cvt.u32.u64 %0, t; }" : "=r"(a) : "l"(p));
    return a;
}
__device__ __forceinline__ void cp16(uint32_t dst, const void* src) {
    asm volatile("cp.async.cg.shared.global [%0], [%1], 16;" :: "r"(dst), "l"(src));
}
#define CP_COMMIT() asm volatile("cp.async.commit_group;" ::: "memory")
#define CP_WAIT2()  asm volatile("cp.async.wait_group 2;" ::: "memory")
#define CP_WAIT1()  asm volatile("cp.async.wait_group 1;" ::: "memory")
#define CP_WAIT0()  asm volatile("cp.async.wait_group 0;" ::: "memory")

__device__ __forceinline__ void ldsm4(uint32_t (&r)[4], uint32_t addr) {
    asm volatile("ldmatrix.sync.aligned.m8n8.x4.shared.b16 {%0,%1,%2,%3}, [%4];"
        : "=r"(r[0]), "=r"(r[1]), "=r"(r[2]), "=r"(r[3]) : "r"(addr));
}
__device__ __forceinline__ void mma_f16(float* d, const uint32_t* a, uint32_t b0, uint32_t b1) {
    asm volatile("mma.sync.aligned.m16n8k16.row.col.f32.f16.f16.f32 "
        "{%0,%1,%2,%3}, {%4,%5,%6,%7}, {%8,%9}, {%0,%1,%2,%3};"
        : "+f"(d[0]), "+f"(d[1]), "+f"(d[2]), "+f"(d[3])
        : "r"(a[0]), "r"(a[1]), "r"(a[2]), "r"(a[3]), "r"(b0), "r"(b1));
}
__device__ __forceinline__ void split2h(float a, float b, uint32_t& hi, uint32_t& lo) {
    __half ah = __float2half_rn(a);
    __half bh = __float2half_rn(b);
    __half al = __float2half_rn(a - __half2float(ah));
    __half bl = __float2half_rn(b - __half2float(bh));
    hi = (uint32_t)__half_as_ushort(ah) | ((uint32_t)__half_as_ushort(bh) << 16);
    lo = (uint32_t)__half_as_ushort(al) | ((uint32_t)__half_as_ushort(bl) << 16);
}

// Per-lane ldmatrix offsets (plane-relative, swizzled). [operand][ks]
struct FragOff { uint32_t a[4][2]; uint32_t b[2][2]; };
__device__ __forceinline__ void frag_offsets(int lane, int warp_m, int warp_n, FragOff& F) {
    int ha = lane >> 4;                      // A k-half (0/1)
#pragma unroll
    for (int wm = 0; wm < 4; wm++) {
        int row = warp_m * 64 + wm * 16 + (lane & 15);
        int x = (row >> 1) & 3;
#pragma unroll
        for (int ks = 0; ks < 2; ks++)
            F.a[wm][ks] = (uint32_t)(row * ROW64 + (((ks * 2 + ha) ^ x) << 4));
    }
    int rb = (lane & 7) + ((lane >> 4) << 3);
    int hb = (lane & 8) ? 1 : 0;             // B k-half
#pragma unroll
    for (int p = 0; p < 2; p++) {
        int row = warp_n * 32 + p * 16 + rb;
        int x = (row >> 1) & 3;
#pragma unroll
        for (int ks = 0; ks < 2; ks++)
            F.b[p][ks] = (uint32_t)(row * ROW64 + (((ks * 2 + hb) ^ x) << 4));
    }
}

// Issue cp.async for one BK=32 chunk (Ahi + Bhi always; Alo only if npass==2)
__device__ __forceinline__ void issue_cp(uint32_t sbase,
    const __half* __restrict__ Ahi, const __half* __restrict__ Alo, int lda,
    const __half* __restrict__ Bhi, int ldb,
    int k0, int tid, int npass)
{
    const int lrow = tid >> 1;
    const int c0 = (tid & 1) * 2;
    const int x = (lrow >> 1) & 3;
    const int koff = k0 + (tid & 1) * 16;
    uint32_t d0 = sbase + (uint32_t)(lrow * ROW64 + ((c0 ^ x) << 4));
    uint32_t d1 = sbase + (uint32_t)(lrow * ROW64 + (((c0 + 1) ^ x) << 4));
    const __half* a0 = Ahi + (size_t)lrow * lda + koff;
    const __half* b0 = Bhi + (size_t)lrow * ldb + koff;
    cp16(d0, a0);               cp16(d1, a0 + 8);
    if (npass == 2) {
        const __half* a1 = Alo + (size_t)lrow * lda + koff;
        cp16(d0 + PLANE, a1);   cp16(d1 + PLANE, a1 + 8);
    }
    cp16(d0 + 2 * PLANE, b0);   cp16(d1 + 2 * PLANE, b0 + 8);
}

// One BK=32 chunk of fp16 MMA (R5 interleave; second pass only if npass==2)
__device__ __forceinline__ void mma_chunk32(uint32_t sb, const FragOff& F,
                                            float (*acc)[4][4], int npass) {
#pragma unroll
    for (int ks = 0; ks < 2; ks++) {
        uint32_t af[4][4], bh[2][4];
#pragma unroll
        for (int wm = 0; wm < 4; wm++) ldsm4(af[wm], sb + F.a[wm][ks]);
#pragma unroll
        for (int p = 0; p < 2; p++) ldsm4(bh[p], sb + 2 * PLANE + F.b[p][ks]);
#pragma unroll
        for (int wm = 0; wm < 4; wm++)
#pragma unroll
            for (int wn = 0; wn < 4; wn++)
                mma_f16(acc[wm][wn], af[wm], bh[wn >> 1][(wn & 1) * 2], bh[wn >> 1][(wn & 1) * 2 + 1]);
        if (npass == 2) {
#pragma unroll
            for (int wm = 0; wm < 4; wm++) ldsm4(af[wm], sb + PLANE + F.a[wm][ks]);
#pragma unroll
            for (int wm = 0; wm < 4; wm++)
#pragma unroll
                for (int wn = 0; wn < 4; wn++)
                    mma_f16(acc[wm][wn], af[wm], bh[wn >> 1][(wn & 1) * 2], bh[wn >> 1][(wn & 1) * 2 + 1]);
        }
    }
}

// 4-stage pipelined fp16 GEMM core, 3-chunk lookahead (acc += A * B^T over K)
__device__ __forceinline__ void gemm_core(uint32_t sb,
    const __half* Ahi, const __half* Alo, int lda,
    const __half* Bhi, int ldb,
    int K, int tid, const FragOff& F, float (*acc)[4][4], int npass)
{
    const int nch = K / BKC;
    issue_cp(sb, Ahi, Alo, lda, Bhi, ldb, 0, tid, npass);
    CP_COMMIT();
    issue_cp(sb + STAGE, Ahi, Alo, lda, Bhi, ldb, BKC, tid, npass);
    CP_COMMIT();
    issue_cp(sb + 2 * STAGE, Ahi, Alo, lda, Bhi, ldb, 2 * BKC, tid, npass);
    CP_COMMIT();
    uint32_t cur = 0, nxt3 = 3 * STAGE;
    for (int ch = 0; ch < nch; ch++) {
        int rem = nch - 1 - ch;
        if (rem >= 2) { CP_WAIT2(); } else if (rem == 1) { CP_WAIT1(); } else { CP_WAIT0(); }
        __syncthreads();
        if (ch + 3 < nch) {
            issue_cp(sb + nxt3, Ahi, Alo, lda, Bhi, ldb, (ch + 3) * BKC, tid, npass);
            CP_COMMIT();
        }
        mma_chunk32(sb + cur, F, acc, npass);
        cur = (cur == (NSTAGE - 1) * STAGE) ? 0 : cur + STAGE;
        nxt3 = (nxt3 == (NSTAGE - 1) * STAGE) ? 0 : nxt3 + STAGE;
    }
    __syncthreads();
}

// ---------------------------------------------------------------------------
// Fused elementwise fp32 -> fp16 hi/lo split (3 tensors via blockIdx.z)
// ---------------------------------------------------------------------------
struct SplitArgs {
    const float* in[3];
    __half* hi[3];
    __half* lo[3];
};
__global__ void split3_kernel(SplitArgs a, int n4)
{
    int z = blockIdx.z;
    int i = blockIdx.x * blockDim.x + threadIdx.x;
    if (i < n4) {
        float4 v = reinterpret_cast<const float4*>(a.in[z])[i];
        uint32_t h0, l0, h1, l1;
        split2h(v.x, v.y, h0, l0);
        split2h(v.z, v.w, h1, l1);
        reinterpret_cast<uint2*>(a.hi[z])[i] = make_uint2(h0, h1);
        if (a.lo[z])
            reinterpret_cast<uint2*>(a.lo[z])[i] = make_uint2(l0, l1);
    }
}

struct ConvArgs {
    const float* in[3];
    __half* hi[3];
};
__global__ void conv3_kernel(ConvArgs a, int n4)
{
    int z = blockIdx.z;
    int i = blockIdx.x * blockDim.x + threadIdx.x;
    if (i < n4) {
        float4 v = reinterpret_cast<const float4*>(a.in[z])[i];
        __half2 h01 = __floats2half2_rn(v.x, v.y);
        __half2 h23 = __floats2half2_rn(v.z, v.w);
        reinterpret_cast<uint2*>(a.hi[z])[i] =
            make_uint2(*reinterpret_cast<uint32_t*>(&h01), *reinterpret_cast<uint32_t*>(&h23));
    }
}

// ---------------------------------------------------------------------------
// Mask transpose + prescale: mT[b][k][q] = bf16(-1e9 * mask[b][q][k])
// ---------------------------------------------------------------------------
__global__ __launch_bounds__(256)
void maskT_kernel(const int* __restrict__ mask, __nv_bfloat16* __restrict__ mT)
{
    __shared__ float t[32][33];
    const int b = blockIdx.z;
    const int q0 = blockIdx.y * 32, k0 = blockIdx.x * 32;
    const int* mb = mask + (size_t)b * SS * SS;
    __nv_bfloat16* ob = mT + (size_t)b * SS * SS;
#pragma unroll
    for (int i = 0; i < 4; i++) {
        int q = q0 + threadIdx.y + i * 8;
        t[threadIdx.y + i * 8][threadIdx.x] =
            -1e9f * (float)mb[(size_t)q * SS + k0 + threadIdx.x];
    }
    __syncthreads();
#pragma unroll
    for (int i = 0; i < 4; i++) {
        int k = k0 + threadIdx.y + i * 8;
        ob[(size_t)k * SS + q0 + threadIdx.x] =
            __float2bfloat16_rn(t[threadIdx.x][threadIdx.y + i * 8]);
    }
}

// ---------------------------------------------------------------------------
// Fused projection (Q/K/V via blockIdx.z): C = A*W^T + bias.
// z==0 (Q): 1-pass (Qp truncated downstream anyway); write hi only.
// z==1 (K): 2-pass; write hi+lo.
// z==2 (V): 2-pass; write WVT[b][n][s] hi only via smem transpose.
// ---------------------------------------------------------------------------
struct ProjArgs {
    const __half *Ahi[3], *Alo[3], *Whi[3];
    const float* bias[3];
    __half *Chi[3], *Clo[3];
};
__global__ __launch_bounds__(256, 2)
void proj_kernel(ProjArgs P)
{
    extern __shared__ char smem[];
    uint32_t sb = smem_u32(smem);
    const int tid = threadIdx.x, lane = tid & 31, wid = tid >> 5;
    const int warp_m = wid & 1, warp_n = wid >> 1;
    const int m0 = blockIdx.y * BM, n0 = blockIdx.x * BN;
    const int z = blockIdx.z;
    const int npass = (z == 0) ? 1 : 2;
    const __half* Ahi = P.Ahi[z];
    const __half* Alo = P.Alo[z];
    const __half* Whi = P.Whi[z];
    const float* bias = P.bias[z];
    __half* Chi = P.Chi[z];
    __half* Clo = P.Clo[z];

    float acc[4][4][4];
#pragma unroll
    for (int i = 0; i < 4; i++)
#pragma unroll
        for (int j = 0; j < 4; j++)
#pragma unroll
            for (int r = 0; r < 4; r++) acc[i][j][r] = 0.f;

    FragOff F;
    frag_offsets(lane, warp_m, warp_n, F);

    gemm_core(sb, Ahi + (size_t)m0 * DD, Alo + (size_t)m0 * DD, DD,
              Whi + (size_t)n0 * DD, DD, DD, tid, F, acc, npass);

    if (z != 2) {
#pragma unroll
        for (int wn = 0; wn < 4; wn++) {
            int n = n0 + warp_n * 32 + wn * 8 + (lane & 3) * 2;
            float b0 = bias[n], b1 = bias[n + 1];
#pragma unroll
            for (int wm = 0; wm < 4; wm++)
#pragma unroll
                for (int h = 0; h < 2; h++) {
                    int m = m0 + warp_m * 64 + wm * 16 + (lane >> 2) + h * 8;
                    uint32_t hv, lv;
                    split2h(acc[wm][wn][h * 2] + b0, acc[wm][wn][h * 2 + 1] + b1, hv, lv);
                    *reinterpret_cast<uint32_t*>(Chi + (size_t)m * AA + n) = hv;
                    if (z == 1)
                        *reinterpret_cast<uint32_t*>(Clo + (size_t)m * AA + n) = lv;
                }
        }
    } else {
        char* T = smem;   // 272B-stride rows, hi plane only
#pragma unroll
        for (int wn = 0; wn < 4; wn++) {
            int ln = warp_n * 32 + wn * 8 + (lane & 3) * 2;
            float b0 = bias[n0 + ln], b1 = bias[n0 + ln + 1];
#pragma unroll
            for (int wm = 0; wm < 4; wm++)
#pragma unroll
                for (int h = 0; h < 2; h++) {
                    int lm = warp_m * 64 + wm * 16 + (lane >> 2) + h * 8;
                    *reinterpret_cast<__half*>(T + ln * 272 + lm * 2) =
                        __float2half_rn(acc[wm][wn][h * 2] + b0);
                    *reinterpret_cast<__half*>(T + (ln + 1) * 272 + lm * 2) =
                        __float2half_rn(acc[wm][wn][h * 2 + 1] + b1);
                }
        }
        __syncthreads();
        int v = tid >> 1, hs = (tid & 1) * 64;
        size_t b = (size_t)(m0 >> 11);
        int s0 = m0 & (SS - 1);
        __half* dh = Chi + (b * DVV + n0 + v) * SS + s0 + hs;
#pragma unroll
        for (int g = 0; g < 8; g++)
            *reinterpret_cast<uint4*>(dh + g * 8) =
                *reinterpret_cast<uint4*>(T + v * 272 + (hs + g * 8) * 2);
    }
}

// ---------------------------------------------------------------------------
// Scores (pre-transposed): attn[b][k][q] = scale*Kp[k]·Qp[q] + mT[b][k][q]
// ---------------------------------------------------------------------------
__global__ __launch_bounds__(256, 2)
void scores_kernel(const __half* __restrict__ KpHi, const __half* __restrict__ KpLo,
                   const __half* __restrict__ QpHi,
                   const __nv_bfloat16* __restrict__ mT, float* __restrict__ attn)
{
    extern __shared__ char smem[];
    uint32_t sb = smem_u32(smem);
    const int tid = threadIdx.x, lane = tid & 31, wid = tid >> 5;
    const int warp_m = wid & 1, warp_n = wid >> 1;
    const int m0 = blockIdx.y * BM, n0 = blockIdx.x * BN, b = blockIdx.z;

    float acc[4][4][4];
#pragma unroll
    for (int i = 0; i < 4; i++)
#pragma unroll
        for (int j = 0; j < 4; j++)
#pragma unroll
            for (int r = 0; r < 4; r++) acc[i][j][r] = 0.f;

    FragOff F;
    frag_offsets(lane, warp_m, warp_n, F);

    const size_t base = (size_t)b * SS * AA;
    gemm_core(sb, KpHi + base + (size_t)m0 * AA, KpLo + base + (size_t)m0 * AA, AA,
              QpHi + base + (size_t)n0 * AA, AA, AA, tid, F, acc, 2);

    const float scale = 0.04419417382415922f;   // 1/sqrt(512)
    const __nv_bfloat16* mb = mT + (size_t)b * SS * SS;
    float* ab = attn + (size_t)b * SS * SS;
#pragma unroll
    for (int wm = 0; wm < 4; wm++)
#pragma unroll
        for (int h = 0; h < 2; h++) {
            int k = m0 + warp_m * 64 + wm * 16 + (lane >> 2) + h * 8;
#pragma unroll
            for (int wn = 0; wn < 4; wn++) {
                int q = n0 + warp_n * 32 + wn * 8 + (lane & 3) * 2;
                uint32_t mu = *reinterpret_cast<const uint32_t*>(mb + (size_t)k * SS + q);
                float mv0 = __bfloat162float(__ushort_as_bfloat16((unsigned short)(mu & 0xFFFF)));
                float mv1 = __bfloat162float(__ushort_as_bfloat16((unsigned short)(mu >> 16)));
                *reinterpret_cast<float2*>(ab + (size_t)k * SS + q) =
                    make_float2(fmaf(acc[wm][wn][h * 2], scale, mv0),
                                fmaf(acc[wm][wn][h * 2 + 1], scale, mv1));
            }
        }
}

// ---------------------------------------------------------------------------
// Output: out[b][k][v] = sum_q attn[b][k][q] * WVT[b][v][q]
// ---------------------------------------------------------------------------
__global__ __launch_bounds__(256, 2)
void out_kernel(const __half* __restrict__ AtHi, const __half* __restrict__ AtLo,
                const __half* __restrict__ WVTHi, float* __restrict__ out)
{
    extern __shared__ char smem[];
    uint32_t sb = smem_u32(smem);
    const int tid = threadIdx.x, lane = tid & 31, wid = tid >> 5;
    const int warp_m = wid & 1, warp_n = wid >> 1;
    const int m0 = blockIdx.y * BM, n0 = blockIdx.x * BN, b = blockIdx.z;

    float acc[4][4][4];
#pragma unroll
    for (int i = 0; i < 4; i++)
#pragma unroll
        for (int j = 0; j < 4; j++)
#pragma unroll
            for (int r = 0; r < 4; r++) acc[i][j][r] = 0.f;

    FragOff F;
    frag_offsets(lane, warp_m, warp_n, F);

    const size_t abase = (size_t)b * SS * SS;
    const size_t bbase = (size_t)b * DVV * SS;
    gemm_core(sb, AtHi + abase + (size_t)m0 * SS, AtLo + abase + (size_t)m0 * SS, SS,
              WVTHi + bbase + (size_t)n0 * SS, SS, SS, tid, F, acc, 2);

    float* ob = out + (size_t)b * SS * DVV;
#pragma unroll
    for (int wm = 0; wm < 4; wm++)
#pragma unroll
        for (int h = 0; h < 2; h++) {
            int m = m0 + warp_m * 64 + wm * 16 + (lane >> 2) + h * 8;
#pragma unroll
            for (int wn = 0; wn < 4; wn++) {
                int n = n0 + warp_n * 32 + wn * 8 + (lane & 3) * 2;
                *reinterpret_cast<float2*>(ob + (size_t)m * DVV + n) =
                    make_float2(acc[wm][wn][h * 2], acc[wm][wn][h * 2 + 1]);
            }
        }
}

// ---------------------------------------------------------------------------
// In-place row softmax (fp32) + fp16 hi/lo split write for the out GEMM.
// ---------------------------------------------------------------------------
__global__ void softmax_rows(float* __restrict__ p,
                             __half* __restrict__ hi,
                             __half* __restrict__ lo)
{
    __shared__ float red[33];
    size_t rb = (size_t)blockIdx.x * SS;
    float* x = p + rb;
    int tid = threadIdx.x;
    float v[8];
    float mx = -1e30f;
#pragma unroll
    for (int i = 0; i < 8; i++) { v[i] = x[tid + i * 256]; mx = fmaxf(mx, v[i]); }
#pragma unroll
    for (int o = 16; o > 0; o >>= 1) mx = fmaxf(mx, __shfl_xor_sync(0xffffffffu, mx, o));
    if ((tid & 31) == 0) red[tid >> 5] = mx;
    __syncthreads();
    if (tid < 32) {
        float m = (tid < 8) ? red[tid] : -1e30f;
#pragma unroll
        for (int o = 4; o > 0; o >>= 1) m = fmaxf(m, __shfl_xor_sync(0xffffffffu, m, o));
        if (tid == 0) red[32] = m;
    }
    __syncthreads();
    mx = red[32];
    float s = 0.f;
#pragma unroll
    for (int i = 0; i < 8; i++) { v[i] = __expf(v[i] - mx); s += v[i]; }
#pragma unroll
    for (int o = 16; o > 0; o >>= 1) s += __shfl_xor_sync(0xffffffffu, s, o);
    if ((tid & 31) == 0) red[tid >> 5] = s;
    __syncthreads();
    if (tid < 32) {
        float m = (tid < 8) ? red[tid] : 0.f;
#pragma unroll
        for (int o = 4; o > 0; o >>= 1) m += __shfl_xor_sync(0xffffffffu, m, o);
        if (tid == 0) red[32] = m;
    }
    __syncthreads();
    float inv = 1.0f / red[32];
#pragma unroll
    for (int i = 0; i < 8; i++) {
        int idx = tid + i * 256;
        float val = v[i] * inv;
        x[idx] = val;
        __half h = __float2half_rn(val);
        hi[rb + idx] = h;
        lo[rb + idx] = __float2half_rn(val - __half2float(h));
    }
}

// ---------------------------------------------------------------------------
extern "C" void kernel_launch(void* const* d_in, const int* in_sizes, int n_in,
                              void* d_out, int out_size)
{
    const float* Q    = (const float*)d_in[0];
    const float* K    = (const float*)d_in[1];
    const float* V    = (const float*)d_in[2];
    const int*   mask = (const int*)  d_in[3];
    const float* Wq   = (const float*)d_in[4];
    const float* bq   = (const float*)d_in[5];
    const float* Wk   = (const float*)d_in[6];
    const float* bk   = (const float*)d_in[7];
    const float* Wv   = (const float*)d_in[8];
    const float* bv   = (const float*)d_in[9];

    float* out  = (float*)d_out;                   // selfOutput [B,S,Dv]
    float* attn = out + (size_t)NB * SS * DVV;     // attn       [B,S,S]

    static __half *pQbHi, *pKbHi, *pKbLo, *pVbHi, *pVbLo;
    static __half *pWqHi, *pWkHi, *pWvHi;
    static __half *pQpHi, *pKpHi, *pKpLo, *pWVTHi, *pAtHi, *pAtLo;
    static __nv_bfloat16 *pMkT;
    static bool inited = false;
    if (!inited) {
        cudaGetSymbolAddress((void**)&pQbHi, g_QbHi);
        cudaGetSymbolAddress((void**)&pKbHi, g_KbHi);   cudaGetSymbolAddress((void**)&pKbLo, g_KbLo);
        cudaGetSymbolAddress((void**)&pVbHi, g_VbHi);   cudaGetSymbolAddress((void**)&pVbLo, g_VbLo);
        cudaGetSymbolAddress((void**)&pWqHi, g_WqHi);
        cudaGetSymbolAddress((void**)&pWkHi, g_WkHi);
        cudaGetSymbolAddress((void**)&pWvHi, g_WvHi);
        cudaGetSymbolAddress((void**)&pQpHi, g_QpHi);
        cudaGetSymbolAddress((void**)&pKpHi, g_KpHi);   cudaGetSymbolAddress((void**)&pKpLo, g_KpLo);
        cudaGetSymbolAddress((void**)&pWVTHi, g_WVTHi);
        cudaGetSymbolAddress((void**)&pAtHi, g_AtHi);   cudaGetSymbolAddress((void**)&pAtLo, g_AtLo);
        cudaGetSymbolAddress((void**)&pMkT, g_MkT);
        cudaFuncSetAttribute(proj_kernel,   cudaFuncAttributeMaxDynamicSharedMemorySize, SMEM_PIPE);
        cudaFuncSetAttribute(scores_kernel, cudaFuncAttributeMaxDynamicSharedMemorySize, SMEM_PIPE);
        cudaFuncSetAttribute(out_kernel,    cudaFuncAttributeMaxDynamicSharedMemorySize, SMEM_PIPE);
        inited = true;
    }

    // 1) Pre-split fp32 inputs to fp16 (Q: hi only — its projection is 1-pass)
    {
        SplitArgs sa;
        sa.in[0] = Q; sa.in[1] = K; sa.in[2] = V;
        sa.hi[0] = pQbHi; sa.hi[1] = pKbHi; sa.hi[2] = pVbHi;
        sa.lo[0] = nullptr; sa.lo[1] = pKbLo; sa.lo[2] = pVbLo;
        int n4 = (NB * SS * DD) / 4;
        split3_kernel<<<dim3((n4 + 255) / 256, 1, 3), 256>>>(sa, n4);

        ConvArgs cw;
        cw.in[0] = Wq; cw.in[1] = Wk; cw.in[2] = Wv;
        cw.hi[0] = pWqHi; cw.hi[1] = pWkHi; cw.hi[2] = pWvHi;
        int w4 = (AA * DD) / 4;
        conv3_kernel<<<dim3((w4 + 255) / 256, 1, 3), 256>>>(cw, w4);
    }
    // 2) Mask transpose + prescale
    maskT_kernel<<<dim3(SS / 32, SS / 32, NB), dim3(32, 8)>>>(mask, pMkT);

    // 3) Fused projections (Q, K, V in one launch; z selects; Q is 1-pass)
    {
        ProjArgs P;
        P.Ahi[0] = pQbHi; P.Alo[0] = pQbHi; P.Whi[0] = pWqHi;   // Alo unused for z=0
        P.bias[0] = bq;   P.Chi[0] = pQpHi; P.Clo[0] = nullptr;
        P.Ahi[1] = pKbHi; P.Alo[1] = pKbLo; P.Whi[1] = pWkHi;
        P.bias[1] = bk;   P.Chi[1] = pKpHi; P.Clo[1] = pKpLo;
        P.Ahi[2] = pVbHi; P.Alo[2] = pVbLo; P.Whi[2] = pWvHi;
        P.bias[2] = bv;   P.Chi[2] = pWVTHi; P.Clo[2] = nullptr;
        proj_kernel<<<dim3(4, 128, 3), 256, SMEM_PIPE>>>(P);
    }

    // 4) Masked, pre-transposed scores -> attn (fp32, in d_out)
    scores_kernel<<<dim3(16, 16, NB), 256, SMEM_PIPE>>>(pKpHi, pKpLo, pQpHi, pMkT, attn);
    // 5) Row softmax in place + fp16 hi/lo side-write
    softmax_rows<<<NB * SS, 256>>>(attn, pAtHi, pAtLo);
    // 6) selfOutput = attn @ WV  (K = 2048)
    out_kernel<<<dim3(4, 16, NB), 256, SMEM_PIPE>>>(pAtHi, pAtLo, pWVTHi, out);
}

// round 12
// speedup vs baseline: 2.0946x; 1.2132x over previous
#include <cuda_runtime.h>
#include <cuda_bf16.h>
#include <cuda_fp16.h>
#include <cstdint>

#define NB 8
#define SS 2048
#define DD 1024
#define AA 512
#define DVV 512

// GEMM tiling: 128x128 CTA tile, BK=32, 4-stage cp.async pipeline, swizzled smem
// Planes per stage: A-hi, A-lo (2-pass only), B-hi
#define BM 128
#define BN 128
#define BKC 32
#define ROW64 64                      // bytes per smem row (32 fp16; XOR swizzle)
#define PLANE (128 * ROW64)           // 8192 B per operand plane
#define STAGE (3 * PLANE)             // 24576 B per stage
#define NSTAGE 4
#define SMEM_PIPE (NSTAGE * STAGE)    // 98304 B

// ---------------------------------------------------------------------------
// Scratch (__device__ globals; allocation-free rule)
// ---------------------------------------------------------------------------
__device__ __half g_QbHi[(size_t)NB * SS * DD];
__device__ __half g_KbHi[(size_t)NB * SS * DD];
__device__ __half g_KbLo[(size_t)NB * SS * DD];
__device__ __half g_VbHi[(size_t)NB * SS * DD];
__device__ __half g_VbLo[(size_t)NB * SS * DD];
__device__ __half g_WqHi[(size_t)AA * DD];
__device__ __half g_WkHi[(size_t)AA * DD];
__device__ __half g_WvHi[(size_t)DVV * DD];
__device__ __half g_QpHi[(size_t)NB * SS * AA];    // Qp (B of scores), fp16
__device__ __half g_KpHi[(size_t)NB * SS * AA];    // Kp (A of scores), fp16 1-pass
__device__ __half g_WVTHi[(size_t)NB * DVV * SS];  // [b][v][s] (B of out), fp16
__device__ __half g_AtHi[(size_t)NB * SS * SS];    // attn (A of out), fp16 1-pass
__device__ __nv_bfloat16 g_MkT[(size_t)NB * SS * SS];  // -1e9*mask, [b][k][q]

// ---------------------------------------------------------------------------
// Helpers
// ---------------------------------------------------------------------------
__device__ __forceinline__ uint32_t smem_u32(const void* p) {
    uint32_t a;
    asm("{ .reg .u64 t; cvta.to.shared.u64 t, %1; cvt.u32.u64 %0, t; }" : "=r"(a) : "l"(p));
    return a;
}
__device__ __forceinline__ void cp16(uint32_t dst, const void* src) {
    asm volatile("cp.async.cg.shared.global [%0], [%1], 16;" :: "r"(dst), "l"(src));
}
#define CP_COMMIT() asm volatile("cp.async.commit_group;" ::: "memory")
#define CP_WAIT2()  asm volatile("cp.async.wait_group 2;" ::: "memory")
#define CP_WAIT1()  asm volatile("cp.async.wait_group 1;" ::: "memory")
#define CP_WAIT0()  asm volatile("cp.async.wait_group 0;" ::: "memory")

__device__ __forceinline__ void ldsm4(uint32_t (&r)[4], uint32_t addr) {
    asm volatile("ldmatrix.sync.aligned.m8n8.x4.shared.b16 {%0,%1,%2,%3}, [%4];"
        : "=r"(r[0]), "=r"(r[1]), "=r"(r[2]), "=r"(r[3]) : "r"(addr));
}
__device__ __forceinline__ void mma_f16(float* d, const uint32_t* a, uint32_t b0, uint32_t b1) {
    asm volatile("mma.sync.aligned.m16n8k16.row.col.f32.f16.f16.f32 "
        "{%0,%1,%2,%3}, {%4,%5,%6,%7}, {%8,%9}, {%0,%1,%2,%3};"
        : "+f"(d[0]), "+f"(d[1]), "+f"(d[2]), "+f"(d[3])
        : "r"(a[0]), "r"(a[1]), "r"(a[2]), "r"(a[3]), "r"(b0), "r"(b1));
}
__device__ __forceinline__ void split2h(float a, float b, uint32_t& hi, uint32_t& lo) {
    __half ah = __float2half_rn(a);
    __half bh = __float2half_rn(b);
    __half al = __float2half_rn(a - __half2float(ah));
    __half bl = __float2half_rn(b - __half2float(bh));
    hi = (uint32_t)__half_as_ushort(ah) | ((uint32_t)__half_as_ushort(bh) << 16);
    lo = (uint32_t)__half_as_ushort(al) | ((uint32_t)__half_as_ushort(bl) << 16);
}

// Per-lane ldmatrix offsets (plane-relative, swizzled). [operand][ks]
struct FragOff { uint32_t a[4][2]; uint32_t b[2][2]; };
__device__ __forceinline__ void frag_offsets(int lane, int warp_m, int warp_n, FragOff& F) {
    int ha = lane >> 4;                      // A k-half (0/1)
#pragma unroll
    for (int wm = 0; wm < 4; wm++) {
        int row = warp_m * 64 + wm * 16 + (lane & 15);
        int x = (row >> 1) & 3;
#pragma unroll
        for (int ks = 0; ks < 2; ks++)
            F.a[wm][ks] = (uint32_t)(row * ROW64 + (((ks * 2 + ha) ^ x) << 4));
    }
    int rb = (lane & 7) + ((lane >> 4) << 3);
    int hb = (lane & 8) ? 1 : 0;             // B k-half
#pragma unroll
    for (int p = 0; p < 2; p++) {
        int row = warp_n * 32 + p * 16 + rb;
        int x = (row >> 1) & 3;
#pragma unroll
        for (int ks = 0; ks < 2; ks++)
            F.b[p][ks] = (uint32_t)(row * ROW64 + (((ks * 2 + hb) ^ x) << 4));
    }
}

// Issue cp.async for one BK=32 chunk (Ahi + Bhi always; Alo only if npass==2)
__device__ __forceinline__ void issue_cp(uint32_t sbase,
    const __half* __restrict__ Ahi, const __half* __restrict__ Alo, int lda,
    const __half* __restrict__ Bhi, int ldb,
    int k0, int tid, int npass)
{
    const int lrow = tid >> 1;
    const int c0 = (tid & 1) * 2;
    const int x = (lrow >> 1) & 3;
    const int koff = k0 + (tid & 1) * 16;
    uint32_t d0 = sbase + (uint32_t)(lrow * ROW64 + ((c0 ^ x) << 4));
    uint32_t d1 = sbase + (uint32_t)(lrow * ROW64 + (((c0 + 1) ^ x) << 4));
    const __half* a0 = Ahi + (size_t)lrow * lda + koff;
    const __half* b0 = Bhi + (size_t)lrow * ldb + koff;
    cp16(d0, a0);               cp16(d1, a0 + 8);
    if (npass == 2) {
        const __half* a1 = Alo + (size_t)lrow * lda + koff;
        cp16(d0 + PLANE, a1);   cp16(d1 + PLANE, a1 + 8);
    }
    cp16(d0 + 2 * PLANE, b0);   cp16(d1 + 2 * PLANE, b0 + 8);
}

// One BK=32 chunk of fp16 MMA (R5 interleave; second pass only if npass==2)
__device__ __forceinline__ void mma_chunk32(uint32_t sb, const FragOff& F,
                                            float (*acc)[4][4], int npass) {
#pragma unroll
    for (int ks = 0; ks < 2; ks++) {
        uint32_t af[4][4], bh[2][4];
#pragma unroll
        for (int wm = 0; wm < 4; wm++) ldsm4(af[wm], sb + F.a[wm][ks]);
#pragma unroll
        for (int p = 0; p < 2; p++) ldsm4(bh[p], sb + 2 * PLANE + F.b[p][ks]);
#pragma unroll
        for (int wm = 0; wm < 4; wm++)
#pragma unroll
            for (int wn = 0; wn < 4; wn++)
                mma_f16(acc[wm][wn], af[wm], bh[wn >> 1][(wn & 1) * 2], bh[wn >> 1][(wn & 1) * 2 + 1]);
        if (npass == 2) {
#pragma unroll
            for (int wm = 0; wm < 4; wm++) ldsm4(af[wm], sb + PLANE + F.a[wm][ks]);
#pragma unroll
            for (int wm = 0; wm < 4; wm++)
#pragma unroll
                for (int wn = 0; wn < 4; wn++)
                    mma_f16(acc[wm][wn], af[wm], bh[wn >> 1][(wn & 1) * 2], bh[wn >> 1][(wn & 1) * 2 + 1]);
        }
    }
}

// 4-stage pipelined fp16 GEMM core, 3-chunk lookahead (acc += A * B^T over K)
__device__ __forceinline__ void gemm_core(uint32_t sb,
    const __half* Ahi, const __half* Alo, int lda,
    const __half* Bhi, int ldb,
    int K, int tid, const FragOff& F, float (*acc)[4][4], int npass)
{
    const int nch = K / BKC;
    issue_cp(sb, Ahi, Alo, lda, Bhi, ldb, 0, tid, npass);
    CP_COMMIT();
    issue_cp(sb + STAGE, Ahi, Alo, lda, Bhi, ldb, BKC, tid, npass);
    CP_COMMIT();
    issue_cp(sb + 2 * STAGE, Ahi, Alo, lda, Bhi, ldb, 2 * BKC, tid, npass);
    CP_COMMIT();
    uint32_t cur = 0, nxt3 = 3 * STAGE;
    for (int ch = 0; ch < nch; ch++) {
        int rem = nch - 1 - ch;
        if (rem >= 2) { CP_WAIT2(); } else if (rem == 1) { CP_WAIT1(); } else { CP_WAIT0(); }
        __syncthreads();
        if (ch + 3 < nch) {
            issue_cp(sb + nxt3, Ahi, Alo, lda, Bhi, ldb, (ch + 3) * BKC, tid, npass);
            CP_COMMIT();
        }
        mma_chunk32(sb + cur, F, acc, npass);
        cur = (cur == (NSTAGE - 1) * STAGE) ? 0 : cur + STAGE;
        nxt3 = (nxt3 == (NSTAGE - 1) * STAGE) ? 0 : nxt3 + STAGE;
    }
    __syncthreads();
}

// ---------------------------------------------------------------------------
// Fused elementwise fp32 -> fp16 hi/lo split (3 tensors via blockIdx.z)
// ---------------------------------------------------------------------------
struct SplitArgs {
    const float* in[3];
    __half* hi[3];
    __half* lo[3];
};
__global__ void split3_kernel(SplitArgs a, int n4)
{
    int z = blockIdx.z;
    int i = blockIdx.x * blockDim.x + threadIdx.x;
    if (i < n4) {
        float4 v = reinterpret_cast<const float4*>(a.in[z])[i];
        uint32_t h0, l0, h1, l1;
        split2h(v.x, v.y, h0, l0);
        split2h(v.z, v.w, h1, l1);
        reinterpret_cast<uint2*>(a.hi[z])[i] = make_uint2(h0, h1);
        if (a.lo[z])
            reinterpret_cast<uint2*>(a.lo[z])[i] = make_uint2(l0, l1);
    }
}

struct ConvArgs {
    const float* in[3];
    __half* hi[3];
};
__global__ void conv3_kernel(ConvArgs a, int n4)
{
    int z = blockIdx.z;
    int i = blockIdx.x * blockDim.x + threadIdx.x;
    if (i < n4) {
        float4 v = reinterpret_cast<const float4*>(a.in[z])[i];
        __half2 h01 = __floats2half2_rn(v.x, v.y);
        __half2 h23 = __floats2half2_rn(v.z, v.w);
        reinterpret_cast<uint2*>(a.hi[z])[i] =
            make_uint2(*reinterpret_cast<uint32_t*>(&h01), *reinterpret_cast<uint32_t*>(&h23));
    }
}

// ---------------------------------------------------------------------------
// Mask transpose + prescale: mT[b][k][q] = bf16(-1e9 * mask[b][q][k])
// ---------------------------------------------------------------------------
__global__ __launch_bounds__(256)
void maskT_kernel(const int* __restrict__ mask, __nv_bfloat16* __restrict__ mT)
{
    __shared__ float t[32][33];
    const int b = blockIdx.z;
    const int q0 = blockIdx.y * 32, k0 = blockIdx.x * 32;
    const int* mb = mask + (size_t)b * SS * SS;
    __nv_bfloat16* ob = mT + (size_t)b * SS * SS;
#pragma unroll
    for (int i = 0; i < 4; i++) {
        int q = q0 + threadIdx.y + i * 8;
        t[threadIdx.y + i * 8][threadIdx.x] =
            -1e9f * (float)mb[(size_t)q * SS + k0 + threadIdx.x];
    }
    __syncthreads();
#pragma unroll
    for (int i = 0; i < 4; i++) {
        int k = k0 + threadIdx.y + i * 8;
        ob[(size_t)k * SS + q0 + threadIdx.x] =
            __float2bfloat16_rn(t[threadIdx.x][threadIdx.y + i * 8]);
    }
}

// ---------------------------------------------------------------------------
// Fused projection (Q/K/V via blockIdx.z): C = A*W^T + bias -> fp16 (hi only).
// z==0 (Q): 1-pass.  z==1 (K): 2-pass.  z==2 (V): 2-pass, transposed epilogue.
// ---------------------------------------------------------------------------
struct ProjArgs {
    const __half *Ahi[3], *Alo[3], *Whi[3];
    const float* bias[3];
    __half *Chi[3];
};
__global__ __launch_bounds__(256, 2)
void proj_kernel(ProjArgs P)
{
    extern __shared__ char smem[];
    uint32_t sb = smem_u32(smem);
    const int tid = threadIdx.x, lane = tid & 31, wid = tid >> 5;
    const int warp_m = wid & 1, warp_n = wid >> 1;
    const int m0 = blockIdx.y * BM, n0 = blockIdx.x * BN;
    const int z = blockIdx.z;
    const int npass = (z == 0) ? 1 : 2;
    const __half* Ahi = P.Ahi[z];
    const __half* Alo = P.Alo[z];
    const __half* Whi = P.Whi[z];
    const float* bias = P.bias[z];
    __half* Chi = P.Chi[z];

    float acc[4][4][4];
#pragma unroll
    for (int i = 0; i < 4; i++)
#pragma unroll
        for (int j = 0; j < 4; j++)
#pragma unroll
            for (int r = 0; r < 4; r++) acc[i][j][r] = 0.f;

    FragOff F;
    frag_offsets(lane, warp_m, warp_n, F);

    gemm_core(sb, Ahi + (size_t)m0 * DD, Alo + (size_t)m0 * DD, DD,
              Whi + (size_t)n0 * DD, DD, DD, tid, F, acc, npass);

    if (z != 2) {
#pragma unroll
        for (int wn = 0; wn < 4; wn++) {
            int n = n0 + warp_n * 32 + wn * 8 + (lane & 3) * 2;
            float b0 = bias[n], b1 = bias[n + 1];
#pragma unroll
            for (int wm = 0; wm < 4; wm++)
#pragma unroll
                for (int h = 0; h < 2; h++) {
                    int m = m0 + warp_m * 64 + wm * 16 + (lane >> 2) + h * 8;
                    __half2 hv = __floats2half2_rn(acc[wm][wn][h * 2] + b0,
                                                   acc[wm][wn][h * 2 + 1] + b1);
                    *reinterpret_cast<__half2*>(Chi + (size_t)m * AA + n) = hv;
                }
        }
    } else {
        char* T = smem;   // 272B-stride rows, hi plane only
#pragma unroll
        for (int wn = 0; wn < 4; wn++) {
            int ln = warp_n * 32 + wn * 8 + (lane & 3) * 2;
            float b0 = bias[n0 + ln], b1 = bias[n0 + ln + 1];
#pragma unroll
            for (int wm = 0; wm < 4; wm++)
#pragma unroll
                for (int h = 0; h < 2; h++) {
                    int lm = warp_m * 64 + wm * 16 + (lane >> 2) + h * 8;
                    *reinterpret_cast<__half*>(T + ln * 272 + lm * 2) =
                        __float2half_rn(acc[wm][wn][h * 2] + b0);
                    *reinterpret_cast<__half*>(T + (ln + 1) * 272 + lm * 2) =
                        __float2half_rn(acc[wm][wn][h * 2 + 1] + b1);
                }
        }
        __syncthreads();
        int v = tid >> 1, hs = (tid & 1) * 64;
        size_t b = (size_t)(m0 >> 11);
        int s0 = m0 & (SS - 1);
        __half* dh = Chi + (b * DVV + n0 + v) * SS + s0 + hs;
#pragma unroll
        for (int g = 0; g < 8; g++)
            *reinterpret_cast<uint4*>(dh + g * 8) =
                *reinterpret_cast<uint4*>(T + v * 272 + (hs + g * 8) * 2);
    }
}

// ---------------------------------------------------------------------------
// Scores (pre-transposed): attn[b][k][q] = scale*Kp[k]·Qp[q] + mT[b][k][q]
// 1-pass fp16 (both operands truncated).
// ---------------------------------------------------------------------------
__global__ __launch_bounds__(256, 2)
void scores_kernel(const __half* __restrict__ KpHi, const __half* __restrict__ QpHi,
                   const __nv_bfloat16* __restrict__ mT, float* __restrict__ attn)
{
    extern __shared__ char smem[];
    uint32_t sb = smem_u32(smem);
    const int tid = threadIdx.x, lane = tid & 31, wid = tid >> 5;
    const int warp_m = wid & 1, warp_n = wid >> 1;
    const int m0 = blockIdx.y * BM, n0 = blockIdx.x * BN, b = blockIdx.z;

    float acc[4][4][4];
#pragma unroll
    for (int i = 0; i < 4; i++)
#pragma unroll
        for (int j = 0; j < 4; j++)
#pragma unroll
            for (int r = 0; r < 4; r++) acc[i][j][r] = 0.f;

    FragOff F;
    frag_offsets(lane, warp_m, warp_n, F);

    const size_t base = (size_t)b * SS * AA;
    gemm_core(sb, KpHi + base + (size_t)m0 * AA, KpHi + base + (size_t)m0 * AA, AA,
              QpHi + base + (size_t)n0 * AA, AA, AA, tid, F, acc, 1);

    const float scale = 0.04419417382415922f;   // 1/sqrt(512)
    const __nv_bfloat16* mb = mT + (size_t)b * SS * SS;
    float* ab = attn + (size_t)b * SS * SS;
#pragma unroll
    for (int wm = 0; wm < 4; wm++)
#pragma unroll
        for (int h = 0; h < 2; h++) {
            int k = m0 + warp_m * 64 + wm * 16 + (lane >> 2) + h * 8;
#pragma unroll
            for (int wn = 0; wn < 4; wn++) {
                int q = n0 + warp_n * 32 + wn * 8 + (lane & 3) * 2;
                uint32_t mu = *reinterpret_cast<const uint32_t*>(mb + (size_t)k * SS + q);
                float mv0 = __bfloat162float(__ushort_as_bfloat16((unsigned short)(mu & 0xFFFF)));
                float mv1 = __bfloat162float(__ushort_as_bfloat16((unsigned short)(mu >> 16)));
                *reinterpret_cast<float2*>(ab + (size_t)k * SS + q) =
                    make_float2(fmaf(acc[wm][wn][h * 2], scale, mv0),
                                fmaf(acc[wm][wn][h * 2 + 1], scale, mv1));
            }
        }
}

// ---------------------------------------------------------------------------
// Output: out[b][k][v] = sum_q attn[b][k][q] * WVT[b][v][q]   (1-pass fp16)
// ---------------------------------------------------------------------------
__global__ __launch_bounds__(256, 2)
void out_kernel(const __half* __restrict__ AtHi,
                const __half* __restrict__ WVTHi, float* __restrict__ out)
{
    extern __shared__ char smem[];
    uint32_t sb = smem_u32(smem);
    const int tid = threadIdx.x, lane = tid & 31, wid = tid >> 5;
    const int warp_m = wid & 1, warp_n = wid >> 1;
    const int m0 = blockIdx.y * BM, n0 = blockIdx.x * BN, b = blockIdx.z;

    float acc[4][4][4];
#pragma unroll
    for (int i = 0; i < 4; i++)
#pragma unroll
        for (int j = 0; j < 4; j++)
#pragma unroll
            for (int r = 0; r < 4; r++) acc[i][j][r] = 0.f;

    FragOff F;
    frag_offsets(lane, warp_m, warp_n, F);

    const size_t abase = (size_t)b * SS * SS;
    const size_t bbase = (size_t)b * DVV * SS;
    gemm_core(sb, AtHi + abase + (size_t)m0 * SS, AtHi + abase + (size_t)m0 * SS, SS,
              WVTHi + bbase + (size_t)n0 * SS, SS, SS, tid, F, acc, 1);

    float* ob = out + (size_t)b * SS * DVV;
#pragma unroll
    for (int wm = 0; wm < 4; wm++)
#pragma unroll
        for (int h = 0; h < 2; h++) {
            int m = m0 + warp_m * 64 + wm * 16 + (lane >> 2) + h * 8;
#pragma unroll
            for (int wn = 0; wn < 4; wn++) {
                int n = n0 + warp_n * 32 + wn * 8 + (lane & 3) * 2;
                *reinterpret_cast<float2*>(ob + (size_t)m * DVV + n) =
                    make_float2(acc[wm][wn][h * 2], acc[wm][wn][h * 2 + 1]);
            }
        }
}

// ---------------------------------------------------------------------------
// In-place row softmax (fp32) + fp16 truncated write for the out GEMM.
// ---------------------------------------------------------------------------
__global__ void softmax_rows(float* __restrict__ p, __half* __restrict__ hi)
{
    __shared__ float red[33];
    size_t rb = (size_t)blockIdx.x * SS;
    float* x = p + rb;
    int tid = threadIdx.x;
    float v[8];
    float mx = -1e30f;
#pragma unroll
    for (int i = 0; i < 8; i++) { v[i] = x[tid + i * 256]; mx = fmaxf(mx, v[i]); }
#pragma unroll
    for (int o = 16; o > 0; o >>= 1) mx = fmaxf(mx, __shfl_xor_sync(0xffffffffu, mx, o));
    if ((tid & 31) == 0) red[tid >> 5] = mx;
    __syncthreads();
    if (tid < 32) {
        float m = (tid < 8) ? red[tid] : -1e30f;
#pragma unroll
        for (int o = 4; o > 0; o >>= 1) m = fmaxf(m, __shfl_xor_sync(0xffffffffu, m, o));
        if (tid == 0) red[32] = m;
    }
    __syncthreads();
    mx = red[32];
    float s = 0.f;
#pragma unroll
    for (int i = 0; i < 8; i++) { v[i] = __expf(v[i] - mx); s += v[i]; }
#pragma unroll
    for (int o = 16; o > 0; o >>= 1) s += __shfl_xor_sync(0xffffffffu, s, o);
    if ((tid & 31) == 0) red[tid >> 5] = s;
    __syncthreads();
    if (tid < 32) {
        float m = (tid < 8) ? red[tid] : 0.f;
#pragma unroll
        for (int o = 4; o > 0; o >>= 1) m += __shfl_xor_sync(0xffffffffu, m, o);
        if (tid == 0) red[32] = m;
    }
    __syncthreads();
    float inv = 1.0f / red[32];
#pragma unroll
    for (int i = 0; i < 8; i++) {
        int idx = tid + i * 256;
        float val = v[i] * inv;
        x[idx] = val;
        hi[rb + idx] = __float2half_rn(val);
    }
}

// ---------------------------------------------------------------------------
extern "C" void kernel_launch(void* const* d_in, const int* in_sizes, int n_in,
                              void* d_out, int out_size)
{
    const float* Q    = (const float*)d_in[0];
    const float* K    = (const float*)d_in[1];
    const float* V    = (const float*)d_in[2];
    const int*   mask = (const int*)  d_in[3];
    const float* Wq   = (const float*)d_in[4];
    const float* bq   = (const float*)d_in[5];
    const float* Wk   = (const float*)d_in[6];
    const float* bk   = (const float*)d_in[7];
    const float* Wv   = (const float*)d_in[8];
    const float* bv   = (const float*)d_in[9];

    float* out  = (float*)d_out;                   // selfOutput [B,S,Dv]
    float* attn = out + (size_t)NB * SS * DVV;     // attn       [B,S,S]

    static __half *pQbHi, *pKbHi, *pKbLo, *pVbHi, *pVbLo;
    static __half *pWqHi, *pWkHi, *pWvHi;
    static __half *pQpHi, *pKpHi, *pWVTHi, *pAtHi;
    static __nv_bfloat16 *pMkT;
    static bool inited = false;
    if (!inited) {
        cudaGetSymbolAddress((void**)&pQbHi, g_QbHi);
        cudaGetSymbolAddress((void**)&pKbHi, g_KbHi);   cudaGetSymbolAddress((void**)&pKbLo, g_KbLo);
        cudaGetSymbolAddress((void**)&pVbHi, g_VbHi);   cudaGetSymbolAddress((void**)&pVbLo, g_VbLo);
        cudaGetSymbolAddress((void**)&pWqHi, g_WqHi);
        cudaGetSymbolAddress((void**)&pWkHi, g_WkHi);
        cudaGetSymbolAddress((void**)&pWvHi, g_WvHi);
        cudaGetSymbolAddress((void**)&pQpHi, g_QpHi);
        cudaGetSymbolAddress((void**)&pKpHi, g_KpHi);
        cudaGetSymbolAddress((void**)&pWVTHi, g_WVTHi);
        cudaGetSymbolAddress((void**)&pAtHi, g_AtHi);
        cudaGetSymbolAddress((void**)&pMkT, g_MkT);
        cudaFuncSetAttribute(proj_kernel,   cudaFuncAttributeMaxDynamicSharedMemorySize, SMEM_PIPE);
        cudaFuncSetAttribute(scores_kernel, cudaFuncAttributeMaxDynamicSharedMemorySize, SMEM_PIPE);
        cudaFuncSetAttribute(out_kernel,    cudaFuncAttributeMaxDynamicSharedMemorySize, SMEM_PIPE);
        inited = true;
    }

    // 1) Pre-convert inputs to fp16 (Q: hi only; K/V: hi+lo for 2-pass proj)
    {
        SplitArgs sa;
        sa.in[0] = Q; sa.in[1] = K; sa.in[2] = V;
        sa.hi[0] = pQbHi; sa.hi[1] = pKbHi; sa.hi[2] = pVbHi;
        sa.lo[0] = nullptr; sa.lo[1] = pKbLo; sa.lo[2] = pVbLo;
        int n4 = (NB * SS * DD) / 4;
        split3_kernel<<<dim3((n4 + 255) / 256, 1, 3), 256>>>(sa, n4);

        ConvArgs cw;
        cw.in[0] = Wq; cw.in[1] = Wk; cw.in[2] = Wv;
        cw.hi[0] = pWqHi; cw.hi[1] = pWkHi; cw.hi[2] = pWvHi;
        int w4 = (AA * DD) / 4;
        conv3_kernel<<<dim3((w4 + 255) / 256, 1, 3), 256>>>(cw, w4);
    }
    // 2) Mask transpose + prescale
    maskT_kernel<<<dim3(SS / 32, SS / 32, NB), dim3(32, 8)>>>(mask, pMkT);

    // 3) Fused projections (Q 1-pass, K/V 2-pass)
    {
        ProjArgs P;
        P.Ahi[0] = pQbHi; P.Alo[0] = pQbHi; P.Whi[0] = pWqHi;
        P.bias[0] = bq;   P.Chi[0] = pQpHi;
        P.Ahi[1] = pKbHi; P.Alo[1] = pKbLo; P.Whi[1] = pWkHi;
        P.bias[1] = bk;   P.Chi[1] = pKpHi;
        P.Ahi[2] = pVbHi; P.Alo[2] = pVbLo; P.Whi[2] = pWvHi;
        P.bias[2] = bv;   P.Chi[2] = pWVTHi;
        proj_kernel<<<dim3(4, 128, 3), 256, SMEM_PIPE>>>(P);
    }

    // 4) Masked, pre-transposed scores -> attn (fp32, in d_out); 1-pass
    scores_kernel<<<dim3(16, 16, NB), 256, SMEM_PIPE>>>(pKpHi, pQpHi, pMkT, attn);
    // 5) Row softmax in place + fp16 side-write
    softmax_rows<<<NB * SS, 256>>>(attn, pAtHi);
    // 6) selfOutput = attn @ WV  (K = 2048); 1-pass
    out_kernel<<<dim3(4, 16, NB), 256, SMEM_PIPE>>>(pAtHi, pWVTHi, out);
}

// round 13
// speedup vs baseline: 2.5044x; 1.1957x over previous
#include <cuda_runtime.h>
#include <cuda_bf16.h>
#include <cuda_fp16.h>
#include <cstdint>

#define NB 8
#define SS 2048
#define DD 1024
#define AA 512
#define DVV 512

// GEMM tiling: 128x128 CTA tile, BK=32, 4-stage cp.async pipeline, swizzled smem
// Plain fp16 1-pass: planes per stage = A, B
#define BM 128
#define BN 128
#define BKC 32
#define ROW64 64                      // bytes per smem row (32 fp16; XOR swizzle)
#define PLANE (128 * ROW64)           // 8192 B per operand plane
#define STAGE (2 * PLANE)             // 16384 B per stage
#define NSTAGE 4
#define SMEM_PIPE (NSTAGE * STAGE)    // 65536 B

// ---------------------------------------------------------------------------
// Scratch (__device__ globals; allocation-free rule)
// ---------------------------------------------------------------------------
__device__ __half g_Qb[(size_t)NB * SS * DD];
__device__ __half g_Kb[(size_t)NB * SS * DD];
__device__ __half g_Vb[(size_t)NB * SS * DD];
__device__ __half g_Wq[(size_t)AA * DD];
__device__ __half g_Wk[(size_t)AA * DD];
__device__ __half g_Wv[(size_t)DVV * DD];
__device__ __half g_Qp[(size_t)NB * SS * AA];     // B of scores
__device__ __half g_Kp[(size_t)NB * SS * AA];     // A of scores
__device__ __half g_WVT[(size_t)NB * DVV * SS];   // [b][v][s], B of out
__device__ __half g_At[(size_t)NB * SS * SS];     // A of out
__device__ __nv_bfloat16 g_MkT[(size_t)NB * SS * SS];  // -1e9*mask, [b][k][q]

// ---------------------------------------------------------------------------
// Helpers
// ---------------------------------------------------------------------------
__device__ __forceinline__ uint32_t smem_u32(const void* p) {
    uint32_t a;
    asm("{ .reg .u64 t; cvta.to.shared.u64 t, %1; cvt.u32.u64 %0, t; }" : "=r"(a) : "l"(p));
    return a;
}
__device__ __forceinline__ void cp16(uint32_t dst, const void* src) {
    asm volatile("cp.async.cg.shared.global [%0], [%1], 16;" :: "r"(dst), "l"(src));
}
#define CP_COMMIT() asm volatile("cp.async.commit_group;" ::: "memory")
#define CP_WAIT2()  asm volatile("cp.async.wait_group 2;" ::: "memory")
#define CP_WAIT1()  asm volatile("cp.async.wait_group 1;" ::: "memory")
#define CP_WAIT0()  asm volatile("cp.async.wait_group 0;" ::: "memory")

__device__ __forceinline__ void ldsm4(uint32_t (&r)[4], uint32_t addr) {
    asm volatile("ldmatrix.sync.aligned.m8n8.x4.shared.b16 {%0,%1,%2,%3}, [%4];"
        : "=r"(r[0]), "=r"(r[1]), "=r"(r[2]), "=r"(r[3]) : "r"(addr));
}
__device__ __forceinline__ void mma_f16(float* d, const uint32_t* a, uint32_t b0, uint32_t b1) {
    asm volatile("mma.sync.aligned.m16n8k16.row.col.f32.f16.f16.f32 "
        "{%0,%1,%2,%3}, {%4,%5,%6,%7}, {%8,%9}, {%0,%1,%2,%3};"
        : "+f"(d[0]), "+f"(d[1]), "+f"(d[2]), "+f"(d[3])
        : "r"(a[0]), "r"(a[1]), "r"(a[2]), "r"(a[3]), "r"(b0), "r"(b1));
}

// Per-lane ldmatrix offsets (plane-relative, swizzled). [operand][ks]
struct FragOff { uint32_t a[4][2]; uint32_t b[2][2]; };
__device__ __forceinline__ void frag_offsets(int lane, int warp_m, int warp_n, FragOff& F) {
    int ha = lane >> 4;                      // A k-half (0/1)
#pragma unroll
    for (int wm = 0; wm < 4; wm++) {
        int row = warp_m * 64 + wm * 16 + (lane & 15);
        int x = (row >> 1) & 3;
#pragma unroll
        for (int ks = 0; ks < 2; ks++)
            F.a[wm][ks] = (uint32_t)(row * ROW64 + (((ks * 2 + ha) ^ x) << 4));
    }
    int rb = (lane & 7) + ((lane >> 4) << 3);
    int hb = (lane & 8) ? 1 : 0;             // B k-half
#pragma unroll
    for (int p = 0; p < 2; p++) {
        int row = warp_n * 32 + p * 16 + rb;
        int x = (row >> 1) & 3;
#pragma unroll
        for (int ks = 0; ks < 2; ks++)
            F.b[p][ks] = (uint32_t)(row * ROW64 + (((ks * 2 + hb) ^ x) << 4));
    }
}

// Issue cp.async for one BK=32 chunk (2 planes: A, B)
__device__ __forceinline__ void issue_cp(uint32_t sbase,
    const __half* __restrict__ A, int lda,
    const __half* __restrict__ B, int ldb,
    int k0, int tid)
{
    const int lrow = tid >> 1;
    const int c0 = (tid & 1) * 2;
    const int x = (lrow >> 1) & 3;
    const int koff = k0 + (tid & 1) * 16;
    uint32_t d0 = sbase + (uint32_t)(lrow * ROW64 + ((c0 ^ x) << 4));
    uint32_t d1 = sbase + (uint32_t)(lrow * ROW64 + (((c0 + 1) ^ x) << 4));
    const __half* a0 = A + (size_t)lrow * lda + koff;
    const __half* b0 = B + (size_t)lrow * ldb + koff;
    cp16(d0, a0);           cp16(d1, a0 + 8);
    cp16(d0 + PLANE, b0);   cp16(d1 + PLANE, b0 + 8);
}

// One BK=32 chunk of fp16 1-pass MMA
__device__ __forceinline__ void mma_chunk32(uint32_t sb, const FragOff& F, float (*acc)[4][4]) {
#pragma unroll
    for (int ks = 0; ks < 2; ks++) {
        uint32_t af[4][4], bh[2][4];
#pragma unroll
        for (int wm = 0; wm < 4; wm++) ldsm4(af[wm], sb + F.a[wm][ks]);
#pragma unroll
        for (int p = 0; p < 2; p++) ldsm4(bh[p], sb + PLANE + F.b[p][ks]);
#pragma unroll
        for (int wm = 0; wm < 4; wm++)
#pragma unroll
            for (int wn = 0; wn < 4; wn++)
                mma_f16(acc[wm][wn], af[wm], bh[wn >> 1][(wn & 1) * 2], bh[wn >> 1][(wn & 1) * 2 + 1]);
    }
}

// 4-stage pipelined fp16 GEMM core, 3-chunk lookahead (acc += A * B^T over K)
__device__ __forceinline__ void gemm_core(uint32_t sb,
    const __half* A, int lda, const __half* B, int ldb,
    int K, int tid, const FragOff& F, float (*acc)[4][4])
{
    const int nch = K / BKC;
    issue_cp(sb, A, lda, B, ldb, 0, tid);
    CP_COMMIT();
    issue_cp(sb + STAGE, A, lda, B, ldb, BKC, tid);
    CP_COMMIT();
    issue_cp(sb + 2 * STAGE, A, lda, B, ldb, 2 * BKC, tid);
    CP_COMMIT();
    uint32_t cur = 0, nxt3 = 3 * STAGE;
    for (int ch = 0; ch < nch; ch++) {
        int rem = nch - 1 - ch;
        if (rem >= 2) { CP_WAIT2(); } else if (rem == 1) { CP_WAIT1(); } else { CP_WAIT0(); }
        __syncthreads();
        if (ch + 3 < nch) {
            issue_cp(sb + nxt3, A, lda, B, ldb, (ch + 3) * BKC, tid);
            CP_COMMIT();
        }
        mma_chunk32(sb + cur, F, acc);
        cur = (cur == (NSTAGE - 1) * STAGE) ? 0 : cur + STAGE;
        nxt3 = (nxt3 == (NSTAGE - 1) * STAGE) ? 0 : nxt3 + STAGE;
    }
    __syncthreads();
}

// ---------------------------------------------------------------------------
// Fused elementwise fp32 -> fp16 convert (3 tensors via blockIdx.z)
// ---------------------------------------------------------------------------
struct ConvArgs {
    const float* in[3];
    __half* hi[3];
};
__global__ void conv3_kernel(ConvArgs a, int n4)
{
    int z = blockIdx.z;
    int i = blockIdx.x * blockDim.x + threadIdx.x;
    if (i < n4) {
        float4 v = reinterpret_cast<const float4*>(a.in[z])[i];
        __half2 h01 = __floats2half2_rn(v.x, v.y);
        __half2 h23 = __floats2half2_rn(v.z, v.w);
        reinterpret_cast<uint2*>(a.hi[z])[i] =
            make_uint2(*reinterpret_cast<uint32_t*>(&h01), *reinterpret_cast<uint32_t*>(&h23));
    }
}

// ---------------------------------------------------------------------------
// Mask transpose + prescale: mT[b][k][q] = bf16(-1e9 * mask[b][q][k])
// ---------------------------------------------------------------------------
__global__ __launch_bounds__(256)
void maskT_kernel(const int* __restrict__ mask, __nv_bfloat16* __restrict__ mT)
{
    __shared__ float t[32][33];
    const int b = blockIdx.z;
    const int q0 = blockIdx.y * 32, k0 = blockIdx.x * 32;
    const int* mb = mask + (size_t)b * SS * SS;
    __nv_bfloat16* ob = mT + (size_t)b * SS * SS;
#pragma unroll
    for (int i = 0; i < 4; i++) {
        int q = q0 + threadIdx.y + i * 8;
        t[threadIdx.y + i * 8][threadIdx.x] =
            -1e9f * (float)mb[(size_t)q * SS + k0 + threadIdx.x];
    }
    __syncthreads();
#pragma unroll
    for (int i = 0; i < 4; i++) {
        int k = k0 + threadIdx.y + i * 8;
        ob[(size_t)k * SS + q0 + threadIdx.x] =
            __float2bfloat16_rn(t[threadIdx.x][threadIdx.y + i * 8]);
    }
}

// ---------------------------------------------------------------------------
// Fused projection (Q/K/V via blockIdx.z): C = A*W^T + bias -> fp16.
// z==2 (V): writes WVT[b][n][s] via smem transpose.
// ---------------------------------------------------------------------------
struct ProjArgs {
    const __half *Ain[3], *Win[3];
    const float* bias[3];
    __half *Cout[3];
};
__global__ __launch_bounds__(256, 2)
void proj_kernel(ProjArgs P)
{
    extern __shared__ char smem[];
    uint32_t sb = smem_u32(smem);
    const int tid = threadIdx.x, lane = tid & 31, wid = tid >> 5;
    const int warp_m = wid & 1, warp_n = wid >> 1;
    const int m0 = blockIdx.y * BM, n0 = blockIdx.x * BN;
    const int z = blockIdx.z;
    const __half* A = P.Ain[z];
    const __half* W = P.Win[z];
    const float* bias = P.bias[z];
    __half* C = P.Cout[z];

    float acc[4][4][4];
#pragma unroll
    for (int i = 0; i < 4; i++)
#pragma unroll
        for (int j = 0; j < 4; j++)
#pragma unroll
            for (int r = 0; r < 4; r++) acc[i][j][r] = 0.f;

    FragOff F;
    frag_offsets(lane, warp_m, warp_n, F);

    gemm_core(sb, A + (size_t)m0 * DD, DD, W + (size_t)n0 * DD, DD,
              DD, tid, F, acc);

    if (z != 2) {
#pragma unroll
        for (int wn = 0; wn < 4; wn++) {
            int n = n0 + warp_n * 32 + wn * 8 + (lane & 3) * 2;
            float b0 = bias[n], b1 = bias[n + 1];
#pragma unroll
            for (int wm = 0; wm < 4; wm++)
#pragma unroll
                for (int h = 0; h < 2; h++) {
                    int m = m0 + warp_m * 64 + wm * 16 + (lane >> 2) + h * 8;
                    __half2 hv = __floats2half2_rn(acc[wm][wn][h * 2] + b0,
                                                   acc[wm][wn][h * 2 + 1] + b1);
                    *reinterpret_cast<__half2*>(C + (size_t)m * AA + n) = hv;
                }
        }
    } else {
        char* T = smem;   // 272B-stride rows
#pragma unroll
        for (int wn = 0; wn < 4; wn++) {
            int ln = warp_n * 32 + wn * 8 + (lane & 3) * 2;
            float b0 = bias[n0 + ln], b1 = bias[n0 + ln + 1];
#pragma unroll
            for (int wm = 0; wm < 4; wm++)
#pragma unroll
                for (int h = 0; h < 2; h++) {
                    int lm = warp_m * 64 + wm * 16 + (lane >> 2) + h * 8;
                    *reinterpret_cast<__half*>(T + ln * 272 + lm * 2) =
                        __float2half_rn(acc[wm][wn][h * 2] + b0);
                    *reinterpret_cast<__half*>(T + (ln + 1) * 272 + lm * 2) =
                        __float2half_rn(acc[wm][wn][h * 2 + 1] + b1);
                }
        }
        __syncthreads();
        int v = tid >> 1, hs = (tid & 1) * 64;
        size_t b = (size_t)(m0 >> 11);
        int s0 = m0 & (SS - 1);
        __half* dh = C + (b * DVV + n0 + v) * SS + s0 + hs;
#pragma unroll
        for (int g = 0; g < 8; g++)
            *reinterpret_cast<uint4*>(dh + g * 8) =
                *reinterpret_cast<uint4*>(T + v * 272 + (hs + g * 8) * 2);
    }
}

// ---------------------------------------------------------------------------
// Scores (pre-transposed): attn[b][k][q] = scale*Kp[k]·Qp[q] + mT[b][k][q]
// ---------------------------------------------------------------------------
__global__ __launch_bounds__(256, 2)
void scores_kernel(const __half* __restrict__ Kp, const __half* __restrict__ Qp,
                   const __nv_bfloat16* __restrict__ mT, float* __restrict__ attn)
{
    extern __shared__ char smem[];
    uint32_t sb = smem_u32(smem);
    const int tid = threadIdx.x, lane = tid & 31, wid = tid >> 5;
    const int warp_m = wid & 1, warp_n = wid >> 1;
    const int m0 = blockIdx.y * BM, n0 = blockIdx.x * BN, b = blockIdx.z;

    float acc[4][4][4];
#pragma unroll
    for (int i = 0; i < 4; i++)
#pragma unroll
        for (int j = 0; j < 4; j++)
#pragma unroll
            for (int r = 0; r < 4; r++) acc[i][j][r] = 0.f;

    FragOff F;
    frag_offsets(lane, warp_m, warp_n, F);

    const size_t base = (size_t)b * SS * AA;
    gemm_core(sb, Kp + base + (size_t)m0 * AA, AA,
              Qp + base + (size_t)n0 * AA, AA, AA, tid, F, acc);

    const float scale = 0.04419417382415922f;   // 1/sqrt(512)
    const __nv_bfloat16* mb = mT + (size_t)b * SS * SS;
    float* ab = attn + (size_t)b * SS * SS;
#pragma unroll
    for (int wm = 0; wm < 4; wm++)
#pragma unroll
        for (int h = 0; h < 2; h++) {
            int k = m0 + warp_m * 64 + wm * 16 + (lane >> 2) + h * 8;
#pragma unroll
            for (int wn = 0; wn < 4; wn++) {
                int q = n0 + warp_n * 32 + wn * 8 + (lane & 3) * 2;
                uint32_t mu = *reinterpret_cast<const uint32_t*>(mb + (size_t)k * SS + q);
                float mv0 = __bfloat162float(__ushort_as_bfloat16((unsigned short)(mu & 0xFFFF)));
                float mv1 = __bfloat162float(__ushort_as_bfloat16((unsigned short)(mu >> 16)));
                *reinterpret_cast<float2*>(ab + (size_t)k * SS + q) =
                    make_float2(fmaf(acc[wm][wn][h * 2], scale, mv0),
                                fmaf(acc[wm][wn][h * 2 + 1], scale, mv1));
            }
        }
}

// ---------------------------------------------------------------------------
// Output: out[b][k][v] = sum_q attn[b][k][q] * WVT[b][v][q]
// ---------------------------------------------------------------------------
__global__ __launch_bounds__(256, 2)
void out_kernel(const __half* __restrict__ At,
                const __half* __restrict__ WVT, float* __restrict__ out)
{
    extern __shared__ char smem[];
    uint32_t sb = smem_u32(smem);
    const int tid = threadIdx.x, lane = tid & 31, wid = tid >> 5;
    const int warp_m = wid & 1, warp_n = wid >> 1;
    const int m0 = blockIdx.y * BM, n0 = blockIdx.x * BN, b = blockIdx.z;

    float acc[4][4][4];
#pragma unroll
    for (int i = 0; i < 4; i++)
#pragma unroll
        for (int j = 0; j < 4; j++)
#pragma unroll
            for (int r = 0; r < 4; r++) acc[i][j][r] = 0.f;

    FragOff F;
    frag_offsets(lane, warp_m, warp_n, F);

    const size_t abase = (size_t)b * SS * SS;
    const size_t bbase = (size_t)b * DVV * SS;
    gemm_core(sb, At + abase + (size_t)m0 * SS, SS,
              WVT + bbase + (size_t)n0 * SS, SS, SS, tid, F, acc);

    float* ob = out + (size_t)b * SS * DVV;
#pragma unroll
    for (int wm = 0; wm < 4; wm++)
#pragma unroll
        for (int h = 0; h < 2; h++) {
            int m = m0 + warp_m * 64 + wm * 16 + (lane >> 2) + h * 8;
#pragma unroll
            for (int wn = 0; wn < 4; wn++) {
                int n = n0 + warp_n * 32 + wn * 8 + (lane & 3) * 2;
                *reinterpret_cast<float2*>(ob + (size_t)m * DVV + n) =
                    make_float2(acc[wm][wn][h * 2], acc[wm][wn][h * 2 + 1]);
            }
        }
}

// ---------------------------------------------------------------------------
// In-place row softmax (fp32) + fp16 truncated write for the out GEMM.
// ---------------------------------------------------------------------------
__global__ void softmax_rows(float* __restrict__ p, __half* __restrict__ hi)
{
    __shared__ float red[33];
    size_t rb = (size_t)blockIdx.x * SS;
    float* x = p + rb;
    int tid = threadIdx.x;
    float v[8];
    float mx = -1e30f;
#pragma unroll
    for (int i = 0; i < 8; i++) { v[i] = x[tid + i * 256]; mx = fmaxf(mx, v[i]); }
#pragma unroll
    for (int o = 16; o > 0; o >>= 1) mx = fmaxf(mx, __shfl_xor_sync(0xffffffffu, mx, o));
    if ((tid & 31) == 0) red[tid >> 5] = mx;
    __syncthreads();
    if (tid < 32) {
        float m = (tid < 8) ? red[tid] : -1e30f;
#pragma unroll
        for (int o = 4; o > 0; o >>= 1) m = fmaxf(m, __shfl_xor_sync(0xffffffffu, m, o));
        if (tid == 0) red[32] = m;
    }
    __syncthreads();
    mx = red[32];
    float s = 0.f;
#pragma unroll
    for (int i = 0; i < 8; i++) { v[i] = __expf(v[i] - mx); s += v[i]; }
#pragma unroll
    for (int o = 16; o > 0; o >>= 1) s += __shfl_xor_sync(0xffffffffu, s, o);
    if ((tid & 31) == 0) red[tid >> 5] = s;
    __syncthreads();
    if (tid < 32) {
        float m = (tid < 8) ? red[tid] : 0.f;
#pragma unroll
        for (int o = 4; o > 0; o >>= 1) m += __shfl_xor_sync(0xffffffffu, m, o);
        if (tid == 0) red[32] = m;
    }
    __syncthreads();
    float inv = 1.0f / red[32];
#pragma unroll
    for (int i = 0; i < 8; i++) {
        int idx = tid + i * 256;
        float val = v[i] * inv;
        x[idx] = val;
        hi[rb + idx] = __float2half_rn(val);
    }
}

// ---------------------------------------------------------------------------
extern "C" void kernel_launch(void* const* d_in, const int* in_sizes, int n_in,
                              void* d_out, int out_size)
{
    const float* Q    = (const float*)d_in[0];
    const float* K    = (const float*)d_in[1];
    const float* V    = (const float*)d_in[2];
    const int*   mask = (const int*)  d_in[3];
    const float* Wq   = (const float*)d_in[4];
    const float* bq   = (const float*)d_in[5];
    const float* Wk   = (const float*)d_in[6];
    const float* bk   = (const float*)d_in[7];
    const float* Wv   = (const float*)d_in[8];
    const float* bv   = (const float*)d_in[9];

    float* out  = (float*)d_out;                   // selfOutput [B,S,Dv]
    float* attn = out + (size_t)NB * SS * DVV;     // attn       [B,S,S]

    static __half *pQb, *pKb, *pVb, *pWq, *pWk, *pWv;
    static __half *pQp, *pKp, *pWVT, *pAt;
    static __nv_bfloat16 *pMkT;
    static bool inited = false;
    if (!inited) {
        cudaGetSymbolAddress((void**)&pQb, g_Qb);
        cudaGetSymbolAddress((void**)&pKb, g_Kb);
        cudaGetSymbolAddress((void**)&pVb, g_Vb);
        cudaGetSymbolAddress((void**)&pWq, g_Wq);
        cudaGetSymbolAddress((void**)&pWk, g_Wk);
        cudaGetSymbolAddress((void**)&pWv, g_Wv);
        cudaGetSymbolAddress((void**)&pQp, g_Qp);
        cudaGetSymbolAddress((void**)&pKp, g_Kp);
        cudaGetSymbolAddress((void**)&pWVT, g_WVT);
        cudaGetSymbolAddress((void**)&pAt, g_At);
        cudaGetSymbolAddress((void**)&pMkT, g_MkT);
        cudaFuncSetAttribute(proj_kernel,   cudaFuncAttributeMaxDynamicSharedMemorySize, SMEM_PIPE);
        cudaFuncSetAttribute(scores_kernel, cudaFuncAttributeMaxDynamicSharedMemorySize, SMEM_PIPE);
        cudaFuncSetAttribute(out_kernel,    cudaFuncAttributeMaxDynamicSharedMemorySize, SMEM_PIPE);
        inited = true;
    }

    // 1) Convert inputs + weights to fp16
    {
        ConvArgs ca;
        ca.in[0] = Q; ca.in[1] = K; ca.in[2] = V;
        ca.hi[0] = pQb; ca.hi[1] = pKb; ca.hi[2] = pVb;
        int n4 = (NB * SS * DD) / 4;
        conv3_kernel<<<dim3((n4 + 255) / 256, 1, 3), 256>>>(ca, n4);

        ConvArgs cw;
        cw.in[0] = Wq; cw.in[1] = Wk; cw.in[2] = Wv;
        cw.hi[0] = pWq; cw.hi[1] = pWk; cw.hi[2] = pWv;
        int w4 = (AA * DD) / 4;
        conv3_kernel<<<dim3((w4 + 255) / 256, 1, 3), 256>>>(cw, w4);
    }
    // 2) Mask transpose + prescale
    maskT_kernel<<<dim3(SS / 32, SS / 32, NB), dim3(32, 8)>>>(mask, pMkT);

    // 3) Fused projections (all 1-pass fp16)
    {
        ProjArgs P;
        P.Ain[0] = pQb; P.Win[0] = pWq; P.bias[0] = bq; P.Cout[0] = pQp;
        P.Ain[1] = pKb; P.Win[1] = pWk; P.bias[1] = bk; P.Cout[1] = pKp;
        P.Ain[2] = pVb; P.Win[2] = pWv; P.bias[2] = bv; P.Cout[2] = pWVT;
        proj_kernel<<<dim3(4, 128, 3), 256, SMEM_PIPE>>>(P);
    }

    // 4) Masked, pre-transposed scores -> attn (fp32, in d_out)
    scores_kernel<<<dim3(16, 16, NB), 256, SMEM_PIPE>>>(pKp, pQp, pMkT, attn);
    // 5) Row softmax in place + fp16 side-write
    softmax_rows<<<NB * SS, 256>>>(attn, pAt);
    // 6) selfOutput = attn @ WV  (K = 2048)
    out_kernel<<<dim3(4, 16, NB), 256, SMEM_PIPE>>>(pAt, pWVT, out);
}

// round 14
// speedup vs baseline: 2.6597x; 1.0620x over previous
#include <cuda_runtime.h>
#include <cuda_fp16.h>
#include <cstdint>

#define NB 8
#define SS 2048
#define DD 1024
#define AA 512
#define DVV 512

// GEMM tiling: 128x128 CTA tile, BK=64, 3-stage cp.async pipeline, swizzled smem
#define BM 128
#define BN 128
#define BKC 64
#define ROWB 128                      // bytes per smem row (64 fp16; XOR swizzle c^(row&7))
#define PLANE (128 * ROWB)            // 16384 B per operand plane
#define STAGE (2 * PLANE)             // 32768 B per stage [A|B]
#define NSTAGE 3
#define SMEM_PIPE (NSTAGE * STAGE)    // 98304 B

// ---------------------------------------------------------------------------
// Scratch (__device__ globals; allocation-free rule)
// ---------------------------------------------------------------------------
__device__ __half g_Qb[(size_t)NB * SS * DD];
__device__ __half g_Kb[(size_t)NB * SS * DD];
__device__ __half g_Vb[(size_t)NB * SS * DD];
__device__ __half g_Wq[(size_t)AA * DD];
__device__ __half g_Wk[(size_t)AA * DD];
__device__ __half g_Wv[(size_t)DVV * DD];
__device__ __half g_Qp[(size_t)NB * SS * AA];     // B of scores
__device__ __half g_Kp[(size_t)NB * SS * AA];     // A of scores
__device__ __half g_WVT[(size_t)NB * DVV * SS];   // [b][v][s], B of out
__device__ __half g_At[(size_t)NB * SS * SS];     // A of out

// ---------------------------------------------------------------------------
// Helpers
// ---------------------------------------------------------------------------
__device__ __forceinline__ uint32_t smem_u32(const void* p) {
    uint32_t a;
    asm("{ .reg .u64 t; cvta.to.shared.u64 t, %1; cvt.u32.u64 %0, t; }" : "=r"(a) : "l"(p));
    return a;
}
__device__ __forceinline__ void cp16(uint32_t dst, const void* src) {
    asm volatile("cp.async.cg.shared.global [%0], [%1], 16;" :: "r"(dst), "l"(src));
}
#define CP_COMMIT() asm volatile("cp.async.commit_group;" ::: "memory")
#define CP_WAIT1()  asm volatile("cp.async.wait_group 1;" ::: "memory")
#define CP_WAIT0()  asm volatile("cp.async.wait_group 0;" ::: "memory")

__device__ __forceinline__ void ldsm4(uint32_t (&r)[4], uint32_t addr) {
    asm volatile("ldmatrix.sync.aligned.m8n8.x4.shared.b16 {%0,%1,%2,%3}, [%4];"
        : "=r"(r[0]), "=r"(r[1]), "=r"(r[2]), "=r"(r[3]) : "r"(addr));
}
__device__ __forceinline__ void mma_f16(float* d, const uint32_t* a, uint32_t b0, uint32_t b1) {
    asm volatile("mma.sync.aligned.m16n8k16.row.col.f32.f16.f16.f32 "
        "{%0,%1,%2,%3}, {%4,%5,%6,%7}, {%8,%9}, {%0,%1,%2,%3};"
        : "+f"(d[0]), "+f"(d[1]), "+f"(d[2]), "+f"(d[3])
        : "r"(a[0]), "r"(a[1]), "r"(a[2]), "r"(a[3]), "r"(b0), "r"(b1));
}

// Per-lane ldmatrix offsets (plane-relative, swizzled). [subtile][ks], ks=0..3
struct FragOff { uint32_t a[4][4]; uint32_t b[2][4]; };
__device__ __forceinline__ void frag_offsets(int lane, int warp_m, int warp_n, FragOff& F) {
    int ha = lane >> 4;                      // A k-half (0/1) within 16-k step
#pragma unroll
    for (int wm = 0; wm < 4; wm++) {
        int row = warp_m * 64 + wm * 16 + (lane & 15);
        int x = row & 7;
#pragma unroll
        for (int ks = 0; ks < 4; ks++)
            F.a[wm][ks] = (uint32_t)(row * ROWB + (((ks * 2 + ha) ^ x) << 4));
    }
    int rb = (lane & 7) + ((lane >> 4) << 3);
    int hb = (lane & 8) ? 1 : 0;             // B k-half
#pragma unroll
    for (int p = 0; p < 2; p++) {
        int row = warp_n * 32 + p * 16 + rb;
        int x = row & 7;
#pragma unroll
        for (int ks = 0; ks < 4; ks++)
            F.b[p][ks] = (uint32_t)(row * ROWB + (((ks * 2 + hb) ^ x) << 4));
    }
}

// Issue cp.async for one BK=64 chunk (2 planes: A, B). Each thread: half a row
// (64B = 4 x 16B) per plane. 256 threads cover 128 rows x 2 halves.
__device__ __forceinline__ void issue_cp(uint32_t sbase,
    const __half* __restrict__ A, int lda,
    const __half* __restrict__ B, int ldb,
    int k0, int tid)
{
    const int lrow = tid >> 1;
    const int half = tid & 1;
    const int x = lrow & 7;
    const int koff = k0 + half * 32;
    uint32_t rbase = sbase + (uint32_t)(lrow * ROWB);
    const __half* a0 = A + (size_t)lrow * lda + koff;
    const __half* b0 = B + (size_t)lrow * ldb + koff;
#pragma unroll
    for (int c = 0; c < 4; c++) {
        uint32_t off = (uint32_t)(((half * 4 + c) ^ x) << 4);
        cp16(rbase + off, a0 + c * 8);
        cp16(rbase + PLANE + off, b0 + c * 8);
    }
}

// One BK=64 chunk of fp16 1-pass MMA (4 k-steps)
__device__ __forceinline__ void mma_chunk64(uint32_t sb, const FragOff& F, float (*acc)[4][4]) {
#pragma unroll
    for (int ks = 0; ks < 4; ks++) {
        uint32_t af[4][4], bh[2][4];
#pragma unroll
        for (int wm = 0; wm < 4; wm++) ldsm4(af[wm], sb + F.a[wm][ks]);
#pragma unroll
        for (int p = 0; p < 2; p++) ldsm4(bh[p], sb + PLANE + F.b[p][ks]);
#pragma unroll
        for (int wm = 0; wm < 4; wm++)
#pragma unroll
            for (int wn = 0; wn < 4; wn++)
                mma_f16(acc[wm][wn], af[wm], bh[wn >> 1][(wn & 1) * 2], bh[wn >> 1][(wn & 1) * 2 + 1]);
    }
}

// 3-stage pipelined fp16 GEMM core, 2-chunk lookahead (acc += A * B^T over K)
__device__ __forceinline__ void gemm_core(uint32_t sb,
    const __half* A, int lda, const __half* B, int ldb,
    int K, int tid, const FragOff& F, float (*acc)[4][4])
{
    const int nch = K / BKC;
    issue_cp(sb, A, lda, B, ldb, 0, tid);
    CP_COMMIT();
    issue_cp(sb + STAGE, A, lda, B, ldb, BKC, tid);
    CP_COMMIT();
    uint32_t cur = 0, nxt2 = 2 * STAGE;
    for (int ch = 0; ch < nch; ch++) {
        if (ch < nch - 1) { CP_WAIT1(); } else { CP_WAIT0(); }
        __syncthreads();
        if (ch + 2 < nch) {
            issue_cp(sb + nxt2, A, lda, B, ldb, (ch + 2) * BKC, tid);
            CP_COMMIT();
        }
        mma_chunk64(sb + cur, F, acc);
        cur = (cur == (NSTAGE - 1) * STAGE) ? 0 : cur + STAGE;
        nxt2 = (nxt2 == (NSTAGE - 1) * STAGE) ? 0 : nxt2 + STAGE;
    }
    __syncthreads();
}

// ---------------------------------------------------------------------------
// Fused elementwise fp32 -> fp16 convert (3 tensors via blockIdx.z)
// ---------------------------------------------------------------------------
struct ConvArgs {
    const float* in[3];
    __half* hi[3];
};
__global__ void conv3_kernel(ConvArgs a, int n4)
{
    int z = blockIdx.z;
    int i = blockIdx.x * blockDim.x + threadIdx.x;
    if (i < n4) {
        float4 v = reinterpret_cast<const float4*>(a.in[z])[i];
        __half2 h01 = __floats2half2_rn(v.x, v.y);
        __half2 h23 = __floats2half2_rn(v.z, v.w);
        reinterpret_cast<uint2*>(a.hi[z])[i] =
            make_uint2(*reinterpret_cast<uint32_t*>(&h01), *reinterpret_cast<uint32_t*>(&h23));
    }
}

// ---------------------------------------------------------------------------
// Fused projection (Q/K/V via blockIdx.z): C = A*W^T + bias -> fp16.
// z==2 (V): writes WVT[b][n][s] via smem transpose.
// ---------------------------------------------------------------------------
struct ProjArgs {
    const __half *Ain[3], *Win[3];
    const float* bias[3];
    __half *Cout[3];
};
__global__ __launch_bounds__(256, 2)
void proj_kernel(ProjArgs P)
{
    extern __shared__ char smem[];
    uint32_t sb = smem_u32(smem);
    const int tid = threadIdx.x, lane = tid & 31, wid = tid >> 5;
    const int warp_m = wid & 1, warp_n = wid >> 1;
    const int m0 = blockIdx.y * BM, n0 = blockIdx.x * BN;
    const int z = blockIdx.z;
    const __half* A = P.Ain[z];
    const __half* W = P.Win[z];
    const float* bias = P.bias[z];
    __half* C = P.Cout[z];

    float acc[4][4][4];
#pragma unroll
    for (int i = 0; i < 4; i++)
#pragma unroll
        for (int j = 0; j < 4; j++)
#pragma unroll
            for (int r = 0; r < 4; r++) acc[i][j][r] = 0.f;

    FragOff F;
    frag_offsets(lane, warp_m, warp_n, F);

    gemm_core(sb, A + (size_t)m0 * DD, DD, W + (size_t)n0 * DD, DD,
              DD, tid, F, acc);

    if (z != 2) {
#pragma unroll
        for (int wn = 0; wn < 4; wn++) {
            int n = n0 + warp_n * 32 + wn * 8 + (lane & 3) * 2;
            float b0 = bias[n], b1 = bias[n + 1];
#pragma unroll
            for (int wm = 0; wm < 4; wm++)
#pragma unroll
                for (int h = 0; h < 2; h++) {
                    int m = m0 + warp_m * 64 + wm * 16 + (lane >> 2) + h * 8;
                    __half2 hv = __floats2half2_rn(acc[wm][wn][h * 2] + b0,
                                                   acc[wm][wn][h * 2 + 1] + b1);
                    *reinterpret_cast<__half2*>(C + (size_t)m * AA + n) = hv;
                }
        }
    } else {
        char* T = smem;   // 272B-stride rows
#pragma unroll
        for (int wn = 0; wn < 4; wn++) {
            int ln = warp_n * 32 + wn * 8 + (lane & 3) * 2;
            float b0 = bias[n0 + ln], b1 = bias[n0 + ln + 1];
#pragma unroll
            for (int wm = 0; wm < 4; wm++)
#pragma unroll
                for (int h = 0; h < 2; h++) {
                    int lm = warp_m * 64 + wm * 16 + (lane >> 2) + h * 8;
                    *reinterpret_cast<__half*>(T + ln * 272 + lm * 2) =
                        __float2half_rn(acc[wm][wn][h * 2] + b0);
                    *reinterpret_cast<__half*>(T + (ln + 1) * 272 + lm * 2) =
                        __float2half_rn(acc[wm][wn][h * 2 + 1] + b1);
                }
        }
        __syncthreads();
        int v = tid >> 1, hs = (tid & 1) * 64;
        size_t b = (size_t)(m0 >> 11);
        int s0 = m0 & (SS - 1);
        __half* dh = C + (b * DVV + n0 + v) * SS + s0 + hs;
#pragma unroll
        for (int g = 0; g < 8; g++)
            *reinterpret_cast<uint4*>(dh + g * 8) =
                *reinterpret_cast<uint4*>(T + v * 272 + (hs + g * 8) * 2);
    }
}

// ---------------------------------------------------------------------------
// Scores (pre-transposed): attn[b][k][q] = scale*Kp[k]·Qp[q] - 1e9*mask[b][q][k]
// Mask read directly (sector-efficient transposed pattern); no maskT pre-pass.
// ---------------------------------------------------------------------------
__global__ __launch_bounds__(256, 2)
void scores_kernel(const __half* __restrict__ Kp, const __half* __restrict__ Qp,
                   const int* __restrict__ mask, float* __restrict__ attn)
{
    extern __shared__ char smem[];
    uint32_t sb = smem_u32(smem);
    const int tid = threadIdx.x, lane = tid & 31, wid = tid >> 5;
    const int warp_m = wid & 1, warp_n = wid >> 1;
    const int m0 = blockIdx.y * BM, n0 = blockIdx.x * BN, b = blockIdx.z;

    float acc[4][4][4];
#pragma unroll
    for (int i = 0; i < 4; i++)
#pragma unroll
        for (int j = 0; j < 4; j++)
#pragma unroll
            for (int r = 0; r < 4; r++) acc[i][j][r] = 0.f;

    FragOff F;
    frag_offsets(lane, warp_m, warp_n, F);

    const size_t base = (size_t)b * SS * AA;
    gemm_core(sb, Kp + base + (size_t)m0 * AA, AA,
              Qp + base + (size_t)n0 * AA, AA, AA, tid, F, acc);

    const float scale = 0.04419417382415922f;   // 1/sqrt(512)
    const int* mk = mask + (size_t)b * SS * SS;
    float* ab = attn + (size_t)b * SS * SS;
#pragma unroll
    for (int wm = 0; wm < 4; wm++)
#pragma unroll
        for (int h = 0; h < 2; h++) {
            int k = m0 + warp_m * 64 + wm * 16 + (lane >> 2) + h * 8;
#pragma unroll
            for (int wn = 0; wn < 4; wn++) {
                int q = n0 + warp_n * 32 + wn * 8 + (lane & 3) * 2;
                float mv0 = -1e9f * (float)mk[(size_t)q * SS + k];
                float mv1 = -1e9f * (float)mk[(size_t)(q + 1) * SS + k];
                *reinterpret_cast<float2*>(ab + (size_t)k * SS + q) =
                    make_float2(fmaf(acc[wm][wn][h * 2], scale, mv0),
                                fmaf(acc[wm][wn][h * 2 + 1], scale, mv1));
            }
        }
}

// ---------------------------------------------------------------------------
// Output: out[b][k][v] = sum_q attn[b][k][q] * WVT[b][v][q]
// ---------------------------------------------------------------------------
__global__ __launch_bounds__(256, 2)
void out_kernel(const __half* __restrict__ At,
                const __half* __restrict__ WVT, float* __restrict__ out)
{
    extern __shared__ char smem[];
    uint32_t sb = smem_u32(smem);
    const int tid = threadIdx.x, lane = tid & 31, wid = tid >> 5;
    const int warp_m = wid & 1, warp_n = wid >> 1;
    const int m0 = blockIdx.y * BM, n0 = blockIdx.x * BN, b = blockIdx.z;

    float acc[4][4][4];
#pragma unroll
    for (int i = 0; i < 4; i++)
#pragma unroll
        for (int j = 0; j < 4; j++)
#pragma unroll
            for (int r = 0; r < 4; r++) acc[i][j][r] = 0.f;

    FragOff F;
    frag_offsets(lane, warp_m, warp_n, F);

    const size_t abase = (size_t)b * SS * SS;
    const size_t bbase = (size_t)b * DVV * SS;
    gemm_core(sb, At + abase + (size_t)m0 * SS, SS,
              WVT + bbase + (size_t)n0 * SS, SS, SS, tid, F, acc);

    float* ob = out + (size_t)b * SS * DVV;
#pragma unroll
    for (int wm = 0; wm < 4; wm++)
#pragma unroll
        for (int h = 0; h < 2; h++) {
            int m = m0 + warp_m * 64 + wm * 16 + (lane >> 2) + h * 8;
#pragma unroll
            for (int wn = 0; wn < 4; wn++) {
                int n = n0 + warp_n * 32 + wn * 8 + (lane & 3) * 2;
                *reinterpret_cast<float2*>(ob + (size_t)m * DVV + n) =
                    make_float2(acc[wm][wn][h * 2], acc[wm][wn][h * 2 + 1]);
            }
        }
}

// ---------------------------------------------------------------------------
// In-place row softmax (fp32) + fp16 truncated write for the out GEMM.
// ---------------------------------------------------------------------------
__global__ void softmax_rows(float* __restrict__ p, __half* __restrict__ hi)
{
    __shared__ float red[33];
    size_t rb = (size_t)blockIdx.x * SS;
    float* x = p + rb;
    int tid = threadIdx.x;
    float v[8];
    float mx = -1e30f;
#pragma unroll
    for (int i = 0; i < 8; i++) { v[i] = x[tid + i * 256]; mx = fmaxf(mx, v[i]); }
#pragma unroll
    for (int o = 16; o > 0; o >>= 1) mx = fmaxf(mx, __shfl_xor_sync(0xffffffffu, mx, o));
    if ((tid & 31) == 0) red[tid >> 5] = mx;
    __syncthreads();
    if (tid < 32) {
        float m = (tid < 8) ? red[tid] : -1e30f;
#pragma unroll
        for (int o = 4; o > 0; o >>= 1) m = fmaxf(m, __shfl_xor_sync(0xffffffffu, m, o));
        if (tid == 0) red[32] = m;
    }
    __syncthreads();
    mx = red[32];
    float s = 0.f;
#pragma unroll
    for (int i = 0; i < 8; i++) { v[i] = __expf(v[i] - mx); s += v[i]; }
#pragma unroll
    for (int o = 16; o > 0; o >>= 1) s += __shfl_xor_sync(0xffffffffu, s, o);
    if ((tid & 31) == 0) red[tid >> 5] = s;
    __syncthreads();
    if (tid < 32) {
        float m = (tid < 8) ? red[tid] : 0.f;
#pragma unroll
        for (int o = 4; o > 0; o >>= 1) m += __shfl_xor_sync(0xffffffffu, m, o);
        if (tid == 0) red[32] = m;
    }
    __syncthreads();
    float inv = 1.0f / red[32];
#pragma unroll
    for (int i = 0; i < 8; i++) {
        int idx = tid + i * 256;
        float val = v[i] * inv;
        x[idx] = val;
        hi[rb + idx] = __float2half_rn(val);
    }
}

// ---------------------------------------------------------------------------
extern "C" void kernel_launch(void* const* d_in, const int* in_sizes, int n_in,
                              void* d_out, int out_size)
{
    const float* Q    = (const float*)d_in[0];
    const float* K    = (const float*)d_in[1];
    const float* V    = (const float*)d_in[2];
    const int*   mask = (const int*)  d_in[3];
    const float* Wq   = (const float*)d_in[4];
    const float* bq   = (const float*)d_in[5];
    const float* Wk   = (const float*)d_in[6];
    const float* bk   = (const float*)d_in[7];
    const float* Wv   = (const float*)d_in[8];
    const float* bv   = (const float*)d_in[9];

    float* out  = (float*)d_out;                   // selfOutput [B,S,Dv]
    float* attn = out + (size_t)NB * SS * DVV;     // attn       [B,S,S]

    static __half *pQb, *pKb, *pVb, *pWq, *pWk, *pWv;
    static __half *pQp, *pKp, *pWVT, *pAt;
    static bool inited = false;
    if (!inited) {
        cudaGetSymbolAddress((void**)&pQb, g_Qb);
        cudaGetSymbolAddress((void**)&pKb, g_Kb);
        cudaGetSymbolAddress((void**)&pVb, g_Vb);
        cudaGetSymbolAddress((void**)&pWq, g_Wq);
        cudaGetSymbolAddress((void**)&pWk, g_Wk);
        cudaGetSymbolAddress((void**)&pWv, g_Wv);
        cudaGetSymbolAddress((void**)&pQp, g_Qp);
        cudaGetSymbolAddress((void**)&pKp, g_Kp);
        cudaGetSymbolAddress((void**)&pWVT, g_WVT);
        cudaGetSymbolAddress((void**)&pAt, g_At);
        cudaFuncSetAttribute(proj_kernel,   cudaFuncAttributeMaxDynamicSharedMemorySize, SMEM_PIPE);
        cudaFuncSetAttribute(scores_kernel, cudaFuncAttributeMaxDynamicSharedMemorySize, SMEM_PIPE);
        cudaFuncSetAttribute(out_kernel,    cudaFuncAttributeMaxDynamicSharedMemorySize, SMEM_PIPE);
        inited = true;
    }

    // 1) Convert inputs + weights to fp16
    {
        ConvArgs ca;
        ca.in[0] = Q; ca.in[1] = K; ca.in[2] = V;
        ca.hi[0] = pQb; ca.hi[1] = pKb; ca.hi[2] = pVb;
        int n4 = (NB * SS * DD) / 4;
        conv3_kernel<<<dim3((n4 + 255) / 256, 1, 3), 256>>>(ca, n4);

        ConvArgs cw;
        cw.in[0] = Wq; cw.in[1] = Wk; cw.in[2] = Wv;
        cw.hi[0] = pWq; cw.hi[1] = pWk; cw.hi[2] = pWv;
        int w4 = (AA * DD) / 4;
        conv3_kernel<<<dim3((w4 + 255) / 256, 1, 3), 256>>>(cw, w4);
    }

    // 2) Fused projections (all 1-pass fp16)
    {
        ProjArgs P;
        P.Ain[0] = pQb; P.Win[0] = pWq; P.bias[0] = bq; P.Cout[0] = pQp;
        P.Ain[1] = pKb; P.Win[1] = pWk; P.bias[1] = bk; P.Cout[1] = pKp;
        P.Ain[2] = pVb; P.Win[2] = pWv; P.bias[2] = bv; P.Cout[2] = pWVT;
        proj_kernel<<<dim3(4, 128, 3), 256, SMEM_PIPE>>>(P);
    }

    // 3) Masked, pre-transposed scores -> attn (fp32, in d_out); mask read inline
    scores_kernel<<<dim3(16, 16, NB), 256, SMEM_PIPE>>>(pKp, pQp, mask, attn);
    // 4) Row softmax in place + fp16 side-write
    softmax_rows<<<NB * SS, 256>>>(attn, pAt);
    // 5) selfOutput = attn @ WV  (K = 2048)
    out_kernel<<<dim3(4, 16, NB), 256, SMEM_PIPE>>>(pAt, pWVT, out);
}